// round 2
// baseline (speedup 1.0000x reference)
#include <cuda_runtime.h>
#include <cuda_bf16.h>
#include <math.h>

// Problem constants
#define BATCH 2
#define SEQ   2048
#define DMODEL 2048
#define QH 16
#define KVH 4
#define HD 128
#define NT (BATCH*SEQ)          // 4096 rows

// Scratch buffers (device globals: no allocation allowed)
__device__ float g_q[(size_t)NT * QH * HD];     // 4096 x 2048
__device__ float g_k[(size_t)NT * KVH * HD];    // 4096 x 512
__device__ float g_v[(size_t)NT * KVH * HD];    // 4096 x 512
__device__ float g_ctx[(size_t)NT * QH * HD];   // 4096 x 2048

// ---------------------------------------------------------------------------
// GEMM:  C[M,N] = A[M,K] * B[N,K]^T   (both row-major, B stored as [N,K])
// BM=BN=128, BK=8, 256 threads, 8x8 accum per thread.
// ---------------------------------------------------------------------------
__global__ __launch_bounds__(256) void gemm_nt_kernel(
    const float* __restrict__ A, const float* __restrict__ Bm,
    float* __restrict__ C, int M, int N, int K)
{
    const int BM = 128, BN = 128, BK = 8;
    __shared__ float As[BK][BM + 1];
    __shared__ float Bs[BK][BN + 1];

    int tid = threadIdx.x;
    int tx = tid & 15;          // 0..15
    int ty = tid >> 4;          // 0..15
    int row0 = blockIdx.y * BM;
    int col0 = blockIdx.x * BN;

    float acc[8][8];
    #pragma unroll
    for (int i = 0; i < 8; i++)
        #pragma unroll
        for (int j = 0; j < 8; j++) acc[i][j] = 0.f;

    for (int k0 = 0; k0 < K; k0 += BK) {
        #pragma unroll
        for (int it = 0; it < 4; it++) {
            int idx = tid + it * 256;        // 0..1023
            int m = idx >> 3, k = idx & 7;
            As[k][m] = A[(size_t)(row0 + m) * K + k0 + k];
        }
        #pragma unroll
        for (int it = 0; it < 4; it++) {
            int idx = tid + it * 256;
            int n = idx >> 3, k = idx & 7;
            Bs[k][n] = Bm[(size_t)(col0 + n) * K + k0 + k];
        }
        __syncthreads();

        #pragma unroll
        for (int kk = 0; kk < BK; kk++) {
            float a[8], b[8];
            #pragma unroll
            for (int i = 0; i < 8; i++) a[i] = As[kk][ty + 16 * i];
            #pragma unroll
            for (int j = 0; j < 8; j++) b[j] = Bs[kk][tx + 16 * j];
            #pragma unroll
            for (int i = 0; i < 8; i++)
                #pragma unroll
                for (int j = 0; j < 8; j++)
                    acc[i][j] += a[i] * b[j];
        }
        __syncthreads();
    }

    #pragma unroll
    for (int i = 0; i < 8; i++) {
        int r = row0 + ty + 16 * i;
        #pragma unroll
        for (int j = 0; j < 8; j++) {
            int c = col0 + tx + 16 * j;
            C[(size_t)r * N + c] = acc[i][j];
        }
    }
}

// ---------------------------------------------------------------------------
// RoPE (in-place): rows = NT, heads = QH or KVH. One thread per rotation pair.
// ---------------------------------------------------------------------------
__global__ void rope_kernel(float* __restrict__ q, const int* __restrict__ positions,
                            int heads, int total)
{
    int idx = blockIdx.x * blockDim.x + threadIdx.x;
    if (idx >= total) return;
    int j = idx & 63;                 // 0..63 (half = 64)
    int h = (idx >> 6) % heads;
    int r = idx / (heads * 64);
    float pos = (float)positions[r];
    // inv_freq = 10000^(-j/64)
    float inv = expf(-9.210340371976184f * (float)j * (1.0f / 64.0f));
    float ang = pos * inv;
    float s, c;
    sincosf(ang, &s, &c);
    float* base = q + ((size_t)r * heads + h) * HD;
    float x1 = base[j];
    float x2 = base[j + 64];
    base[j]      = x1 * c - x2 * s;
    base[j + 64] = x1 * s + x2 * c;
}

// ---------------------------------------------------------------------------
// Flash attention (fp32, online softmax). Block = (q-tile of 16, head, batch),
// 128 threads. Each thread owns one output column d = tid, acc[16] in regs.
// ---------------------------------------------------------------------------
#define BQ 16
#define BKT 64
#define KSTR 132   // padded stride for k/v tiles: conflict-free + float4-aligned

#define ATTN_SMEM_FLOATS (BQ*HD + 2*BKT*KSTR + BQ*BKT + 3*BQ)

extern __shared__ float attn_smem[];

__global__ __launch_bounds__(128) void attn_kernel(
    const float* __restrict__ gq, const float* __restrict__ gk,
    const float* __restrict__ gv, float* __restrict__ gctx)
{
    int qt = blockIdx.x;            // 0..SEQ/BQ-1
    int h  = blockIdx.y;            // 0..QH-1
    int b  = blockIdx.z;            // 0..BATCH-1
    int tid = threadIdx.x;          // 0..127

    float* qs   = attn_smem;                    // BQ * 128
    float* ks   = qs + BQ * HD;                 // BKT * KSTR
    float* vs   = ks + BKT * KSTR;              // BKT * KSTR
    float* sp   = vs + BKT * KSTR;              // BQ * BKT
    float* mrow = sp + BQ * BKT;                // BQ
    float* lrow = mrow + BQ;                    // BQ
    float* arow = lrow + BQ;                    // BQ

    int q0 = qt * BQ;
    int kvh = h >> 2;                            // QH/KVH = 4
    const float scale = 0.08838834764831845f;    // 1/sqrt(128)

    // Load + scale Q tile
    for (int i = tid; i < BQ * HD; i += 128) {
        int qi = i >> 7, d = i & 127;
        qs[i] = gq[(((size_t)(b * SEQ + q0 + qi)) * QH + h) * HD + d] * scale;
    }
    if (tid < BQ) { mrow[tid] = -1e30f; lrow[tid] = 0.f; }

    float acc[BQ];
    #pragma unroll
    for (int i = 0; i < BQ; i++) acc[i] = 0.f;

    int ktiles = (q0 + BQ + BKT - 1) / BKT;
    for (int kt = 0; kt < ktiles; kt++) {
        int k0 = kt * BKT;
        __syncthreads();   // previous acc-update done before overwriting tiles
        for (int i = tid; i < BKT * HD; i += 128) {
            int kj = i >> 7, d = i & 127;
            size_t gidx = (((size_t)(b * SEQ + k0 + kj)) * KVH + kvh) * HD + d;
            ks[kj * KSTR + d] = gk[gidx];
            vs[kj * KSTR + d] = gv[gidx];
        }
        __syncthreads();

        // S = Q K^T  (8 (qi,kj) pairs per thread)
        #pragma unroll
        for (int it = 0; it < 8; it++) {
            int idx = tid + it * 128;
            int qi = idx >> 6, kj = idx & 63;
            const float4* q4 = reinterpret_cast<const float4*>(qs + qi * HD);
            const float4* k4 = reinterpret_cast<const float4*>(ks + kj * KSTR);
            float sum = 0.f;
            #pragma unroll
            for (int kk = 0; kk < HD / 4; kk++) {
                float4 a = q4[kk];
                float4 bb = k4[kk];
                sum += a.x * bb.x + a.y * bb.y + a.z * bb.z + a.w * bb.w;
            }
            if (k0 + kj > q0 + qi) sum = -1e30f;
            sp[qi * BKT + kj] = sum;
        }
        __syncthreads();

        // Online softmax: one thread per query row
        if (tid < BQ) {
            float m_old = mrow[tid];
            float mx = m_old;
            float* row = sp + tid * BKT;
            #pragma unroll
            for (int kj = 0; kj < BKT; kj++) mx = fmaxf(mx, row[kj]);
            float al = expf(m_old - mx);
            float lsum = 0.f;
            #pragma unroll
            for (int kj = 0; kj < BKT; kj++) {
                float p = expf(row[kj] - mx);
                row[kj] = p;
                lsum += p;
            }
            mrow[tid] = mx;
            lrow[tid] = lrow[tid] * al + lsum;
            arow[tid] = al;
        }
        __syncthreads();

        // acc = acc*alpha + P @ V  (thread owns column d = tid)
        #pragma unroll
        for (int qi = 0; qi < BQ; qi++) acc[qi] *= arow[qi];
        for (int kj = 0; kj < BKT; kj++) {
            float vv = vs[kj * KSTR + tid];
            #pragma unroll
            for (int qi = 0; qi < BQ; qi++)
                acc[qi] += sp[qi * BKT + kj] * vv;
        }
    }

    #pragma unroll
    for (int qi = 0; qi < BQ; qi++) {
        gctx[(((size_t)(b * SEQ + q0 + qi)) * QH + h) * HD + tid] = acc[qi] / lrow[qi];
    }
}

// ---------------------------------------------------------------------------
// Launch
// ---------------------------------------------------------------------------
extern "C" void kernel_launch(void* const* d_in, const int* in_sizes, int n_in,
                              void* d_out, int out_size)
{
    const float* x         = (const float*)d_in[0];
    const int*   positions = (const int*)  d_in[1];
    const float* wq        = (const float*)d_in[2];
    const float* wk        = (const float*)d_in[3];
    const float* wv        = (const float*)d_in[4];
    const float* wo        = (const float*)d_in[5];
    float* out = (float*)d_out;

    float *pq, *pk, *pv, *pctx;
    cudaGetSymbolAddress((void**)&pq,   g_q);
    cudaGetSymbolAddress((void**)&pk,   g_k);
    cudaGetSymbolAddress((void**)&pv,   g_v);
    cudaGetSymbolAddress((void**)&pctx, g_ctx);

    // QKV projections
    {
        dim3 blk(256);
        dim3 gq_grid((QH * HD) / 128, NT / 128);
        gemm_nt_kernel<<<gq_grid, blk>>>(x, wq, pq, NT, QH * HD, DMODEL);
        dim3 gkv_grid((KVH * HD) / 128, NT / 128);
        gemm_nt_kernel<<<gkv_grid, blk>>>(x, wk, pk, NT, KVH * HD, DMODEL);
        gemm_nt_kernel<<<gkv_grid, blk>>>(x, wv, pv, NT, KVH * HD, DMODEL);
    }

    // RoPE
    {
        int total_q = NT * QH * 64;
        int total_k = NT * KVH * 64;
        rope_kernel<<<(total_q + 255) / 256, 256>>>(pq, positions, QH, total_q);
        rope_kernel<<<(total_k + 255) / 256, 256>>>(pk, positions, KVH, total_k);
    }

    // Attention
    {
        size_t smem = ATTN_SMEM_FLOATS * sizeof(float);   // ~80 KB
        cudaFuncSetAttribute(attn_kernel, cudaFuncAttributeMaxDynamicSharedMemorySize,
                             (int)smem);
        dim3 grid(SEQ / BQ, QH, BATCH);
        attn_kernel<<<grid, 128, smem>>>(pq, pk, pv, pctx);
    }

    // Output projection
    {
        dim3 blk(256);
        dim3 grid(DMODEL / 128, NT / 128);
        gemm_nt_kernel<<<grid, blk>>>(pctx, wo, out, NT, DMODEL, DMODEL);
    }
}

// round 6
// speedup vs baseline: 1.5768x; 1.5768x over previous
#include <cuda_runtime.h>
#include <cuda_bf16.h>
#include <math.h>
#include <stdint.h>

// Problem constants
#define BATCH 2
#define SEQ   2048
#define DMODEL 2048
#define QH 16
#define KVH 4
#define HD 128
#define NT (BATCH*SEQ)          // 4096 rows

// ---------------------------------------------------------------------------
// Scratch buffers (device globals: no allocation allowed)
// ---------------------------------------------------------------------------
__device__ float g_q[(size_t)NT * QH * HD];
__device__ float g_k[(size_t)NT * KVH * HD];
__device__ float g_v[(size_t)NT * KVH * HD];
__device__ float g_ctx[(size_t)NT * QH * HD];

// bf16 hi/lo split buffers
__device__ __nv_bfloat16 g_xh[(size_t)NT * DMODEL];
__device__ __nv_bfloat16 g_xl[(size_t)NT * DMODEL];
__device__ __nv_bfloat16 g_wqh[(size_t)(QH*HD) * DMODEL];
__device__ __nv_bfloat16 g_wql[(size_t)(QH*HD) * DMODEL];
__device__ __nv_bfloat16 g_wkh[(size_t)(KVH*HD) * DMODEL];
__device__ __nv_bfloat16 g_wkl[(size_t)(KVH*HD) * DMODEL];
__device__ __nv_bfloat16 g_wvh[(size_t)(KVH*HD) * DMODEL];
__device__ __nv_bfloat16 g_wvl[(size_t)(KVH*HD) * DMODEL];
__device__ __nv_bfloat16 g_woh[(size_t)DMODEL * (QH*HD)];
__device__ __nv_bfloat16 g_wol[(size_t)DMODEL * (QH*HD)];
__device__ __nv_bfloat16 g_ch[(size_t)NT * (QH*HD)];
__device__ __nv_bfloat16 g_cl[(size_t)NT * (QH*HD)];

// ---------------------------------------------------------------------------
// bf16 hi/lo split
// ---------------------------------------------------------------------------
__global__ void split_bf16_kernel(const float* __restrict__ in,
                                  __nv_bfloat16* __restrict__ hi,
                                  __nv_bfloat16* __restrict__ lo, int n)
{
    int i = blockIdx.x * blockDim.x + threadIdx.x;
    if (i >= n) return;
    float x = in[i];
    __nv_bfloat16 h = __float2bfloat16(x);
    hi[i] = h;
    lo[i] = __float2bfloat16(x - __bfloat162float(h));
}

// ---------------------------------------------------------------------------
// mma.sync bf16 GEMM with bf16x3 compensation.
// C[M,N] = A[M,K] * B[N,K]^T.  CTA tile 128x128, BK=32, 3-stage cp.async.
// ---------------------------------------------------------------------------
#define BKK 32
#define TILE_B 8192u          // 128 rows * 64 bytes (32 bf16)
#define STAGE_B (4u*TILE_B)   // Ah, Al, Bh, Bl
#define NSTAGE 3
#define GEMM_SMEM (NSTAGE*STAGE_B)   // 96 KB

// crosswise swizzle: row r (0..127), 16B-chunk c (0..3)
__device__ __forceinline__ uint32_t phys_off(int r, int c) {
    return (uint32_t)(r * 64 + (((c ^ (r >> 1)) & 3) << 4));
}

#define LDSM4(r, addr) \
    asm volatile("ldmatrix.sync.aligned.m8n8.x4.shared.b16 {%0,%1,%2,%3}, [%4];" \
        : "=r"((r)[0]), "=r"((r)[1]), "=r"((r)[2]), "=r"((r)[3]) : "r"(addr))

// A-frag reorder baked in: mma wants {a0,a1,a2,a3} = ldsm regs {0,2,1,3}
#define MMA16816(acc, A, B0, B1) \
    asm volatile("mma.sync.aligned.m16n8k16.row.col.f32.bf16.bf16.f32 " \
        "{%0,%1,%2,%3}, {%4,%5,%6,%7}, {%8,%9}, {%0,%1,%2,%3};" \
        : "+f"((acc)[0]), "+f"((acc)[1]), "+f"((acc)[2]), "+f"((acc)[3]) \
        : "r"((A)[0]), "r"((A)[2]), "r"((A)[1]), "r"((A)[3]), "r"(B0), "r"(B1))

__device__ __forceinline__ void gemm_issue_stage(
    uint32_t sbase, int st, int it, int row0, int col0, int tid, int K,
    const __nv_bfloat16* Ah, const __nv_bfloat16* Al,
    const __nv_bfloat16* Bh, const __nv_bfloat16* Bl)
{
    int k0 = it * BKK;
    uint32_t dst0 = sbase + (uint32_t)st * STAGE_B;
    const __nv_bfloat16* srcs[4] = {Ah, Al, Bh, Bl};
    #pragma unroll
    for (int u = 0; u < 8; ++u) {
        int idx = tid + u * 256;        // 0..2047
        int t = idx >> 9;               // tile 0..3
        int win = idx & 511;
        int r = win >> 2, c = win & 3;
        int gr = ((t < 2) ? row0 : col0) + r;
        const __nv_bfloat16* gp = srcs[t] + (size_t)gr * K + k0 + c * 8;
        uint32_t d = dst0 + (uint32_t)t * TILE_B + phys_off(r, c);
        asm volatile("cp.async.cg.shared.global [%0], [%1], 16;"
                     :: "r"(d), "l"(gp));
    }
    asm volatile("cp.async.commit_group;" ::: "memory");
}

__global__ __launch_bounds__(256)
void gemm_mma_kernel(const __nv_bfloat16* __restrict__ Ah,
                     const __nv_bfloat16* __restrict__ Al,
                     const __nv_bfloat16* __restrict__ Bh,
                     const __nv_bfloat16* __restrict__ Bl,
                     float* __restrict__ C, int M, int N, int K)
{
    extern __shared__ char smem[];
    uint32_t sbase = (uint32_t)__cvta_generic_to_shared(smem);

    int tid = threadIdx.x;
    int lane = tid & 31;
    int w = tid >> 5;
    int wm = w & 3;          // 4 warps along M (32 rows each)
    int wn = w >> 2;         // 2 warps along N (64 cols each)
    int row0 = blockIdx.y * 128;
    int col0 = blockIdx.x * 128;

    float acc[2][8][4];
    #pragma unroll
    for (int i = 0; i < 2; i++)
        #pragma unroll
        for (int j = 0; j < 8; j++)
            #pragma unroll
            for (int q = 0; q < 4; q++) acc[i][j][q] = 0.f;

    const int nIter = K / BKK;

    gemm_issue_stage(sbase, 0, 0, row0, col0, tid, K, Ah, Al, Bh, Bl);
    gemm_issue_stage(sbase, 1, 1, row0, col0, tid, K, Ah, Al, Bh, Bl);

    // per-lane ldmatrix row/col components
    int lrow = (lane & 7) + ((lane >> 4) << 3);   // row within 16-row frag
    int lsel = (lane >> 3) & 1;                   // chunk select (k 0-7 vs 8-15)

    for (int it = 0; it < nIter; ++it) {
        if (it + 2 < nIter)
            gemm_issue_stage(sbase, (it + 2) % NSTAGE, it + 2, row0, col0, tid, K,
                             Ah, Al, Bh, Bl);
        if (it + 2 < nIter)
            asm volatile("cp.async.wait_group 2;" ::: "memory");
        else if (it + 1 < nIter)
            asm volatile("cp.async.wait_group 1;" ::: "memory");
        else
            asm volatile("cp.async.wait_group 0;" ::: "memory");
        __syncthreads();

        uint32_t tb = sbase + (uint32_t)(it % NSTAGE) * STAGE_B;
        uint32_t aH = tb;
        uint32_t aL = tb + TILE_B;
        uint32_t bHb = tb + 2 * TILE_B;
        uint32_t bLb = tb + 3 * TILE_B;

        #pragma unroll
        for (int kk = 0; kk < 2; ++kk) {
            int c = 2 * kk + lsel;
            uint32_t a[2][4], b[4][4];

            // pass 1: Al * Bh
            #pragma unroll
            for (int mf = 0; mf < 2; ++mf) {
                int r = wm * 32 + mf * 16 + lrow;
                LDSM4(a[mf], aL + phys_off(r, c));
            }
            #pragma unroll
            for (int p = 0; p < 4; ++p) {
                int r = wn * 64 + p * 16 + lrow;
                LDSM4(b[p], bHb + phys_off(r, c));
            }
            #pragma unroll
            for (int mf = 0; mf < 2; ++mf)
                #pragma unroll
                for (int p = 0; p < 4; ++p) {
                    MMA16816(acc[mf][2*p],   a[mf], b[p][0], b[p][1]);
                    MMA16816(acc[mf][2*p+1], a[mf], b[p][2], b[p][3]);
                }

            // pass 2: Ah * Bh (reuse b)
            #pragma unroll
            for (int mf = 0; mf < 2; ++mf) {
                int r = wm * 32 + mf * 16 + lrow;
                LDSM4(a[mf], aH + phys_off(r, c));
            }
            #pragma unroll
            for (int mf = 0; mf < 2; ++mf)
                #pragma unroll
                for (int p = 0; p < 4; ++p) {
                    MMA16816(acc[mf][2*p],   a[mf], b[p][0], b[p][1]);
                    MMA16816(acc[mf][2*p+1], a[mf], b[p][2], b[p][3]);
                }

            // pass 3: Ah * Bl (reuse a)
            #pragma unroll
            for (int p = 0; p < 4; ++p) {
                int r = wn * 64 + p * 16 + lrow;
                LDSM4(b[p], bLb + phys_off(r, c));
            }
            #pragma unroll
            for (int mf = 0; mf < 2; ++mf)
                #pragma unroll
                for (int p = 0; p < 4; ++p) {
                    MMA16816(acc[mf][2*p],   a[mf], b[p][0], b[p][1]);
                    MMA16816(acc[mf][2*p+1], a[mf], b[p][2], b[p][3]);
                }
        }
        __syncthreads();
    }

    // Epilogue
    #pragma unroll
    for (int mf = 0; mf < 2; ++mf) {
        int rbase = row0 + wm * 32 + mf * 16 + (lane >> 2);
        #pragma unroll
        for (int nf = 0; nf < 8; ++nf) {
            int cc = col0 + wn * 64 + nf * 8 + (lane & 3) * 2;
            float2 v0 = make_float2(acc[mf][nf][0], acc[mf][nf][1]);
            float2 v1 = make_float2(acc[mf][nf][2], acc[mf][nf][3]);
            *reinterpret_cast<float2*>(&C[(size_t)rbase * N + cc]) = v0;
            *reinterpret_cast<float2*>(&C[(size_t)(rbase + 8) * N + cc]) = v1;
        }
    }
}

// ---------------------------------------------------------------------------
// RoPE (in-place)
// ---------------------------------------------------------------------------
__global__ void rope_kernel(float* __restrict__ q, const int* __restrict__ positions,
                            int heads, int total)
{
    int idx = blockIdx.x * blockDim.x + threadIdx.x;
    if (idx >= total) return;
    int j = idx & 63;
    int h = (idx >> 6) % heads;
    int r = idx / (heads * 64);
    float pos = (float)positions[r];
    float inv = expf(-9.210340371976184f * (float)j * (1.0f / 64.0f));
    float ang = pos * inv;
    float s, c;
    sincosf(ang, &s, &c);
    float* base = q + ((size_t)r * heads + h) * HD;
    float x1 = base[j];
    float x2 = base[j + 64];
    base[j]      = x1 * c - x2 * s;
    base[j + 64] = x1 * s + x2 * c;
}

// ---------------------------------------------------------------------------
// Flash attention (fp32, online softmax) — unchanged from R2 (passing).
// ---------------------------------------------------------------------------
#define BQ 16
#define BKT 64
#define KSTR 132

#define ATTN_SMEM_FLOATS (BQ*HD + 2*BKT*KSTR + BQ*BKT + 3*BQ)

extern __shared__ float attn_smem[];

__global__ __launch_bounds__(128) void attn_kernel(
    const float* __restrict__ gq, const float* __restrict__ gk,
    const float* __restrict__ gv, float* __restrict__ gctx)
{
    int qt = blockIdx.x;
    int h  = blockIdx.y;
    int b  = blockIdx.z;
    int tid = threadIdx.x;

    float* qs   = attn_smem;
    float* ks   = qs + BQ * HD;
    float* vs   = ks + BKT * KSTR;
    float* sp   = vs + BKT * KSTR;
    float* mrow = sp + BQ * BKT;
    float* lrow = mrow + BQ;
    float* arow = lrow + BQ;

    int q0 = qt * BQ;
    int kvh = h >> 2;
    const float scale = 0.08838834764831845f;

    for (int i = tid; i < BQ * HD; i += 128) {
        int qi = i >> 7, d = i & 127;
        qs[i] = gq[(((size_t)(b * SEQ + q0 + qi)) * QH + h) * HD + d] * scale;
    }
    if (tid < BQ) { mrow[tid] = -1e30f; lrow[tid] = 0.f; }

    float acc[BQ];
    #pragma unroll
    for (int i = 0; i < BQ; i++) acc[i] = 0.f;

    int ktiles = (q0 + BQ + BKT - 1) / BKT;
    for (int kt = 0; kt < ktiles; kt++) {
        int k0 = kt * BKT;
        __syncthreads();
        for (int i = tid; i < BKT * HD; i += 128) {
            int kj = i >> 7, d = i & 127;
            size_t gidx = (((size_t)(b * SEQ + k0 + kj)) * KVH + kvh) * HD + d;
            ks[kj * KSTR + d] = gk[gidx];
            vs[kj * KSTR + d] = gv[gidx];
        }
        __syncthreads();

        #pragma unroll
        for (int it = 0; it < 8; it++) {
            int idx = tid + it * 128;
            int qi = idx >> 6, kj = idx & 63;
            const float4* q4 = reinterpret_cast<const float4*>(qs + qi * HD);
            const float4* k4 = reinterpret_cast<const float4*>(ks + kj * KSTR);
            float sum = 0.f;
            #pragma unroll
            for (int kk = 0; kk < HD / 4; kk++) {
                float4 a = q4[kk];
                float4 bb = k4[kk];
                sum += a.x * bb.x + a.y * bb.y + a.z * bb.z + a.w * bb.w;
            }
            if (k0 + kj > q0 + qi) sum = -1e30f;
            sp[qi * BKT + kj] = sum;
        }
        __syncthreads();

        if (tid < BQ) {
            float m_old = mrow[tid];
            float mx = m_old;
            float* row = sp + tid * BKT;
            #pragma unroll
            for (int kj = 0; kj < BKT; kj++) mx = fmaxf(mx, row[kj]);
            float al = expf(m_old - mx);
            float lsum = 0.f;
            #pragma unroll
            for (int kj = 0; kj < BKT; kj++) {
                float p = expf(row[kj] - mx);
                row[kj] = p;
                lsum += p;
            }
            mrow[tid] = mx;
            lrow[tid] = lrow[tid] * al + lsum;
            arow[tid] = al;
        }
        __syncthreads();

        #pragma unroll
        for (int qi = 0; qi < BQ; qi++) acc[qi] *= arow[qi];
        for (int kj = 0; kj < BKT; kj++) {
            float vv = vs[kj * KSTR + tid];
            #pragma unroll
            for (int qi = 0; qi < BQ; qi++)
                acc[qi] += sp[qi * BKT + kj] * vv;
        }
    }

    #pragma unroll
    for (int qi = 0; qi < BQ; qi++) {
        gctx[(((size_t)(b * SEQ + q0 + qi)) * QH + h) * HD + tid] = acc[qi] / lrow[qi];
    }
}

// ---------------------------------------------------------------------------
// Launch
// ---------------------------------------------------------------------------
extern "C" void kernel_launch(void* const* d_in, const int* in_sizes, int n_in,
                              void* d_out, int out_size)
{
    const float* x         = (const float*)d_in[0];
    const int*   positions = (const int*)  d_in[1];
    const float* wq        = (const float*)d_in[2];
    const float* wk        = (const float*)d_in[3];
    const float* wv        = (const float*)d_in[4];
    const float* wo        = (const float*)d_in[5];
    float* out = (float*)d_out;

    float *pq, *pk, *pv, *pctx;
    cudaGetSymbolAddress((void**)&pq,   g_q);
    cudaGetSymbolAddress((void**)&pk,   g_k);
    cudaGetSymbolAddress((void**)&pv,   g_v);
    cudaGetSymbolAddress((void**)&pctx, g_ctx);

    __nv_bfloat16 *xh, *xl, *wqh, *wql, *wkh, *wkl, *wvh, *wvl, *woh, *wol, *ch, *cl;
    cudaGetSymbolAddress((void**)&xh,  g_xh);  cudaGetSymbolAddress((void**)&xl,  g_xl);
    cudaGetSymbolAddress((void**)&wqh, g_wqh); cudaGetSymbolAddress((void**)&wql, g_wql);
    cudaGetSymbolAddress((void**)&wkh, g_wkh); cudaGetSymbolAddress((void**)&wkl, g_wkl);
    cudaGetSymbolAddress((void**)&wvh, g_wvh); cudaGetSymbolAddress((void**)&wvl, g_wvl);
    cudaGetSymbolAddress((void**)&woh, g_woh); cudaGetSymbolAddress((void**)&wol, g_wol);
    cudaGetSymbolAddress((void**)&ch,  g_ch);  cudaGetSymbolAddress((void**)&cl,  g_cl);

    cudaFuncSetAttribute(gemm_mma_kernel, cudaFuncAttributeMaxDynamicSharedMemorySize,
                         GEMM_SMEM);

    // Splits
    {
        int n;
        n = NT * DMODEL;
        split_bf16_kernel<<<(n + 255) / 256, 256>>>(x, xh, xl, n);
        n = QH * HD * DMODEL;
        split_bf16_kernel<<<(n + 255) / 256, 256>>>(wq, wqh, wql, n);
        n = KVH * HD * DMODEL;
        split_bf16_kernel<<<(n + 255) / 256, 256>>>(wk, wkh, wkl, n);
        split_bf16_kernel<<<(n + 255) / 256, 256>>>(wv, wvh, wvl, n);
        n = DMODEL * QH * HD;
        split_bf16_kernel<<<(n + 255) / 256, 256>>>(wo, woh, wol, n);
    }

    // QKV projections (mma.sync bf16x3)
    {
        dim3 blk(256);
        dim3 gq_grid((QH * HD) / 128, NT / 128);
        gemm_mma_kernel<<<gq_grid, blk, GEMM_SMEM>>>(xh, xl, wqh, wql, pq, NT, QH * HD, DMODEL);
        dim3 gkv_grid((KVH * HD) / 128, NT / 128);
        gemm_mma_kernel<<<gkv_grid, blk, GEMM_SMEM>>>(xh, xl, wkh, wkl, pk, NT, KVH * HD, DMODEL);
        gemm_mma_kernel<<<gkv_grid, blk, GEMM_SMEM>>>(xh, xl, wvh, wvl, pv, NT, KVH * HD, DMODEL);
    }

    // RoPE
    {
        int total_q = NT * QH * 64;
        int total_k = NT * KVH * 64;
        rope_kernel<<<(total_q + 255) / 256, 256>>>(pq, positions, QH, total_q);
        rope_kernel<<<(total_k + 255) / 256, 256>>>(pk, positions, KVH, total_k);
    }

    // Attention
    {
        size_t smem = ATTN_SMEM_FLOATS * sizeof(float);
        cudaFuncSetAttribute(attn_kernel, cudaFuncAttributeMaxDynamicSharedMemorySize,
                             (int)smem);
        dim3 grid(SEQ / BQ, QH, BATCH);
        attn_kernel<<<grid, 128, smem>>>(pq, pk, pv, pctx);
    }

    // Output projection
    {
        int n = NT * QH * HD;
        split_bf16_kernel<<<(n + 255) / 256, 256>>>(pctx, ch, cl, n);
        dim3 blk(256);
        dim3 grid(DMODEL / 128, NT / 128);
        gemm_mma_kernel<<<grid, blk, GEMM_SMEM>>>(ch, cl, woh, wol, out, NT, DMODEL, DMODEL);
    }
}

// round 7
// speedup vs baseline: 4.4526x; 2.8237x over previous
#include <cuda_runtime.h>
#include <cuda_bf16.h>
#include <math.h>
#include <stdint.h>

// Problem constants
#define BATCH 2
#define SEQ   2048
#define DMODEL 2048
#define QH 16
#define KVH 4
#define HD 128
#define NT (BATCH*SEQ)          // 4096 rows

// ---------------------------------------------------------------------------
// Scratch buffers (device globals: no allocation allowed)
// ---------------------------------------------------------------------------
__device__ float g_q[(size_t)NT * QH * HD];
__device__ float g_k[(size_t)NT * KVH * HD];
__device__ float g_v[(size_t)NT * KVH * HD];

// bf16 hi/lo split buffers (GEMM inputs)
__device__ __nv_bfloat16 g_xh[(size_t)NT * DMODEL];
__device__ __nv_bfloat16 g_xl[(size_t)NT * DMODEL];
__device__ __nv_bfloat16 g_wqh[(size_t)(QH*HD) * DMODEL];
__device__ __nv_bfloat16 g_wql[(size_t)(QH*HD) * DMODEL];
__device__ __nv_bfloat16 g_wkh[(size_t)(KVH*HD) * DMODEL];
__device__ __nv_bfloat16 g_wkl[(size_t)(KVH*HD) * DMODEL];
__device__ __nv_bfloat16 g_wvh[(size_t)(KVH*HD) * DMODEL];
__device__ __nv_bfloat16 g_wvl[(size_t)(KVH*HD) * DMODEL];
__device__ __nv_bfloat16 g_woh[(size_t)DMODEL * (QH*HD)];
__device__ __nv_bfloat16 g_wol[(size_t)DMODEL * (QH*HD)];
__device__ __nv_bfloat16 g_ch[(size_t)NT * (QH*HD)];
__device__ __nv_bfloat16 g_cl[(size_t)NT * (QH*HD)];

// attention bf16 hi/lo inputs (post-RoPE)
__device__ __nv_bfloat16 g_aqh[(size_t)NT * QH * HD];
__device__ __nv_bfloat16 g_aql[(size_t)NT * QH * HD];
__device__ __nv_bfloat16 g_akh[(size_t)NT * KVH * HD];
__device__ __nv_bfloat16 g_akl[(size_t)NT * KVH * HD];
__device__ __nv_bfloat16 g_avh[(size_t)NT * KVH * HD];
__device__ __nv_bfloat16 g_avl[(size_t)NT * KVH * HD];

// ---------------------------------------------------------------------------
// helpers
// ---------------------------------------------------------------------------
__global__ void split_bf16_kernel(const float* __restrict__ in,
                                  __nv_bfloat16* __restrict__ hi,
                                  __nv_bfloat16* __restrict__ lo, int n)
{
    int i = blockIdx.x * blockDim.x + threadIdx.x;
    if (i >= n) return;
    float x = in[i];
    __nv_bfloat16 h = __float2bfloat16(x);
    hi[i] = h;
    lo[i] = __float2bfloat16(x - __bfloat162float(h));
}

__device__ __forceinline__ void split_pack(float e0, float e1,
                                           uint32_t& hi, uint32_t& lo)
{
    __nv_bfloat16 h0 = __float2bfloat16(e0);
    __nv_bfloat16 h1 = __float2bfloat16(e1);
    hi = ((uint32_t)__bfloat16_as_ushort(h1) << 16) | __bfloat16_as_ushort(h0);
    __nv_bfloat16 g0 = __float2bfloat16(e0 - __bfloat162float(h0));
    __nv_bfloat16 g1 = __float2bfloat16(e1 - __bfloat162float(h1));
    lo = ((uint32_t)__bfloat16_as_ushort(g1) << 16) | __bfloat16_as_ushort(g0);
}

#define LDSM4(r, addr) \
    asm volatile("ldmatrix.sync.aligned.m8n8.x4.shared.b16 {%0,%1,%2,%3}, [%4];" \
        : "=r"((r)[0]), "=r"((r)[1]), "=r"((r)[2]), "=r"((r)[3]) : "r"(addr))

#define LDSM4T(r, addr) \
    asm volatile("ldmatrix.sync.aligned.m8n8.x4.trans.shared.b16 {%0,%1,%2,%3}, [%4];" \
        : "=r"((r)[0]), "=r"((r)[1]), "=r"((r)[2]), "=r"((r)[3]) : "r"(addr))

// A from ldmatrix (reorder 0,2,1,3)
#define MMA16816(acc, A, B0, B1) \
    asm volatile("mma.sync.aligned.m16n8k16.row.col.f32.bf16.bf16.f32 " \
        "{%0,%1,%2,%3}, {%4,%5,%6,%7}, {%8,%9}, {%0,%1,%2,%3};" \
        : "+f"((acc)[0]), "+f"((acc)[1]), "+f"((acc)[2]), "+f"((acc)[3]) \
        : "r"((A)[0]), "r"((A)[2]), "r"((A)[1]), "r"((A)[3]), "r"(B0), "r"(B1))

// A already in mma register order
#define MMA_PV(acc, A, B0, B1) \
    asm volatile("mma.sync.aligned.m16n8k16.row.col.f32.bf16.bf16.f32 " \
        "{%0,%1,%2,%3}, {%4,%5,%6,%7}, {%8,%9}, {%0,%1,%2,%3};" \
        : "+f"((acc)[0]), "+f"((acc)[1]), "+f"((acc)[2]), "+f"((acc)[3]) \
        : "r"((A)[0]), "r"((A)[1]), "r"((A)[2]), "r"((A)[3]), "r"(B0), "r"(B1))

// ---------------------------------------------------------------------------
// mma.sync bf16 GEMM with bf16x3 compensation (unchanged from R6, passing).
// C[M,N] = A[M,K] * B[N,K]^T.  CTA tile 128x128, BK=32, 3-stage cp.async.
// ---------------------------------------------------------------------------
#define BKK 32
#define TILE_B 8192u
#define STAGE_B (4u*TILE_B)
#define NSTAGE 3
#define GEMM_SMEM (NSTAGE*STAGE_B)

__device__ __forceinline__ uint32_t phys_off(int r, int c) {
    return (uint32_t)(r * 64 + (((c ^ (r >> 1)) & 3) << 4));
}

__device__ __forceinline__ void gemm_issue_stage(
    uint32_t sbase, int st, int it, int row0, int col0, int tid, int K,
    const __nv_bfloat16* Ah, const __nv_bfloat16* Al,
    const __nv_bfloat16* Bh, const __nv_bfloat16* Bl)
{
    int k0 = it * BKK;
    uint32_t dst0 = sbase + (uint32_t)st * STAGE_B;
    const __nv_bfloat16* srcs[4] = {Ah, Al, Bh, Bl};
    #pragma unroll
    for (int u = 0; u < 8; ++u) {
        int idx = tid + u * 256;
        int t = idx >> 9;
        int win = idx & 511;
        int r = win >> 2, c = win & 3;
        int gr = ((t < 2) ? row0 : col0) + r;
        const __nv_bfloat16* gp = srcs[t] + (size_t)gr * K + k0 + c * 8;
        uint32_t d = dst0 + (uint32_t)t * TILE_B + phys_off(r, c);
        asm volatile("cp.async.cg.shared.global [%0], [%1], 16;"
                     :: "r"(d), "l"(gp));
    }
    asm volatile("cp.async.commit_group;" ::: "memory");
}

__global__ __launch_bounds__(256)
void gemm_mma_kernel(const __nv_bfloat16* __restrict__ Ah,
                     const __nv_bfloat16* __restrict__ Al,
                     const __nv_bfloat16* __restrict__ Bh,
                     const __nv_bfloat16* __restrict__ Bl,
                     float* __restrict__ C, int M, int N, int K)
{
    extern __shared__ char smem[];
    uint32_t sbase = (uint32_t)__cvta_generic_to_shared(smem);

    int tid = threadIdx.x;
    int lane = tid & 31;
    int w = tid >> 5;
    int wm = w & 3;
    int wn = w >> 2;
    int row0 = blockIdx.y * 128;
    int col0 = blockIdx.x * 128;

    float acc[2][8][4];
    #pragma unroll
    for (int i = 0; i < 2; i++)
        #pragma unroll
        for (int j = 0; j < 8; j++)
            #pragma unroll
            for (int q = 0; q < 4; q++) acc[i][j][q] = 0.f;

    const int nIter = K / BKK;

    gemm_issue_stage(sbase, 0, 0, row0, col0, tid, K, Ah, Al, Bh, Bl);
    gemm_issue_stage(sbase, 1, 1, row0, col0, tid, K, Ah, Al, Bh, Bl);

    int lrow = (lane & 7) + ((lane >> 4) << 3);
    int lsel = (lane >> 3) & 1;

    for (int it = 0; it < nIter; ++it) {
        if (it + 2 < nIter)
            gemm_issue_stage(sbase, (it + 2) % NSTAGE, it + 2, row0, col0, tid, K,
                             Ah, Al, Bh, Bl);
        if (it + 2 < nIter)
            asm volatile("cp.async.wait_group 2;" ::: "memory");
        else if (it + 1 < nIter)
            asm volatile("cp.async.wait_group 1;" ::: "memory");
        else
            asm volatile("cp.async.wait_group 0;" ::: "memory");
        __syncthreads();

        uint32_t tb = sbase + (uint32_t)(it % NSTAGE) * STAGE_B;
        uint32_t aH = tb;
        uint32_t aL = tb + TILE_B;
        uint32_t bHb = tb + 2 * TILE_B;
        uint32_t bLb = tb + 3 * TILE_B;

        #pragma unroll
        for (int kk = 0; kk < 2; ++kk) {
            int c = 2 * kk + lsel;
            uint32_t a[2][4], b[4][4];

            #pragma unroll
            for (int mf = 0; mf < 2; ++mf) {
                int r = wm * 32 + mf * 16 + lrow;
                LDSM4(a[mf], aL + phys_off(r, c));
            }
            #pragma unroll
            for (int p = 0; p < 4; ++p) {
                int r = wn * 64 + p * 16 + lrow;
                LDSM4(b[p], bHb + phys_off(r, c));
            }
            #pragma unroll
            for (int mf = 0; mf < 2; ++mf)
                #pragma unroll
                for (int p = 0; p < 4; ++p) {
                    MMA16816(acc[mf][2*p],   a[mf], b[p][0], b[p][1]);
                    MMA16816(acc[mf][2*p+1], a[mf], b[p][2], b[p][3]);
                }

            #pragma unroll
            for (int mf = 0; mf < 2; ++mf) {
                int r = wm * 32 + mf * 16 + lrow;
                LDSM4(a[mf], aH + phys_off(r, c));
            }
            #pragma unroll
            for (int mf = 0; mf < 2; ++mf)
                #pragma unroll
                for (int p = 0; p < 4; ++p) {
                    MMA16816(acc[mf][2*p],   a[mf], b[p][0], b[p][1]);
                    MMA16816(acc[mf][2*p+1], a[mf], b[p][2], b[p][3]);
                }

            #pragma unroll
            for (int p = 0; p < 4; ++p) {
                int r = wn * 64 + p * 16 + lrow;
                LDSM4(b[p], bLb + phys_off(r, c));
            }
            #pragma unroll
            for (int mf = 0; mf < 2; ++mf)
                #pragma unroll
                for (int p = 0; p < 4; ++p) {
                    MMA16816(acc[mf][2*p],   a[mf], b[p][0], b[p][1]);
                    MMA16816(acc[mf][2*p+1], a[mf], b[p][2], b[p][3]);
                }
        }
        __syncthreads();
    }

    #pragma unroll
    for (int mf = 0; mf < 2; ++mf) {
        int rbase = row0 + wm * 32 + mf * 16 + (lane >> 2);
        #pragma unroll
        for (int nf = 0; nf < 8; ++nf) {
            int cc = col0 + wn * 64 + nf * 8 + (lane & 3) * 2;
            float2 v0 = make_float2(acc[mf][nf][0], acc[mf][nf][1]);
            float2 v1 = make_float2(acc[mf][nf][2], acc[mf][nf][3]);
            *reinterpret_cast<float2*>(&C[(size_t)rbase * N + cc]) = v0;
            *reinterpret_cast<float2*>(&C[(size_t)(rbase + 8) * N + cc]) = v1;
        }
    }
}

// ---------------------------------------------------------------------------
// RoPE + scale + bf16 hi/lo split (reads fp32 proj output, writes bf16 pair)
// ---------------------------------------------------------------------------
__global__ void rope_split_kernel(const float* __restrict__ src,
                                  const int* __restrict__ positions,
                                  __nv_bfloat16* __restrict__ dh,
                                  __nv_bfloat16* __restrict__ dl,
                                  int heads, float scale, int total)
{
    int idx = blockIdx.x * blockDim.x + threadIdx.x;
    if (idx >= total) return;
    int j = idx & 63;
    int h = (idx >> 6) % heads;
    int r = idx / (heads * 64);
    float pos = (float)positions[r];
    float inv = expf(-9.210340371976184f * (float)j * (1.0f / 64.0f));
    float ang = pos * inv;
    float sn, cs;
    sincosf(ang, &sn, &cs);
    size_t base = ((size_t)r * heads + h) * HD;
    float x1 = src[base + j];
    float x2 = src[base + j + 64];
    float y1 = (x1 * cs - x2 * sn) * scale;
    float y2 = (x1 * sn + x2 * cs) * scale;
    __nv_bfloat16 h1 = __float2bfloat16(y1);
    __nv_bfloat16 h2 = __float2bfloat16(y2);
    dh[base + j] = h1;
    dl[base + j] = __float2bfloat16(y1 - __bfloat162float(h1));
    dh[base + j + 64] = h2;
    dl[base + j + 64] = __float2bfloat16(y2 - __bfloat162float(h2));
}

// ---------------------------------------------------------------------------
// Tensor-core flash attention, bf16 compensated.
// CTA: 64 queries x (head, batch). 4 warps (16 q-rows each). K tile = 64.
// smem: qh,ql,kh,kl,vh,vl tiles, 64 rows x 256B each (swizzled).
// ---------------------------------------------------------------------------
#define AQ 64
#define AKT 64
#define ATILE 16384u
#define ATT_SMEM (6u*ATILE)

__device__ __forceinline__ uint32_t off256(int r, int c) {
    return (uint32_t)(r * 256 + (((c ^ (r & 7)) & 15) << 4));
}

__global__ __launch_bounds__(128)
void attn_mma_kernel(const __nv_bfloat16* __restrict__ qh, const __nv_bfloat16* __restrict__ ql,
                     const __nv_bfloat16* __restrict__ kh, const __nv_bfloat16* __restrict__ kl,
                     const __nv_bfloat16* __restrict__ vh, const __nv_bfloat16* __restrict__ vl,
                     __nv_bfloat16* __restrict__ ch, __nv_bfloat16* __restrict__ cl)
{
    extern __shared__ char asmem[];
    uint32_t sb = (uint32_t)__cvta_generic_to_shared(asmem);
    uint32_t sqh = sb,            sql = sb + ATILE;
    uint32_t skh = sb + 2*ATILE,  skl = sb + 3*ATILE;
    uint32_t svh = sb + 4*ATILE,  svl = sb + 5*ATILE;

    int qt = blockIdx.x, h = blockIdx.y, b = blockIdx.z;
    int tid = threadIdx.x, lane = tid & 31, w = tid >> 5;
    int q0 = qt * AQ;
    int kvh = h >> 2;

    int lrow = (lane & 7) | ((lane >> 4) << 3);   // non-trans ldsm row
    int lsel = (lane >> 3) & 1;                   // non-trans k-chunk select
    int vrow = (lane & 7) | (((lane >> 3) & 1) << 3);  // trans ldsm row (k dim)
    int vcol = lane >> 4;                              // trans ldsm n-chunk

    // ---- load Q tiles (hi + lo) ----
    {
        const __nv_bfloat16* srcs[2] = {qh, ql};
        uint32_t dsts[2] = {sqh, sql};
        #pragma unroll
        for (int u = 0; u < 16; ++u) {
            int idx = tid + u * 128;
            int t = idx >> 10, win = idx & 1023;
            int r = win >> 4, c = win & 15;
            const __nv_bfloat16* gp = srcs[t] +
                (((size_t)(b * SEQ + q0 + r) * QH + h) * HD + c * 8);
            uint32_t d = dsts[t] + off256(r, c);
            asm volatile("cp.async.cg.shared.global [%0], [%1], 16;" :: "r"(d), "l"(gp));
        }
        asm volatile("cp.async.commit_group;" ::: "memory");
    }

    float o[16][4];
    #pragma unroll
    for (int i = 0; i < 16; i++) {
        o[i][0] = 0.f; o[i][1] = 0.f; o[i][2] = 0.f; o[i][3] = 0.f;
    }
    float mrun0 = -1e30f, mrun1 = -1e30f, l0 = 0.f, l1 = 0.f;

    for (int kt = 0; kt <= qt; ++kt) {
        int k0 = kt * AKT;
        __syncthreads();
        {
            const __nv_bfloat16* srcs[4] = {kh, kl, vh, vl};
            uint32_t dsts[4] = {skh, skl, svh, svl};
            #pragma unroll
            for (int u = 0; u < 32; ++u) {
                int idx = tid + u * 128;
                int t = idx >> 10, win = idx & 1023;
                int r = win >> 4, c = win & 15;
                const __nv_bfloat16* gp = srcs[t] +
                    (((size_t)(b * SEQ + k0 + r) * KVH + kvh) * HD + c * 8);
                uint32_t d = dsts[t] + off256(r, c);
                asm volatile("cp.async.cg.shared.global [%0], [%1], 16;" :: "r"(d), "l"(gp));
            }
            asm volatile("cp.async.commit_group;" ::: "memory");
            asm volatile("cp.async.wait_group 0;" ::: "memory");
        }
        __syncthreads();

        // ---- S = Q K^T (3 compensated passes) ----
        float s[8][4];
        #pragma unroll
        for (int f = 0; f < 8; f++) {
            s[f][0] = 0.f; s[f][1] = 0.f; s[f][2] = 0.f; s[f][3] = 0.f;
        }
        #pragma unroll
        for (int kk = 0; kk < 8; ++kk) {
            int c = 2 * kk + lsel;
            uint32_t qa[4], qb[4], kb[4][4];
            LDSM4(qa, sqh + off256(w * 16 + lrow, c));
            LDSM4(qb, sql + off256(w * 16 + lrow, c));
            #pragma unroll
            for (int p = 0; p < 4; ++p)
                LDSM4(kb[p], skh + off256(p * 16 + lrow, c));
            #pragma unroll
            for (int p = 0; p < 4; ++p) {
                MMA16816(s[2*p],   qa, kb[p][0], kb[p][1]);
                MMA16816(s[2*p+1], qa, kb[p][2], kb[p][3]);
                MMA16816(s[2*p],   qb, kb[p][0], kb[p][1]);
                MMA16816(s[2*p+1], qb, kb[p][2], kb[p][3]);
            }
            #pragma unroll
            for (int p = 0; p < 4; ++p) {
                LDSM4(kb[p], skl + off256(p * 16 + lrow, c));
                MMA16816(s[2*p],   qa, kb[p][0], kb[p][1]);
                MMA16816(s[2*p+1], qa, kb[p][2], kb[p][3]);
            }
        }

        // ---- causal mask (diagonal tile only) ----
        if (kt == qt) {
            #pragma unroll
            for (int f = 0; f < 8; ++f) {
                #pragma unroll
                for (int cc = 0; cc < 4; ++cc) {
                    int col = f * 8 + (lane & 3) * 2 + (cc & 1);
                    int row = w * 16 + (lane >> 2) + ((cc >> 1) << 3);
                    if (k0 + col > q0 + row) s[f][cc] = -1e30f;
                }
            }
        }

        // ---- online softmax ----
        float mx0 = -1e30f, mx1 = -1e30f;
        #pragma unroll
        for (int f = 0; f < 8; f++) {
            mx0 = fmaxf(mx0, fmaxf(s[f][0], s[f][1]));
            mx1 = fmaxf(mx1, fmaxf(s[f][2], s[f][3]));
        }
        mx0 = fmaxf(mx0, __shfl_xor_sync(0xffffffffu, mx0, 1));
        mx0 = fmaxf(mx0, __shfl_xor_sync(0xffffffffu, mx0, 2));
        mx1 = fmaxf(mx1, __shfl_xor_sync(0xffffffffu, mx1, 1));
        mx1 = fmaxf(mx1, __shfl_xor_sync(0xffffffffu, mx1, 2));

        float mn0 = fmaxf(mrun0, mx0), mn1 = fmaxf(mrun1, mx1);
        float al0 = __expf(mrun0 - mn0), al1 = __expf(mrun1 - mn1);
        mrun0 = mn0; mrun1 = mn1;

        float sum0 = 0.f, sum1 = 0.f;
        #pragma unroll
        for (int f = 0; f < 8; f++) {
            s[f][0] = __expf(s[f][0] - mn0); sum0 += s[f][0];
            s[f][1] = __expf(s[f][1] - mn0); sum0 += s[f][1];
            s[f][2] = __expf(s[f][2] - mn1); sum1 += s[f][2];
            s[f][3] = __expf(s[f][3] - mn1); sum1 += s[f][3];
        }
        sum0 += __shfl_xor_sync(0xffffffffu, sum0, 1);
        sum0 += __shfl_xor_sync(0xffffffffu, sum0, 2);
        sum1 += __shfl_xor_sync(0xffffffffu, sum1, 1);
        sum1 += __shfl_xor_sync(0xffffffffu, sum1, 2);
        l0 = l0 * al0 + sum0;
        l1 = l1 * al1 + sum1;

        #pragma unroll
        for (int nf = 0; nf < 16; ++nf) {
            o[nf][0] *= al0; o[nf][1] *= al0;
            o[nf][2] *= al1; o[nf][3] *= al1;
        }

        // ---- O += P V (3 compensated passes) ----
        #pragma unroll
        for (int j = 0; j < 4; ++j) {
            uint32_t ph[4], pl[4];
            split_pack(s[2*j][0],   s[2*j][1],   ph[0], pl[0]);
            split_pack(s[2*j][2],   s[2*j][3],   ph[1], pl[1]);
            split_pack(s[2*j+1][0], s[2*j+1][1], ph[2], pl[2]);
            split_pack(s[2*j+1][2], s[2*j+1][3], ph[3], pl[3]);
            #pragma unroll
            for (int nb = 0; nb < 8; ++nb) {
                uint32_t vb[4];
                LDSM4T(vb, svh + off256(16 * j + vrow, nb * 2 + vcol));
                MMA_PV(o[2*nb],   ph, vb[0], vb[1]);
                MMA_PV(o[2*nb+1], ph, vb[2], vb[3]);
                MMA_PV(o[2*nb],   pl, vb[0], vb[1]);
                MMA_PV(o[2*nb+1], pl, vb[2], vb[3]);
            }
            #pragma unroll
            for (int nb = 0; nb < 8; ++nb) {
                uint32_t vb[4];
                LDSM4T(vb, svl + off256(16 * j + vrow, nb * 2 + vcol));
                MMA_PV(o[2*nb],   ph, vb[0], vb[1]);
                MMA_PV(o[2*nb+1], ph, vb[2], vb[3]);
            }
        }
    }

    // ---- normalize + write bf16 hi/lo ctx ----
    float inv0 = 1.f / l0, inv1 = 1.f / l1;
    int r0g = q0 + w * 16 + (lane >> 2);
    #pragma unroll
    for (int nf = 0; nf < 16; ++nf) {
        int col = nf * 8 + (lane & 3) * 2;
        size_t base0 = ((size_t)(b * SEQ + r0g) * QH + h) * HD + col;
        size_t base1 = ((size_t)(b * SEQ + r0g + 8) * QH + h) * HD + col;
        uint32_t hh, ll;
        split_pack(o[nf][0] * inv0, o[nf][1] * inv0, hh, ll);
        *reinterpret_cast<uint32_t*>(&ch[base0]) = hh;
        *reinterpret_cast<uint32_t*>(&cl[base0]) = ll;
        split_pack(o[nf][2] * inv1, o[nf][3] * inv1, hh, ll);
        *reinterpret_cast<uint32_t*>(&ch[base1]) = hh;
        *reinterpret_cast<uint32_t*>(&cl[base1]) = ll;
    }
}

// ---------------------------------------------------------------------------
// Launch
// ---------------------------------------------------------------------------
extern "C" void kernel_launch(void* const* d_in, const int* in_sizes, int n_in,
                              void* d_out, int out_size)
{
    const float* x         = (const float*)d_in[0];
    const int*   positions = (const int*)  d_in[1];
    const float* wq        = (const float*)d_in[2];
    const float* wk        = (const float*)d_in[3];
    const float* wv        = (const float*)d_in[4];
    const float* wo        = (const float*)d_in[5];
    float* out = (float*)d_out;

    float *pq, *pk, *pv;
    cudaGetSymbolAddress((void**)&pq, g_q);
    cudaGetSymbolAddress((void**)&pk, g_k);
    cudaGetSymbolAddress((void**)&pv, g_v);

    __nv_bfloat16 *xh, *xl, *wqh, *wql, *wkh, *wkl, *wvh, *wvl, *woh, *wol, *ch, *cl;
    __nv_bfloat16 *aqh, *aql, *akh, *akl, *avh, *avl;
    cudaGetSymbolAddress((void**)&xh,  g_xh);  cudaGetSymbolAddress((void**)&xl,  g_xl);
    cudaGetSymbolAddress((void**)&wqh, g_wqh); cudaGetSymbolAddress((void**)&wql, g_wql);
    cudaGetSymbolAddress((void**)&wkh, g_wkh); cudaGetSymbolAddress((void**)&wkl, g_wkl);
    cudaGetSymbolAddress((void**)&wvh, g_wvh); cudaGetSymbolAddress((void**)&wvl, g_wvl);
    cudaGetSymbolAddress((void**)&woh, g_woh); cudaGetSymbolAddress((void**)&wol, g_wol);
    cudaGetSymbolAddress((void**)&ch,  g_ch);  cudaGetSymbolAddress((void**)&cl,  g_cl);
    cudaGetSymbolAddress((void**)&aqh, g_aqh); cudaGetSymbolAddress((void**)&aql, g_aql);
    cudaGetSymbolAddress((void**)&akh, g_akh); cudaGetSymbolAddress((void**)&akl, g_akl);
    cudaGetSymbolAddress((void**)&avh, g_avh); cudaGetSymbolAddress((void**)&avl, g_avl);

    cudaFuncSetAttribute(gemm_mma_kernel, cudaFuncAttributeMaxDynamicSharedMemorySize,
                         GEMM_SMEM);
    cudaFuncSetAttribute(attn_mma_kernel, cudaFuncAttributeMaxDynamicSharedMemorySize,
                         (int)ATT_SMEM);

    // Splits for projection GEMMs
    {
        int n;
        n = NT * DMODEL;
        split_bf16_kernel<<<(n + 255) / 256, 256>>>(x, xh, xl, n);
        n = QH * HD * DMODEL;
        split_bf16_kernel<<<(n + 255) / 256, 256>>>(wq, wqh, wql, n);
        n = KVH * HD * DMODEL;
        split_bf16_kernel<<<(n + 255) / 256, 256>>>(wk, wkh, wkl, n);
        split_bf16_kernel<<<(n + 255) / 256, 256>>>(wv, wvh, wvl, n);
        n = DMODEL * QH * HD;
        split_bf16_kernel<<<(n + 255) / 256, 256>>>(wo, woh, wol, n);
    }

    // QKV projections
    {
        dim3 blk(256);
        dim3 gq_grid((QH * HD) / 128, NT / 128);
        gemm_mma_kernel<<<gq_grid, blk, GEMM_SMEM>>>(xh, xl, wqh, wql, pq, NT, QH * HD, DMODEL);
        dim3 gkv_grid((KVH * HD) / 128, NT / 128);
        gemm_mma_kernel<<<gkv_grid, blk, GEMM_SMEM>>>(xh, xl, wkh, wkl, pk, NT, KVH * HD, DMODEL);
        gemm_mma_kernel<<<gkv_grid, blk, GEMM_SMEM>>>(xh, xl, wvh, wvl, pv, NT, KVH * HD, DMODEL);
    }

    // RoPE + split (scale folded into Q)
    {
        int tq = NT * QH * 64;
        int tk = NT * KVH * 64;
        rope_split_kernel<<<(tq + 255) / 256, 256>>>(pq, positions, aqh, aql, QH,
                                                     0.08838834764831845f, tq);
        rope_split_kernel<<<(tk + 255) / 256, 256>>>(pk, positions, akh, akl, KVH,
                                                     1.0f, tk);
        int nv = NT * KVH * HD;
        split_bf16_kernel<<<(nv + 255) / 256, 256>>>(pv, avh, avl, nv);
    }

    // Attention (tensor cores) -> ctx bf16 hi/lo
    {
        dim3 grid(SEQ / AQ, QH, BATCH);
        attn_mma_kernel<<<grid, 128, ATT_SMEM>>>(aqh, aql, akh, akl, avh, avl, ch, cl);
    }

    // Output projection
    {
        dim3 blk(256);
        dim3 grid(DMODEL / 128, NT / 128);
        gemm_mma_kernel<<<grid, blk, GEMM_SMEM>>>(ch, cl, woh, wol, out, NT, DMODEL, DMODEL);
    }
}

// round 8
// speedup vs baseline: 4.5564x; 1.0233x over previous
#include <cuda_runtime.h>
#include <cuda_bf16.h>
#include <math.h>
#include <stdint.h>

// Problem constants
#define BATCH 2
#define SEQ   2048
#define DMODEL 2048
#define QH 16
#define KVH 4
#define HD 128
#define NT (BATCH*SEQ)          // 4096 rows

// ---------------------------------------------------------------------------
// Scratch buffers (device globals: no allocation allowed)
// ---------------------------------------------------------------------------
__device__ __nv_bfloat16 g_xh[(size_t)NT * DMODEL];
__device__ __nv_bfloat16 g_xl[(size_t)NT * DMODEL];
__device__ __nv_bfloat16 g_wqh[(size_t)(QH*HD) * DMODEL];
__device__ __nv_bfloat16 g_wql[(size_t)(QH*HD) * DMODEL];
__device__ __nv_bfloat16 g_wkh[(size_t)(KVH*HD) * DMODEL];
__device__ __nv_bfloat16 g_wkl[(size_t)(KVH*HD) * DMODEL];
__device__ __nv_bfloat16 g_wvh[(size_t)(KVH*HD) * DMODEL];
__device__ __nv_bfloat16 g_wvl[(size_t)(KVH*HD) * DMODEL];
__device__ __nv_bfloat16 g_woh[(size_t)DMODEL * (QH*HD)];
__device__ __nv_bfloat16 g_wol[(size_t)DMODEL * (QH*HD)];
__device__ __nv_bfloat16 g_ch[(size_t)NT * (QH*HD)];
__device__ __nv_bfloat16 g_cl[(size_t)NT * (QH*HD)];

// attention bf16 hi/lo inputs (post-RoPE, written by GEMM epilogues)
__device__ __nv_bfloat16 g_aqh[(size_t)NT * QH * HD];
__device__ __nv_bfloat16 g_aql[(size_t)NT * QH * HD];
__device__ __nv_bfloat16 g_akh[(size_t)NT * KVH * HD];
__device__ __nv_bfloat16 g_akl[(size_t)NT * KVH * HD];
__device__ __nv_bfloat16 g_avh[(size_t)NT * KVH * HD];
__device__ __nv_bfloat16 g_avl[(size_t)NT * KVH * HD];

// ---------------------------------------------------------------------------
// helpers
// ---------------------------------------------------------------------------
__device__ __forceinline__ void split_pack(float e0, float e1,
                                           uint32_t& hi, uint32_t& lo)
{
    __nv_bfloat16 h0 = __float2bfloat16(e0);
    __nv_bfloat16 h1 = __float2bfloat16(e1);
    hi = ((uint32_t)__bfloat16_as_ushort(h1) << 16) | __bfloat16_as_ushort(h0);
    __nv_bfloat16 g0 = __float2bfloat16(e0 - __bfloat162float(h0));
    __nv_bfloat16 g1 = __float2bfloat16(e1 - __bfloat162float(h1));
    lo = ((uint32_t)__bfloat16_as_ushort(g1) << 16) | __bfloat16_as_ushort(g0);
}

// vectorized split: 4 elems/thread
__global__ void split_bf16_kernel(const float4* __restrict__ in,
                                  uint2* __restrict__ hi,
                                  uint2* __restrict__ lo, int n4)
{
    int i = blockIdx.x * blockDim.x + threadIdx.x;
    if (i >= n4) return;
    float4 v = in[i];
    uint2 h, l;
    split_pack(v.x, v.y, h.x, l.x);
    split_pack(v.z, v.w, h.y, l.y);
    hi[i] = h;
    lo[i] = l;
}

#define LDSM4(r, addr) \
    asm volatile("ldmatrix.sync.aligned.m8n8.x4.shared.b16 {%0,%1,%2,%3}, [%4];" \
        : "=r"((r)[0]), "=r"((r)[1]), "=r"((r)[2]), "=r"((r)[3]) : "r"(addr))

#define LDSM4T(r, addr) \
    asm volatile("ldmatrix.sync.aligned.m8n8.x4.trans.shared.b16 {%0,%1,%2,%3}, [%4];" \
        : "=r"((r)[0]), "=r"((r)[1]), "=r"((r)[2]), "=r"((r)[3]) : "r"(addr))

// A from ldmatrix (reorder 0,2,1,3)
#define MMA16816(acc, A, B0, B1) \
    asm volatile("mma.sync.aligned.m16n8k16.row.col.f32.bf16.bf16.f32 " \
        "{%0,%1,%2,%3}, {%4,%5,%6,%7}, {%8,%9}, {%0,%1,%2,%3};" \
        : "+f"((acc)[0]), "+f"((acc)[1]), "+f"((acc)[2]), "+f"((acc)[3]) \
        : "r"((A)[0]), "r"((A)[2]), "r"((A)[1]), "r"((A)[3]), "r"(B0), "r"(B1))

// A already in mma register order
#define MMA_PV(acc, A, B0, B1) \
    asm volatile("mma.sync.aligned.m16n8k16.row.col.f32.bf16.bf16.f32 " \
        "{%0,%1,%2,%3}, {%4,%5,%6,%7}, {%8,%9}, {%0,%1,%2,%3};" \
        : "+f"((acc)[0]), "+f"((acc)[1]), "+f"((acc)[2]), "+f"((acc)[3]) \
        : "r"((A)[0]), "r"((A)[1]), "r"((A)[2]), "r"((A)[3]), "r"(B0), "r"(B1))

// ---------------------------------------------------------------------------
// mma.sync bf16 GEMM with bf16x3 compensation.
// C[M,N] = A[M,K] * B[N,K]^T.  CTA tile 128x128, BK=32, 3-stage cp.async.
// EPI: 0 = fp32 C store, 1 = bf16 hi/lo split store, 2 = rope+scale+split.
// ---------------------------------------------------------------------------
#define BKK 32
#define TILE_B 8192u
#define STAGE_B (4u*TILE_B)
#define NSTAGE 3
#define GEMM_SMEM (NSTAGE*STAGE_B)

__device__ __forceinline__ uint32_t phys_off(int r, int c) {
    return (uint32_t)(r * 64 + (((c ^ (r >> 1)) & 3) << 4));
}

__device__ __forceinline__ void gemm_issue_stage(
    uint32_t sbase, int st, int it, int row0, int col0, int tid, int K,
    const __nv_bfloat16* Ah, const __nv_bfloat16* Al,
    const __nv_bfloat16* Bh, const __nv_bfloat16* Bl)
{
    int k0 = it * BKK;
    uint32_t dst0 = sbase + (uint32_t)st * STAGE_B;
    const __nv_bfloat16* srcs[4] = {Ah, Al, Bh, Bl};
    #pragma unroll
    for (int u = 0; u < 8; ++u) {
        int idx = tid + u * 256;
        int t = idx >> 9;
        int win = idx & 511;
        int r = win >> 2, c = win & 3;
        int gr = ((t < 2) ? row0 : col0) + r;
        const __nv_bfloat16* gp = srcs[t] + (size_t)gr * K + k0 + c * 8;
        uint32_t d = dst0 + (uint32_t)t * TILE_B + phys_off(r, c);
        asm volatile("cp.async.cg.shared.global [%0], [%1], 16;"
                     :: "r"(d), "l"(gp));
    }
    asm volatile("cp.async.commit_group;" ::: "memory");
}

template <int EPI>
__global__ __launch_bounds__(256)
void gemm_mma_kernel(const __nv_bfloat16* __restrict__ Ah,
                     const __nv_bfloat16* __restrict__ Al,
                     const __nv_bfloat16* __restrict__ Bh,
                     const __nv_bfloat16* __restrict__ Bl,
                     float* __restrict__ C,
                     __nv_bfloat16* __restrict__ Dh,
                     __nv_bfloat16* __restrict__ Dl,
                     const int* __restrict__ positions, float scale,
                     int M, int N, int K)
{
    extern __shared__ char smem[];
    uint32_t sbase = (uint32_t)__cvta_generic_to_shared(smem);

    int tid = threadIdx.x;
    int lane = tid & 31;
    int w = tid >> 5;
    int wm = w & 3;
    int wn = w >> 2;
    int row0 = blockIdx.y * 128;
    int col0 = blockIdx.x * 128;

    float acc[2][8][4];
    #pragma unroll
    for (int i = 0; i < 2; i++)
        #pragma unroll
        for (int j = 0; j < 8; j++)
            #pragma unroll
            for (int q = 0; q < 4; q++) acc[i][j][q] = 0.f;

    const int nIter = K / BKK;

    gemm_issue_stage(sbase, 0, 0, row0, col0, tid, K, Ah, Al, Bh, Bl);
    gemm_issue_stage(sbase, 1, 1, row0, col0, tid, K, Ah, Al, Bh, Bl);

    int lrow = (lane & 7) + ((lane >> 4) << 3);
    int lsel = (lane >> 3) & 1;

    for (int it = 0; it < nIter; ++it) {
        if (it + 2 < nIter)
            gemm_issue_stage(sbase, (it + 2) % NSTAGE, it + 2, row0, col0, tid, K,
                             Ah, Al, Bh, Bl);
        if (it + 2 < nIter)
            asm volatile("cp.async.wait_group 2;" ::: "memory");
        else if (it + 1 < nIter)
            asm volatile("cp.async.wait_group 1;" ::: "memory");
        else
            asm volatile("cp.async.wait_group 0;" ::: "memory");
        __syncthreads();

        uint32_t tb = sbase + (uint32_t)(it % NSTAGE) * STAGE_B;
        uint32_t aH = tb;
        uint32_t aL = tb + TILE_B;
        uint32_t bHb = tb + 2 * TILE_B;
        uint32_t bLb = tb + 3 * TILE_B;

        #pragma unroll
        for (int kk = 0; kk < 2; ++kk) {
            int c = 2 * kk + lsel;
            uint32_t a[2][4], b[4][4];

            #pragma unroll
            for (int mf = 0; mf < 2; ++mf) {
                int r = wm * 32 + mf * 16 + lrow;
                LDSM4(a[mf], aL + phys_off(r, c));
            }
            #pragma unroll
            for (int p = 0; p < 4; ++p) {
                int r = wn * 64 + p * 16 + lrow;
                LDSM4(b[p], bHb + phys_off(r, c));
            }
            #pragma unroll
            for (int mf = 0; mf < 2; ++mf)
                #pragma unroll
                for (int p = 0; p < 4; ++p) {
                    MMA16816(acc[mf][2*p],   a[mf], b[p][0], b[p][1]);
                    MMA16816(acc[mf][2*p+1], a[mf], b[p][2], b[p][3]);
                }

            #pragma unroll
            for (int mf = 0; mf < 2; ++mf) {
                int r = wm * 32 + mf * 16 + lrow;
                LDSM4(a[mf], aH + phys_off(r, c));
            }
            #pragma unroll
            for (int mf = 0; mf < 2; ++mf)
                #pragma unroll
                for (int p = 0; p < 4; ++p) {
                    MMA16816(acc[mf][2*p],   a[mf], b[p][0], b[p][1]);
                    MMA16816(acc[mf][2*p+1], a[mf], b[p][2], b[p][3]);
                }

            #pragma unroll
            for (int p = 0; p < 4; ++p) {
                int r = wn * 64 + p * 16 + lrow;
                LDSM4(b[p], bLb + phys_off(r, c));
            }
            #pragma unroll
            for (int mf = 0; mf < 2; ++mf)
                #pragma unroll
                for (int p = 0; p < 4; ++p) {
                    MMA16816(acc[mf][2*p],   a[mf], b[p][0], b[p][1]);
                    MMA16816(acc[mf][2*p+1], a[mf], b[p][2], b[p][3]);
                }
        }
        __syncthreads();
    }

    if (EPI == 0) {
        // fp32 store
        #pragma unroll
        for (int mf = 0; mf < 2; ++mf) {
            int rbase = row0 + wm * 32 + mf * 16 + (lane >> 2);
            #pragma unroll
            for (int nf = 0; nf < 8; ++nf) {
                int cc = col0 + wn * 64 + nf * 8 + (lane & 3) * 2;
                float2 v0 = make_float2(acc[mf][nf][0], acc[mf][nf][1]);
                float2 v1 = make_float2(acc[mf][nf][2], acc[mf][nf][3]);
                *reinterpret_cast<float2*>(&C[(size_t)rbase * N + cc]) = v0;
                *reinterpret_cast<float2*>(&C[(size_t)(rbase + 8) * N + cc]) = v1;
            }
        }
    } else if (EPI == 1) {
        // bf16 hi/lo split, register-direct
        #pragma unroll
        for (int mf = 0; mf < 2; ++mf) {
            int rbase = row0 + wm * 32 + mf * 16 + (lane >> 2);
            #pragma unroll
            for (int nf = 0; nf < 8; ++nf) {
                int cc = col0 + wn * 64 + nf * 8 + (lane & 3) * 2;
                uint32_t hh, ll;
                split_pack(acc[mf][nf][0], acc[mf][nf][1], hh, ll);
                *reinterpret_cast<uint32_t*>(&Dh[(size_t)rbase * N + cc]) = hh;
                *reinterpret_cast<uint32_t*>(&Dl[(size_t)rbase * N + cc]) = ll;
                split_pack(acc[mf][nf][2], acc[mf][nf][3], hh, ll);
                *reinterpret_cast<uint32_t*>(&Dh[(size_t)(rbase + 8) * N + cc]) = hh;
                *reinterpret_cast<uint32_t*>(&Dl[(size_t)(rbase + 8) * N + cc]) = ll;
            }
        }
    } else {
        // rope + scale + split. Stage fp32 acc through smem (d <-> d+64 pairing
        // crosses warps). col0 block == one head (N % 128 == 0, HD == 128).
        float* S = reinterpret_cast<float*>(smem);
        #pragma unroll
        for (int mf = 0; mf < 2; ++mf) {
            int rl = wm * 32 + mf * 16 + (lane >> 2);
            #pragma unroll
            for (int nf = 0; nf < 8; ++nf) {
                int cl2 = wn * 64 + nf * 8 + (lane & 3) * 2;
                S[rl * 132 + cl2]           = acc[mf][nf][0];
                S[rl * 132 + cl2 + 1]       = acc[mf][nf][1];
                S[(rl + 8) * 132 + cl2]     = acc[mf][nf][2];
                S[(rl + 8) * 132 + cl2 + 1] = acc[mf][nf][3];
            }
        }
        __syncthreads();
        #pragma unroll
        for (int u = 0; u < 32; ++u) {
            int idx = tid + u * 256;          // 0..8191
            int r = idx >> 6, j = idx & 63;
            float x1 = S[r * 132 + j];
            float x2 = S[r * 132 + j + 64];
            float pos = (float)positions[row0 + r];
            float inv = expf(-9.210340371976184f * (float)j * (1.0f / 64.0f));
            float sn, cs;
            sincosf(pos * inv, &sn, &cs);
            float y1 = (x1 * cs - x2 * sn) * scale;
            float y2 = (x1 * sn + x2 * cs) * scale;
            size_t base = (size_t)(row0 + r) * N + col0 + j;
            __nv_bfloat16 h1 = __float2bfloat16(y1);
            __nv_bfloat16 h2 = __float2bfloat16(y2);
            Dh[base]      = h1;
            Dl[base]      = __float2bfloat16(y1 - __bfloat162float(h1));
            Dh[base + 64] = h2;
            Dl[base + 64] = __float2bfloat16(y2 - __bfloat162float(h2));
        }
    }
}

// ---------------------------------------------------------------------------
// Tensor-core flash attention, bf16 compensated, double-buffered KV.
// CTA: 64 queries x (head, batch). 4 warps. K tile = 32, 2 stages.
// smem: qh,ql (16KB each) + 2 stages x {kh,kl,vh,vl} (8KB each) = 96KB.
// ---------------------------------------------------------------------------
#define AQ 64
#define AKT 32
#define QTILE 16384u
#define KVTILE 8192u
#define KVSTAGE (4u*KVTILE)
#define ATT_SMEM (2u*QTILE + 2u*KVSTAGE)   // 96 KB

__device__ __forceinline__ uint32_t off256(int r, int c) {
    return (uint32_t)(r * 256 + (((c ^ (r & 7)) & 15) << 4));
}

__device__ __forceinline__ void attn_load_kv(
    uint32_t dst, int tid, int b, int kvh, int k0,
    const __nv_bfloat16* kh, const __nv_bfloat16* kl,
    const __nv_bfloat16* vh, const __nv_bfloat16* vl)
{
    const __nv_bfloat16* srcs[4] = {kh, kl, vh, vl};
    #pragma unroll
    for (int u = 0; u < 16; ++u) {
        int idx = tid + u * 128;          // 0..2047
        int t = idx >> 9, win = idx & 511;
        int r = win >> 4, c = win & 15;
        const __nv_bfloat16* gp = srcs[t] +
            (((size_t)(b * SEQ + k0 + r) * KVH + kvh) * HD + c * 8);
        uint32_t d = dst + (uint32_t)t * KVTILE + off256(r, c);
        asm volatile("cp.async.cg.shared.global [%0], [%1], 16;" :: "r"(d), "l"(gp));
    }
}

__global__ __launch_bounds__(128)
void attn_mma_kernel(const __nv_bfloat16* __restrict__ qh, const __nv_bfloat16* __restrict__ ql,
                     const __nv_bfloat16* __restrict__ kh, const __nv_bfloat16* __restrict__ kl,
                     const __nv_bfloat16* __restrict__ vh, const __nv_bfloat16* __restrict__ vl,
                     __nv_bfloat16* __restrict__ ch, __nv_bfloat16* __restrict__ cl)
{
    extern __shared__ char asmem[];
    uint32_t sb = (uint32_t)__cvta_generic_to_shared(asmem);
    uint32_t sqh = sb, sql = sb + QTILE;
    uint32_t kvs0 = sb + 2 * QTILE;

    int qt = blockIdx.x, h = blockIdx.y, b = blockIdx.z;
    int tid = threadIdx.x, lane = tid & 31, w = tid >> 5;
    int q0 = qt * AQ;
    int kvh = h >> 2;

    int lrow = (lane & 7) | ((lane >> 4) << 3);
    int lsel = (lane >> 3) & 1;
    int vrow = (lane & 7) | (((lane >> 3) & 1) << 3);
    int vcol = lane >> 4;

    const int nt = 2 * qt + 2;   // number of 32-key tiles

    // group 0: Q (hi+lo) + KV tile 0
    {
        const __nv_bfloat16* srcs[2] = {qh, ql};
        uint32_t dsts[2] = {sqh, sql};
        #pragma unroll
        for (int u = 0; u < 16; ++u) {
            int idx = tid + u * 128;
            int t = idx >> 10, win = idx & 1023;
            int r = win >> 4, c = win & 15;
            const __nv_bfloat16* gp = srcs[t] +
                (((size_t)(b * SEQ + q0 + r) * QH + h) * HD + c * 8);
            uint32_t d = dsts[t] + off256(r, c);
            asm volatile("cp.async.cg.shared.global [%0], [%1], 16;" :: "r"(d), "l"(gp));
        }
        attn_load_kv(kvs0, tid, b, kvh, 0, kh, kl, vh, vl);
        asm volatile("cp.async.commit_group;" ::: "memory");
    }
    // group 1: KV tile 1
    attn_load_kv(kvs0 + KVSTAGE, tid, b, kvh, AKT, kh, kl, vh, vl);
    asm volatile("cp.async.commit_group;" ::: "memory");

    float o[16][4];
    #pragma unroll
    for (int i = 0; i < 16; i++) {
        o[i][0] = 0.f; o[i][1] = 0.f; o[i][2] = 0.f; o[i][3] = 0.f;
    }
    float mrun0 = -1e30f, mrun1 = -1e30f, l0 = 0.f, l1 = 0.f;

    for (int kt = 0; kt < nt; ++kt) {
        int k0 = kt * AKT;
        if (kt + 1 < nt)
            asm volatile("cp.async.wait_group 1;" ::: "memory");
        else
            asm volatile("cp.async.wait_group 0;" ::: "memory");
        __syncthreads();

        uint32_t st = kvs0 + (uint32_t)(kt & 1) * KVSTAGE;
        uint32_t skh = st, skl = st + KVTILE;
        uint32_t svh = st + 2 * KVTILE, svl = st + 3 * KVTILE;

        // ---- S = Q K^T (3 compensated passes), 32 keys ----
        float s[4][4];
        #pragma unroll
        for (int f = 0; f < 4; f++) {
            s[f][0] = 0.f; s[f][1] = 0.f; s[f][2] = 0.f; s[f][3] = 0.f;
        }
        #pragma unroll
        for (int kk = 0; kk < 8; ++kk) {
            int c = 2 * kk + lsel;
            uint32_t qa[4], qb[4], kbf[2][4];
            LDSM4(qa, sqh + off256(w * 16 + lrow, c));
            LDSM4(qb, sql + off256(w * 16 + lrow, c));
            #pragma unroll
            for (int p = 0; p < 2; ++p)
                LDSM4(kbf[p], skh + off256(p * 16 + lrow, c));
            #pragma unroll
            for (int p = 0; p < 2; ++p) {
                MMA16816(s[2*p],   qa, kbf[p][0], kbf[p][1]);
                MMA16816(s[2*p+1], qa, kbf[p][2], kbf[p][3]);
                MMA16816(s[2*p],   qb, kbf[p][0], kbf[p][1]);
                MMA16816(s[2*p+1], qb, kbf[p][2], kbf[p][3]);
            }
            #pragma unroll
            for (int p = 0; p < 2; ++p) {
                LDSM4(kbf[p], skl + off256(p * 16 + lrow, c));
                MMA16816(s[2*p],   qa, kbf[p][0], kbf[p][1]);
                MMA16816(s[2*p+1], qa, kbf[p][2], kbf[p][3]);
            }
        }

        // ---- causal mask (only last two tiles can cross the diagonal) ----
        if (k0 + AKT - 1 > q0) {
            #pragma unroll
            for (int f = 0; f < 4; ++f) {
                #pragma unroll
                for (int cc = 0; cc < 4; ++cc) {
                    int col = f * 8 + (lane & 3) * 2 + (cc & 1);
                    int row = w * 16 + (lane >> 2) + ((cc >> 1) << 3);
                    if (k0 + col > q0 + row) s[f][cc] = -1e30f;
                }
            }
        }

        // ---- online softmax ----
        float mx0 = -1e30f, mx1 = -1e30f;
        #pragma unroll
        for (int f = 0; f < 4; f++) {
            mx0 = fmaxf(mx0, fmaxf(s[f][0], s[f][1]));
            mx1 = fmaxf(mx1, fmaxf(s[f][2], s[f][3]));
        }
        mx0 = fmaxf(mx0, __shfl_xor_sync(0xffffffffu, mx0, 1));
        mx0 = fmaxf(mx0, __shfl_xor_sync(0xffffffffu, mx0, 2));
        mx1 = fmaxf(mx1, __shfl_xor_sync(0xffffffffu, mx1, 1));
        mx1 = fmaxf(mx1, __shfl_xor_sync(0xffffffffu, mx1, 2));

        float mn0 = fmaxf(mrun0, mx0), mn1 = fmaxf(mrun1, mx1);
        float al0 = __expf(mrun0 - mn0), al1 = __expf(mrun1 - mn1);
        mrun0 = mn0; mrun1 = mn1;

        float sum0 = 0.f, sum1 = 0.f;
        #pragma unroll
        for (int f = 0; f < 4; f++) {
            s[f][0] = __expf(s[f][0] - mn0); sum0 += s[f][0];
            s[f][1] = __expf(s[f][1] - mn0); sum0 += s[f][1];
            s[f][2] = __expf(s[f][2] - mn1); sum1 += s[f][2];
            s[f][3] = __expf(s[f][3] - mn1); sum1 += s[f][3];
        }
        sum0 += __shfl_xor_sync(0xffffffffu, sum0, 1);
        sum0 += __shfl_xor_sync(0xffffffffu, sum0, 2);
        sum1 += __shfl_xor_sync(0xffffffffu, sum1, 1);
        sum1 += __shfl_xor_sync(0xffffffffu, sum1, 2);
        l0 = l0 * al0 + sum0;
        l1 = l1 * al1 + sum1;

        #pragma unroll
        for (int nf = 0; nf < 16; ++nf) {
            o[nf][0] *= al0; o[nf][1] *= al0;
            o[nf][2] *= al1; o[nf][3] *= al1;
        }

        // ---- O += P V (3 compensated passes) ----
        #pragma unroll
        for (int j = 0; j < 2; ++j) {
            uint32_t ph[4], pl[4];
            split_pack(s[2*j][0],   s[2*j][1],   ph[0], pl[0]);
            split_pack(s[2*j][2],   s[2*j][3],   ph[1], pl[1]);
            split_pack(s[2*j+1][0], s[2*j+1][1], ph[2], pl[2]);
            split_pack(s[2*j+1][2], s[2*j+1][3], ph[3], pl[3]);
            #pragma unroll
            for (int nb = 0; nb < 8; ++nb) {
                uint32_t vb[4];
                LDSM4T(vb, svh + off256(16 * j + vrow, nb * 2 + vcol));
                MMA_PV(o[2*nb],   ph, vb[0], vb[1]);
                MMA_PV(o[2*nb+1], ph, vb[2], vb[3]);
                MMA_PV(o[2*nb],   pl, vb[0], vb[1]);
                MMA_PV(o[2*nb+1], pl, vb[2], vb[3]);
            }
            #pragma unroll
            for (int nb = 0; nb < 8; ++nb) {
                uint32_t vb[4];
                LDSM4T(vb, svl + off256(16 * j + vrow, nb * 2 + vcol));
                MMA_PV(o[2*nb],   ph, vb[0], vb[1]);
                MMA_PV(o[2*nb+1], ph, vb[2], vb[3]);
            }
        }

        __syncthreads();
        if (kt + 2 < nt) {
            attn_load_kv(kvs0 + (uint32_t)(kt & 1) * KVSTAGE, tid, b, kvh,
                         (kt + 2) * AKT, kh, kl, vh, vl);
            asm volatile("cp.async.commit_group;" ::: "memory");
        }
    }

    // ---- normalize + write bf16 hi/lo ctx ----
    float inv0 = 1.f / l0, inv1 = 1.f / l1;
    int r0g = q0 + w * 16 + (lane >> 2);
    #pragma unroll
    for (int nf = 0; nf < 16; ++nf) {
        int col = nf * 8 + (lane & 3) * 2;
        size_t base0 = ((size_t)(b * SEQ + r0g) * QH + h) * HD + col;
        size_t base1 = ((size_t)(b * SEQ + r0g + 8) * QH + h) * HD + col;
        uint32_t hh, ll;
        split_pack(o[nf][0] * inv0, o[nf][1] * inv0, hh, ll);
        *reinterpret_cast<uint32_t*>(&ch[base0]) = hh;
        *reinterpret_cast<uint32_t*>(&cl[base0]) = ll;
        split_pack(o[nf][2] * inv1, o[nf][3] * inv1, hh, ll);
        *reinterpret_cast<uint32_t*>(&ch[base1]) = hh;
        *reinterpret_cast<uint32_t*>(&cl[base1]) = ll;
    }
}

// ---------------------------------------------------------------------------
// Launch
// ---------------------------------------------------------------------------
extern "C" void kernel_launch(void* const* d_in, const int* in_sizes, int n_in,
                              void* d_out, int out_size)
{
    const float* x         = (const float*)d_in[0];
    const int*   positions = (const int*)  d_in[1];
    const float* wq        = (const float*)d_in[2];
    const float* wk        = (const float*)d_in[3];
    const float* wv        = (const float*)d_in[4];
    const float* wo        = (const float*)d_in[5];
    float* out = (float*)d_out;

    __nv_bfloat16 *xh, *xl, *wqh, *wql, *wkh, *wkl, *wvh, *wvl, *woh, *wol, *ch, *cl;
    __nv_bfloat16 *aqh, *aql, *akh, *akl, *avh, *avl;
    cudaGetSymbolAddress((void**)&xh,  g_xh);  cudaGetSymbolAddress((void**)&xl,  g_xl);
    cudaGetSymbolAddress((void**)&wqh, g_wqh); cudaGetSymbolAddress((void**)&wql, g_wql);
    cudaGetSymbolAddress((void**)&wkh, g_wkh); cudaGetSymbolAddress((void**)&wkl, g_wkl);
    cudaGetSymbolAddress((void**)&wvh, g_wvh); cudaGetSymbolAddress((void**)&wvl, g_wvl);
    cudaGetSymbolAddress((void**)&woh, g_woh); cudaGetSymbolAddress((void**)&wol, g_wol);
    cudaGetSymbolAddress((void**)&ch,  g_ch);  cudaGetSymbolAddress((void**)&cl,  g_cl);
    cudaGetSymbolAddress((void**)&aqh, g_aqh); cudaGetSymbolAddress((void**)&aql, g_aql);
    cudaGetSymbolAddress((void**)&akh, g_akh); cudaGetSymbolAddress((void**)&akl, g_akl);
    cudaGetSymbolAddress((void**)&avh, g_avh); cudaGetSymbolAddress((void**)&avl, g_avl);

    cudaFuncSetAttribute(gemm_mma_kernel<0>, cudaFuncAttributeMaxDynamicSharedMemorySize, GEMM_SMEM);
    cudaFuncSetAttribute(gemm_mma_kernel<1>, cudaFuncAttributeMaxDynamicSharedMemorySize, GEMM_SMEM);
    cudaFuncSetAttribute(gemm_mma_kernel<2>, cudaFuncAttributeMaxDynamicSharedMemorySize, GEMM_SMEM);
    cudaFuncSetAttribute(attn_mma_kernel, cudaFuncAttributeMaxDynamicSharedMemorySize, (int)ATT_SMEM);

    // Splits (vectorized) for GEMM inputs
    {
        int n4;
        n4 = NT * DMODEL / 4;
        split_bf16_kernel<<<(n4 + 255) / 256, 256>>>((const float4*)x, (uint2*)xh, (uint2*)xl, n4);
        n4 = QH * HD * DMODEL / 4;
        split_bf16_kernel<<<(n4 + 255) / 256, 256>>>((const float4*)wq, (uint2*)wqh, (uint2*)wql, n4);
        n4 = KVH * HD * DMODEL / 4;
        split_bf16_kernel<<<(n4 + 255) / 256, 256>>>((const float4*)wk, (uint2*)wkh, (uint2*)wkl, n4);
        split_bf16_kernel<<<(n4 + 255) / 256, 256>>>((const float4*)wv, (uint2*)wvh, (uint2*)wvl, n4);
        n4 = DMODEL * QH * HD / 4;
        split_bf16_kernel<<<(n4 + 255) / 256, 256>>>((const float4*)wo, (uint2*)woh, (uint2*)wol, n4);
    }

    const float qscale = 0.08838834764831845f;   // 1/sqrt(128)

    // Projections with fused epilogues
    {
        dim3 blk(256);
        dim3 gq_grid((QH * HD) / 128, NT / 128);
        gemm_mma_kernel<2><<<gq_grid, blk, GEMM_SMEM>>>(
            xh, xl, wqh, wql, nullptr, aqh, aql, positions, qscale, NT, QH * HD, DMODEL);
        dim3 gkv_grid((KVH * HD) / 128, NT / 128);
        gemm_mma_kernel<2><<<gkv_grid, blk, GEMM_SMEM>>>(
            xh, xl, wkh, wkl, nullptr, akh, akl, positions, 1.0f, NT, KVH * HD, DMODEL);
        gemm_mma_kernel<1><<<gkv_grid, blk, GEMM_SMEM>>>(
            xh, xl, wvh, wvl, nullptr, avh, avl, nullptr, 1.0f, NT, KVH * HD, DMODEL);
    }

    // Attention (tensor cores, double-buffered KV) -> ctx bf16 hi/lo
    {
        dim3 grid(SEQ / AQ, QH, BATCH);
        attn_mma_kernel<<<grid, 128, ATT_SMEM>>>(aqh, aql, akh, akl, avh, avl, ch, cl);
    }

    // Output projection (fp32 epilogue)
    {
        dim3 blk(256);
        dim3 grid(DMODEL / 128, NT / 128);
        gemm_mma_kernel<0><<<grid, blk, GEMM_SMEM>>>(
            ch, cl, woh, wol, out, nullptr, nullptr, nullptr, 1.0f, NT, DMODEL, DMODEL);
    }
}

// round 9
// speedup vs baseline: 6.2076x; 1.3624x over previous
#include <cuda_runtime.h>
#include <cuda_fp16.h>
#include <math.h>
#include <stdint.h>

// Problem constants
#define BATCH 2
#define SEQ   2048
#define DMODEL 2048
#define QH 16
#define KVH 4
#define HD 128
#define NT (BATCH*SEQ)          // 4096 rows

// ---------------------------------------------------------------------------
// Scratch buffers (device globals: no allocation allowed)
// ---------------------------------------------------------------------------
__device__ __half g_xh[(size_t)NT * DMODEL];
__device__ __half g_xl[(size_t)NT * DMODEL];
__device__ __half g_wqh[(size_t)(QH*HD) * DMODEL];
__device__ __half g_wkh[(size_t)(KVH*HD) * DMODEL];
__device__ __half g_wvh[(size_t)(KVH*HD) * DMODEL];
__device__ __half g_woh[(size_t)DMODEL * (QH*HD)];
__device__ __half g_ch[(size_t)NT * (QH*HD)];
__device__ __half g_cl[(size_t)NT * (QH*HD)];

// attention inputs (post-RoPE)
__device__ __half g_aqh[(size_t)NT * QH * HD];
__device__ __half g_aql[(size_t)NT * QH * HD];
__device__ __half g_akh[(size_t)NT * KVH * HD];
__device__ __half g_avh[(size_t)NT * KVH * HD];

// ---------------------------------------------------------------------------
// helpers
// ---------------------------------------------------------------------------
__device__ __forceinline__ void split_pack(float e0, float e1,
                                           uint32_t& hi, uint32_t& lo)
{
    __half h0 = __float2half_rn(e0);
    __half h1 = __float2half_rn(e1);
    hi = ((uint32_t)__half_as_ushort(h1) << 16) | __half_as_ushort(h0);
    __half g0 = __float2half_rn(e0 - __half2float(h0));
    __half g1 = __float2half_rn(e1 - __half2float(h1));
    lo = ((uint32_t)__half_as_ushort(g1) << 16) | __half_as_ushort(g0);
}

__device__ __forceinline__ uint32_t pack_h2(float e0, float e1)
{
    __half h0 = __float2half_rn(e0);
    __half h1 = __float2half_rn(e1);
    return ((uint32_t)__half_as_ushort(h1) << 16) | __half_as_ushort(h0);
}

// x: hi/lo split, 4 elems/thread
__global__ void split_h_kernel(const float4* __restrict__ in,
                               uint2* __restrict__ hi,
                               uint2* __restrict__ lo, int n4)
{
    int i = blockIdx.x * blockDim.x + threadIdx.x;
    if (i >= n4) return;
    float4 v = in[i];
    uint2 h, l;
    split_pack(v.x, v.y, h.x, l.x);
    split_pack(v.z, v.w, h.y, l.y);
    hi[i] = h;
    lo[i] = l;
}

// weights: fp16 convert only
__global__ void tohalf_kernel(const float4* __restrict__ in,
                              uint2* __restrict__ hi, int n4)
{
    int i = blockIdx.x * blockDim.x + threadIdx.x;
    if (i >= n4) return;
    float4 v = in[i];
    uint2 h;
    h.x = pack_h2(v.x, v.y);
    h.y = pack_h2(v.z, v.w);
    hi[i] = h;
}

#define LDSM4(r, addr) \
    asm volatile("ldmatrix.sync.aligned.m8n8.x4.shared.b16 {%0,%1,%2,%3}, [%4];" \
        : "=r"((r)[0]), "=r"((r)[1]), "=r"((r)[2]), "=r"((r)[3]) : "r"(addr))

#define LDSM4T(r, addr) \
    asm volatile("ldmatrix.sync.aligned.m8n8.x4.trans.shared.b16 {%0,%1,%2,%3}, [%4];" \
        : "=r"((r)[0]), "=r"((r)[1]), "=r"((r)[2]), "=r"((r)[3]) : "r"(addr))

// A from ldmatrix (reorder 0,2,1,3)
#define MMA16816(acc, A, B0, B1) \
    asm volatile("mma.sync.aligned.m16n8k16.row.col.f32.f16.f16.f32 " \
        "{%0,%1,%2,%3}, {%4,%5,%6,%7}, {%8,%9}, {%0,%1,%2,%3};" \
        : "+f"((acc)[0]), "+f"((acc)[1]), "+f"((acc)[2]), "+f"((acc)[3]) \
        : "r"((A)[0]), "r"((A)[2]), "r"((A)[1]), "r"((A)[3]), "r"(B0), "r"(B1))

// A already in mma register order
#define MMA_PV(acc, A, B0, B1) \
    asm volatile("mma.sync.aligned.m16n8k16.row.col.f32.f16.f16.f32 " \
        "{%0,%1,%2,%3}, {%4,%5,%6,%7}, {%8,%9}, {%0,%1,%2,%3};" \
        : "+f"((acc)[0]), "+f"((acc)[1]), "+f"((acc)[2]), "+f"((acc)[3]) \
        : "r"((A)[0]), "r"((A)[1]), "r"((A)[2]), "r"((A)[3]), "r"(B0), "r"(B1))

// ---------------------------------------------------------------------------
// mma.sync fp16 GEMM, 2-pass compensation (AhBh + AlBh).
// C[M,N] = A[M,K] * B[N,K]^T.  CTA tile 128x128, BK=32, 3-stage cp.async.
// EPI: 0 = fp32 C store, 1 = fp16 store (hi only), 2 = rope+split store.
// ---------------------------------------------------------------------------
#define BKK 32
#define TILE_B 8192u
#define STAGE_B (3u*TILE_B)     // Ah, Al, Bh
#define NSTAGE 3
#define GEMM_SMEM (NSTAGE*STAGE_B)   // 72 KB

__device__ __forceinline__ uint32_t phys_off(int r, int c) {
    return (uint32_t)(r * 64 + (((c ^ (r >> 1)) & 3) << 4));
}

__device__ __forceinline__ void gemm_issue_stage(
    uint32_t sbase, int st, int it, int row0, int col0, int tid, int K,
    const __half* Ah, const __half* Al, const __half* Bh)
{
    int k0 = it * BKK;
    uint32_t dst0 = sbase + (uint32_t)st * STAGE_B;
    const __half* srcs[3] = {Ah, Al, Bh};
    #pragma unroll
    for (int u = 0; u < 6; ++u) {
        int idx = tid + u * 256;          // 0..1535
        int t = idx >> 9;
        int win = idx & 511;
        int r = win >> 2, c = win & 3;
        int gr = ((t < 2) ? row0 : col0) + r;
        const __half* gp = srcs[t] + (size_t)gr * K + k0 + c * 8;
        uint32_t d = dst0 + (uint32_t)t * TILE_B + phys_off(r, c);
        asm volatile("cp.async.cg.shared.global [%0], [%1], 16;"
                     :: "r"(d), "l"(gp));
    }
    asm volatile("cp.async.commit_group;" ::: "memory");
}

template <int EPI>
__global__ __launch_bounds__(256)
void gemm_mma_kernel(const __half* __restrict__ Ah,
                     const __half* __restrict__ Al,
                     const __half* __restrict__ Bh,
                     float* __restrict__ C,
                     __half* __restrict__ Dh,
                     __half* __restrict__ Dl,
                     const int* __restrict__ positions,
                     int M, int N, int K)
{
    extern __shared__ char smem[];
    uint32_t sbase = (uint32_t)__cvta_generic_to_shared(smem);

    int tid = threadIdx.x;
    int lane = tid & 31;
    int w = tid >> 5;
    int wm = w & 3;
    int wn = w >> 2;
    int row0 = blockIdx.y * 128;
    int col0 = blockIdx.x * 128;

    float acc[2][8][4];
    #pragma unroll
    for (int i = 0; i < 2; i++)
        #pragma unroll
        for (int j = 0; j < 8; j++)
            #pragma unroll
            for (int q = 0; q < 4; q++) acc[i][j][q] = 0.f;

    const int nIter = K / BKK;

    gemm_issue_stage(sbase, 0, 0, row0, col0, tid, K, Ah, Al, Bh);
    gemm_issue_stage(sbase, 1, 1, row0, col0, tid, K, Ah, Al, Bh);

    int lrow = (lane & 7) + ((lane >> 4) << 3);
    int lsel = (lane >> 3) & 1;

    for (int it = 0; it < nIter; ++it) {
        if (it + 2 < nIter)
            gemm_issue_stage(sbase, (it + 2) % NSTAGE, it + 2, row0, col0, tid, K,
                             Ah, Al, Bh);
        if (it + 2 < nIter)
            asm volatile("cp.async.wait_group 2;" ::: "memory");
        else if (it + 1 < nIter)
            asm volatile("cp.async.wait_group 1;" ::: "memory");
        else
            asm volatile("cp.async.wait_group 0;" ::: "memory");
        __syncthreads();

        uint32_t tb = sbase + (uint32_t)(it % NSTAGE) * STAGE_B;
        uint32_t aH = tb;
        uint32_t aL = tb + TILE_B;
        uint32_t bHb = tb + 2 * TILE_B;

        #pragma unroll
        for (int kk = 0; kk < 2; ++kk) {
            int c = 2 * kk + lsel;
            uint32_t ah2[2][4], al2[2][4], b[4][4];

            #pragma unroll
            for (int mf = 0; mf < 2; ++mf) {
                int r = wm * 32 + mf * 16 + lrow;
                LDSM4(al2[mf], aL + phys_off(r, c));
                LDSM4(ah2[mf], aH + phys_off(r, c));
            }
            #pragma unroll
            for (int p = 0; p < 4; ++p) {
                int r = wn * 64 + p * 16 + lrow;
                LDSM4(b[p], bHb + phys_off(r, c));
            }
            #pragma unroll
            for (int mf = 0; mf < 2; ++mf)
                #pragma unroll
                for (int p = 0; p < 4; ++p) {
                    MMA16816(acc[mf][2*p],   al2[mf], b[p][0], b[p][1]);
                    MMA16816(acc[mf][2*p+1], al2[mf], b[p][2], b[p][3]);
                }
            #pragma unroll
            for (int mf = 0; mf < 2; ++mf)
                #pragma unroll
                for (int p = 0; p < 4; ++p) {
                    MMA16816(acc[mf][2*p],   ah2[mf], b[p][0], b[p][1]);
                    MMA16816(acc[mf][2*p+1], ah2[mf], b[p][2], b[p][3]);
                }
        }
        __syncthreads();
    }

    if (EPI == 0) {
        #pragma unroll
        for (int mf = 0; mf < 2; ++mf) {
            int rbase = row0 + wm * 32 + mf * 16 + (lane >> 2);
            #pragma unroll
            for (int nf = 0; nf < 8; ++nf) {
                int cc = col0 + wn * 64 + nf * 8 + (lane & 3) * 2;
                float2 v0 = make_float2(acc[mf][nf][0], acc[mf][nf][1]);
                float2 v1 = make_float2(acc[mf][nf][2], acc[mf][nf][3]);
                *reinterpret_cast<float2*>(&C[(size_t)rbase * N + cc]) = v0;
                *reinterpret_cast<float2*>(&C[(size_t)(rbase + 8) * N + cc]) = v1;
            }
        }
    } else if (EPI == 1) {
        // fp16 store (hi only) — V path
        #pragma unroll
        for (int mf = 0; mf < 2; ++mf) {
            int rbase = row0 + wm * 32 + mf * 16 + (lane >> 2);
            #pragma unroll
            for (int nf = 0; nf < 8; ++nf) {
                int cc = col0 + wn * 64 + nf * 8 + (lane & 3) * 2;
                *reinterpret_cast<uint32_t*>(&Dh[(size_t)rbase * N + cc]) =
                    pack_h2(acc[mf][nf][0], acc[mf][nf][1]);
                *reinterpret_cast<uint32_t*>(&Dh[(size_t)(rbase + 8) * N + cc]) =
                    pack_h2(acc[mf][nf][2], acc[mf][nf][3]);
            }
        }
    } else {
        // rope + store. Dl != nullptr -> hi/lo pair (Q); else hi only (K).
        float* S = reinterpret_cast<float*>(smem);
        #pragma unroll
        for (int mf = 0; mf < 2; ++mf) {
            int rl = wm * 32 + mf * 16 + (lane >> 2);
            #pragma unroll
            for (int nf = 0; nf < 8; ++nf) {
                int cl2 = wn * 64 + nf * 8 + (lane & 3) * 2;
                S[rl * 132 + cl2]           = acc[mf][nf][0];
                S[rl * 132 + cl2 + 1]       = acc[mf][nf][1];
                S[(rl + 8) * 132 + cl2]     = acc[mf][nf][2];
                S[(rl + 8) * 132 + cl2 + 1] = acc[mf][nf][3];
            }
        }
        __syncthreads();
        #pragma unroll
        for (int u = 0; u < 32; ++u) {
            int idx = tid + u * 256;          // 0..8191
            int r = idx >> 6, j = idx & 63;
            float x1 = S[r * 132 + j];
            float x2 = S[r * 132 + j + 64];
            float pos = (float)positions[row0 + r];
            float inv = expf(-9.210340371976184f * (float)j * (1.0f / 64.0f));
            float sn, cs;
            sincosf(pos * inv, &sn, &cs);
            float y1 = x1 * cs - x2 * sn;
            float y2 = x1 * sn + x2 * cs;
            size_t base = (size_t)(row0 + r) * N + col0 + j;
            __half h1 = __float2half_rn(y1);
            __half h2 = __float2half_rn(y2);
            Dh[base]      = h1;
            Dh[base + 64] = h2;
            if (Dl) {
                Dl[base]      = __float2half_rn(y1 - __half2float(h1));
                Dl[base + 64] = __float2half_rn(y2 - __half2float(h2));
            }
        }
    }
}

// ---------------------------------------------------------------------------
// Tensor-core flash attention, fp16 2-pass compensated, double-buffered KV.
// CTA: 64 queries x (head, batch). 4 warps. K tile = 32, 2 stages.
// smem: qh,ql (16KB each) + 2 stages x {kh,vh} (8KB each) = 64KB.
// ---------------------------------------------------------------------------
#define AQ 64
#define AKT 32
#define QTILE 16384u
#define KVTILE 8192u
#define KVSTAGE (2u*KVTILE)
#define ATT_SMEM (2u*QTILE + 2u*KVSTAGE)   // 64 KB

__device__ __forceinline__ uint32_t off256(int r, int c) {
    return (uint32_t)(r * 256 + (((c ^ (r & 7)) & 15) << 4));
}

__device__ __forceinline__ void attn_load_kv(
    uint32_t dst, int tid, int b, int kvh, int k0,
    const __half* kh, const __half* vh)
{
    const __half* srcs[2] = {kh, vh};
    #pragma unroll
    for (int u = 0; u < 8; ++u) {
        int idx = tid + u * 128;          // 0..1023
        int t = idx >> 9, win = idx & 511;
        int r = win >> 4, c = win & 15;
        const __half* gp = srcs[t] +
            (((size_t)(b * SEQ + k0 + r) * KVH + kvh) * HD + c * 8);
        uint32_t d = dst + (uint32_t)t * KVTILE + off256(r, c);
        asm volatile("cp.async.cg.shared.global [%0], [%1], 16;" :: "r"(d), "l"(gp));
    }
}

__global__ __launch_bounds__(128)
void attn_mma_kernel(const __half* __restrict__ qh, const __half* __restrict__ ql,
                     const __half* __restrict__ kh, const __half* __restrict__ vh,
                     __half* __restrict__ ch, __half* __restrict__ cl)
{
    extern __shared__ char asmem[];
    uint32_t sb = (uint32_t)__cvta_generic_to_shared(asmem);
    uint32_t sqh = sb, sql = sb + QTILE;
    uint32_t kvs0 = sb + 2 * QTILE;

    int qt = blockIdx.x, h = blockIdx.y, b = blockIdx.z;
    int tid = threadIdx.x, lane = tid & 31, w = tid >> 5;
    int q0 = qt * AQ;
    int kvh = h >> 2;
    const float SC = 0.08838834764831845f;   // 1/sqrt(128)

    int lrow = (lane & 7) | ((lane >> 4) << 3);
    int lsel = (lane >> 3) & 1;
    int vrow = (lane & 7) | (((lane >> 3) & 1) << 3);
    int vcol = lane >> 4;

    const int nt = 2 * qt + 2;

    // group 0: Q (hi+lo) + KV tile 0
    {
        const __half* srcs[2] = {qh, ql};
        uint32_t dsts[2] = {sqh, sql};
        #pragma unroll
        for (int u = 0; u < 16; ++u) {
            int idx = tid + u * 128;
            int t = idx >> 10, win = idx & 1023;
            int r = win >> 4, c = win & 15;
            const __half* gp = srcs[t] +
                (((size_t)(b * SEQ + q0 + r) * QH + h) * HD + c * 8);
            uint32_t d = dsts[t] + off256(r, c);
            asm volatile("cp.async.cg.shared.global [%0], [%1], 16;" :: "r"(d), "l"(gp));
        }
        attn_load_kv(kvs0, tid, b, kvh, 0, kh, vh);
        asm volatile("cp.async.commit_group;" ::: "memory");
    }
    attn_load_kv(kvs0 + KVSTAGE, tid, b, kvh, AKT, kh, vh);
    asm volatile("cp.async.commit_group;" ::: "memory");

    float o[16][4];
    #pragma unroll
    for (int i = 0; i < 16; i++) {
        o[i][0] = 0.f; o[i][1] = 0.f; o[i][2] = 0.f; o[i][3] = 0.f;
    }
    float mrun0 = -1e30f, mrun1 = -1e30f, l0 = 0.f, l1 = 0.f;

    for (int kt = 0; kt < nt; ++kt) {
        int k0 = kt * AKT;
        if (kt + 1 < nt)
            asm volatile("cp.async.wait_group 1;" ::: "memory");
        else
            asm volatile("cp.async.wait_group 0;" ::: "memory");
        __syncthreads();

        uint32_t st = kvs0 + (uint32_t)(kt & 1) * KVSTAGE;
        uint32_t skh = st, svh = st + KVTILE;

        // ---- S = Q K^T (2 compensated passes), 32 keys ----
        float s[4][4];
        #pragma unroll
        for (int f = 0; f < 4; f++) {
            s[f][0] = 0.f; s[f][1] = 0.f; s[f][2] = 0.f; s[f][3] = 0.f;
        }
        #pragma unroll
        for (int kk = 0; kk < 8; ++kk) {
            int c = 2 * kk + lsel;
            uint32_t qa[4], qb[4], kbf[2][4];
            LDSM4(qa, sqh + off256(w * 16 + lrow, c));
            LDSM4(qb, sql + off256(w * 16 + lrow, c));
            #pragma unroll
            for (int p = 0; p < 2; ++p)
                LDSM4(kbf[p], skh + off256(p * 16 + lrow, c));
            #pragma unroll
            for (int p = 0; p < 2; ++p) {
                MMA16816(s[2*p],   qa, kbf[p][0], kbf[p][1]);
                MMA16816(s[2*p+1], qa, kbf[p][2], kbf[p][3]);
                MMA16816(s[2*p],   qb, kbf[p][0], kbf[p][1]);
                MMA16816(s[2*p+1], qb, kbf[p][2], kbf[p][3]);
            }
        }

        // ---- scale (fp32) then causal mask ----
        #pragma unroll
        for (int f = 0; f < 4; f++) {
            s[f][0] *= SC; s[f][1] *= SC; s[f][2] *= SC; s[f][3] *= SC;
        }
        if (k0 + AKT - 1 > q0) {
            #pragma unroll
            for (int f = 0; f < 4; ++f) {
                #pragma unroll
                for (int cc = 0; cc < 4; ++cc) {
                    int col = f * 8 + (lane & 3) * 2 + (cc & 1);
                    int row = w * 16 + (lane >> 2) + ((cc >> 1) << 3);
                    if (k0 + col > q0 + row) s[f][cc] = -1e30f;
                }
            }
        }

        // ---- online softmax ----
        float mx0 = -1e30f, mx1 = -1e30f;
        #pragma unroll
        for (int f = 0; f < 4; f++) {
            mx0 = fmaxf(mx0, fmaxf(s[f][0], s[f][1]));
            mx1 = fmaxf(mx1, fmaxf(s[f][2], s[f][3]));
        }
        mx0 = fmaxf(mx0, __shfl_xor_sync(0xffffffffu, mx0, 1));
        mx0 = fmaxf(mx0, __shfl_xor_sync(0xffffffffu, mx0, 2));
        mx1 = fmaxf(mx1, __shfl_xor_sync(0xffffffffu, mx1, 1));
        mx1 = fmaxf(mx1, __shfl_xor_sync(0xffffffffu, mx1, 2));

        float mn0 = fmaxf(mrun0, mx0), mn1 = fmaxf(mrun1, mx1);
        float al0 = __expf(mrun0 - mn0), al1 = __expf(mrun1 - mn1);
        mrun0 = mn0; mrun1 = mn1;

        float sum0 = 0.f, sum1 = 0.f;
        #pragma unroll
        for (int f = 0; f < 4; f++) {
            s[f][0] = __expf(s[f][0] - mn0); sum0 += s[f][0];
            s[f][1] = __expf(s[f][1] - mn0); sum0 += s[f][1];
            s[f][2] = __expf(s[f][2] - mn1); sum1 += s[f][2];
            s[f][3] = __expf(s[f][3] - mn1); sum1 += s[f][3];
        }
        sum0 += __shfl_xor_sync(0xffffffffu, sum0, 1);
        sum0 += __shfl_xor_sync(0xffffffffu, sum0, 2);
        sum1 += __shfl_xor_sync(0xffffffffu, sum1, 1);
        sum1 += __shfl_xor_sync(0xffffffffu, sum1, 2);
        l0 = l0 * al0 + sum0;
        l1 = l1 * al1 + sum1;

        #pragma unroll
        for (int nf = 0; nf < 16; ++nf) {
            o[nf][0] *= al0; o[nf][1] *= al0;
            o[nf][2] *= al1; o[nf][3] *= al1;
        }

        // ---- O += P V (2 compensated passes) ----
        #pragma unroll
        for (int j = 0; j < 2; ++j) {
            uint32_t ph[4], pl[4];
            split_pack(s[2*j][0],   s[2*j][1],   ph[0], pl[0]);
            split_pack(s[2*j][2],   s[2*j][3],   ph[1], pl[1]);
            split_pack(s[2*j+1][0], s[2*j+1][1], ph[2], pl[2]);
            split_pack(s[2*j+1][2], s[2*j+1][3], ph[3], pl[3]);
            #pragma unroll
            for (int nb = 0; nb < 8; ++nb) {
                uint32_t vb[4];
                LDSM4T(vb, svh + off256(16 * j + vrow, nb * 2 + vcol));
                MMA_PV(o[2*nb],   ph, vb[0], vb[1]);
                MMA_PV(o[2*nb+1], ph, vb[2], vb[3]);
                MMA_PV(o[2*nb],   pl, vb[0], vb[1]);
                MMA_PV(o[2*nb+1], pl, vb[2], vb[3]);
            }
        }

        __syncthreads();
        if (kt + 2 < nt) {
            attn_load_kv(kvs0 + (uint32_t)(kt & 1) * KVSTAGE, tid, b, kvh,
                         (kt + 2) * AKT, kh, vh);
            asm volatile("cp.async.commit_group;" ::: "memory");
        }
    }

    // ---- normalize + write fp16 hi/lo ctx ----
    float inv0 = 1.f / l0, inv1 = 1.f / l1;
    int r0g = q0 + w * 16 + (lane >> 2);
    #pragma unroll
    for (int nf = 0; nf < 16; ++nf) {
        int col = nf * 8 + (lane & 3) * 2;
        size_t base0 = ((size_t)(b * SEQ + r0g) * QH + h) * HD + col;
        size_t base1 = ((size_t)(b * SEQ + r0g + 8) * QH + h) * HD + col;
        uint32_t hh, ll;
        split_pack(o[nf][0] * inv0, o[nf][1] * inv0, hh, ll);
        *reinterpret_cast<uint32_t*>(&ch[base0]) = hh;
        *reinterpret_cast<uint32_t*>(&cl[base0]) = ll;
        split_pack(o[nf][2] * inv1, o[nf][3] * inv1, hh, ll);
        *reinterpret_cast<uint32_t*>(&ch[base1]) = hh;
        *reinterpret_cast<uint32_t*>(&cl[base1]) = ll;
    }
}

// ---------------------------------------------------------------------------
// Launch
// ---------------------------------------------------------------------------
extern "C" void kernel_launch(void* const* d_in, const int* in_sizes, int n_in,
                              void* d_out, int out_size)
{
    const float* x         = (const float*)d_in[0];
    const int*   positions = (const int*)  d_in[1];
    const float* wq        = (const float*)d_in[2];
    const float* wk        = (const float*)d_in[3];
    const float* wv        = (const float*)d_in[4];
    const float* wo        = (const float*)d_in[5];
    float* out = (float*)d_out;

    __half *xh, *xl, *wqh, *wkh, *wvh, *woh, *ch, *cl;
    __half *aqh, *aql, *akh, *avh;
    cudaGetSymbolAddress((void**)&xh,  g_xh);  cudaGetSymbolAddress((void**)&xl,  g_xl);
    cudaGetSymbolAddress((void**)&wqh, g_wqh);
    cudaGetSymbolAddress((void**)&wkh, g_wkh);
    cudaGetSymbolAddress((void**)&wvh, g_wvh);
    cudaGetSymbolAddress((void**)&woh, g_woh);
    cudaGetSymbolAddress((void**)&ch,  g_ch);  cudaGetSymbolAddress((void**)&cl,  g_cl);
    cudaGetSymbolAddress((void**)&aqh, g_aqh); cudaGetSymbolAddress((void**)&aql, g_aql);
    cudaGetSymbolAddress((void**)&akh, g_akh);
    cudaGetSymbolAddress((void**)&avh, g_avh);

    cudaFuncSetAttribute(gemm_mma_kernel<0>, cudaFuncAttributeMaxDynamicSharedMemorySize, GEMM_SMEM);
    cudaFuncSetAttribute(gemm_mma_kernel<1>, cudaFuncAttributeMaxDynamicSharedMemorySize, GEMM_SMEM);
    cudaFuncSetAttribute(gemm_mma_kernel<2>, cudaFuncAttributeMaxDynamicSharedMemorySize, GEMM_SMEM);
    cudaFuncSetAttribute(attn_mma_kernel, cudaFuncAttributeMaxDynamicSharedMemorySize, (int)ATT_SMEM);

    // Splits / converts
    {
        int n4;
        n4 = NT * DMODEL / 4;
        split_h_kernel<<<(n4 + 255) / 256, 256>>>((const float4*)x, (uint2*)xh, (uint2*)xl, n4);
        n4 = QH * HD * DMODEL / 4;
        tohalf_kernel<<<(n4 + 255) / 256, 256>>>((const float4*)wq, (uint2*)wqh, n4);
        n4 = KVH * HD * DMODEL / 4;
        tohalf_kernel<<<(n4 + 255) / 256, 256>>>((const float4*)wk, (uint2*)wkh, n4);
        tohalf_kernel<<<(n4 + 255) / 256, 256>>>((const float4*)wv, (uint2*)wvh, n4);
        n4 = DMODEL * QH * HD / 4;
        tohalf_kernel<<<(n4 + 255) / 256, 256>>>((const float4*)wo, (uint2*)woh, n4);
    }

    // Projections with fused epilogues
    {
        dim3 blk(256);
        dim3 gq_grid((QH * HD) / 128, NT / 128);
        gemm_mma_kernel<2><<<gq_grid, blk, GEMM_SMEM>>>(
            xh, xl, wqh, nullptr, aqh, aql, positions, NT, QH * HD, DMODEL);
        dim3 gkv_grid((KVH * HD) / 128, NT / 128);
        gemm_mma_kernel<2><<<gkv_grid, blk, GEMM_SMEM>>>(
            xh, xl, wkh, nullptr, akh, nullptr, positions, NT, KVH * HD, DMODEL);
        gemm_mma_kernel<1><<<gkv_grid, blk, GEMM_SMEM>>>(
            xh, xl, wvh, nullptr, avh, nullptr, nullptr, NT, KVH * HD, DMODEL);
    }

    // Attention (fp16 2-pass) -> ctx fp16 hi/lo
    {
        dim3 grid(SEQ / AQ, QH, BATCH);
        attn_mma_kernel<<<grid, 128, ATT_SMEM>>>(aqh, aql, akh, avh, ch, cl);
    }

    // Output projection (fp32 epilogue)
    {
        dim3 blk(256);
        dim3 grid(DMODEL / 128, NT / 128);
        gemm_mma_kernel<0><<<grid, blk, GEMM_SMEM>>>(
            ch, cl, woh, out, nullptr, nullptr, nullptr, NT, DMODEL, DMODEL);
    }
}

// round 12
// speedup vs baseline: 6.5497x; 1.0551x over previous
#include <cuda_runtime.h>
#include <cuda_fp16.h>
#include <math.h>
#include <stdint.h>

// Problem constants
#define BATCH 2
#define SEQ   2048
#define DMODEL 2048
#define QH 16
#define KVH 4
#define HD 128
#define NT (BATCH*SEQ)          // 4096 rows

// ---------------------------------------------------------------------------
// Scratch buffers (device globals: no allocation allowed)
// ---------------------------------------------------------------------------
__device__ __half g_xh[(size_t)NT * DMODEL];
__device__ __half g_xl[(size_t)NT * DMODEL];
__device__ __half g_wqh[(size_t)(QH*HD) * DMODEL];
__device__ __half g_wkh[(size_t)(KVH*HD) * DMODEL];
__device__ __half g_wvh[(size_t)(KVH*HD) * DMODEL];
__device__ __half g_woh[(size_t)DMODEL * (QH*HD)];
__device__ __half g_ch[(size_t)NT * (QH*HD)];
__device__ __half g_cl[(size_t)NT * (QH*HD)];

// attention inputs (post-RoPE)
__device__ __half g_aqh[(size_t)NT * QH * HD];
__device__ __half g_aql[(size_t)NT * QH * HD];
__device__ __half g_akh[(size_t)NT * KVH * HD];
__device__ __half g_avh[(size_t)NT * KVH * HD];

// ---------------------------------------------------------------------------
// helpers
// ---------------------------------------------------------------------------
__device__ __forceinline__ void split_pack(float e0, float e1,
                                           uint32_t& hi, uint32_t& lo)
{
    __half h0 = __float2half_rn(e0);
    __half h1 = __float2half_rn(e1);
    hi = ((uint32_t)__half_as_ushort(h1) << 16) | __half_as_ushort(h0);
    __half g0 = __float2half_rn(e0 - __half2float(h0));
    __half g1 = __float2half_rn(e1 - __half2float(h1));
    lo = ((uint32_t)__half_as_ushort(g1) << 16) | __half_as_ushort(g0);
}

__device__ __forceinline__ uint32_t pack_h2(float e0, float e1)
{
    __half h0 = __float2half_rn(e0);
    __half h1 = __float2half_rn(e1);
    return ((uint32_t)__half_as_ushort(h1) << 16) | __half_as_ushort(h0);
}

__global__ void split_h_kernel(const float4* __restrict__ in,
                               uint2* __restrict__ hi,
                               uint2* __restrict__ lo, int n4)
{
    int i = blockIdx.x * blockDim.x + threadIdx.x;
    if (i >= n4) return;
    float4 v = in[i];
    uint2 h, l;
    split_pack(v.x, v.y, h.x, l.x);
    split_pack(v.z, v.w, h.y, l.y);
    hi[i] = h;
    lo[i] = l;
}

__global__ void tohalf_kernel(const float4* __restrict__ in,
                              uint2* __restrict__ hi, int n4)
{
    int i = blockIdx.x * blockDim.x + threadIdx.x;
    if (i >= n4) return;
    float4 v = in[i];
    uint2 h;
    h.x = pack_h2(v.x, v.y);
    h.y = pack_h2(v.z, v.w);
    hi[i] = h;
}

#define LDSM4(r, addr) \
    asm volatile("ldmatrix.sync.aligned.m8n8.x4.shared.b16 {%0,%1,%2,%3}, [%4];" \
        : "=r"((r)[0]), "=r"((r)[1]), "=r"((r)[2]), "=r"((r)[3]) : "r"(addr))

#define LDSM4T(r, addr) \
    asm volatile("ldmatrix.sync.aligned.m8n8.x4.trans.shared.b16 {%0,%1,%2,%3}, [%4];" \
        : "=r"((r)[0]), "=r"((r)[1]), "=r"((r)[2]), "=r"((r)[3]) : "r"(addr))

// A from ldmatrix (reorder 0,2,1,3)
#define MMA16816(acc, A, B0, B1) \
    asm volatile("mma.sync.aligned.m16n8k16.row.col.f32.f16.f16.f32 " \
        "{%0,%1,%2,%3}, {%4,%5,%6,%7}, {%8,%9}, {%0,%1,%2,%3};" \
        : "+f"((acc)[0]), "+f"((acc)[1]), "+f"((acc)[2]), "+f"((acc)[3]) \
        : "r"((A)[0]), "r"((A)[2]), "r"((A)[1]), "r"((A)[3]), "r"(B0), "r"(B1))

// A already in mma register order
#define MMA_PV(acc, A, B0, B1) \
    asm volatile("mma.sync.aligned.m16n8k16.row.col.f32.f16.f16.f32 " \
        "{%0,%1,%2,%3}, {%4,%5,%6,%7}, {%8,%9}, {%0,%1,%2,%3};" \
        : "+f"((acc)[0]), "+f"((acc)[1]), "+f"((acc)[2]), "+f"((acc)[3]) \
        : "r"((A)[0]), "r"((A)[1]), "r"((A)[2]), "r"((A)[3]), "r"(B0), "r"(B1))

// ---------------------------------------------------------------------------
// mma.sync fp16 GEMM, 2-pass compensation (AhBh + AlBh).
// C[M,N] = A[M,K] * B[N,K]^T.  CTA tile 128x128, BK=32, 3-stage cp.async,
// single __syncthreads per mainloop iteration.
// EPI: 0 = fp32 C store, 1 = fp16 store (hi only), 2 = rope+split store.
// ---------------------------------------------------------------------------
#define BKK 32
#define TILE_B 8192u
#define STAGE_B (3u*TILE_B)     // Ah, Al, Bh
#define NSTAGE 3
#define GEMM_SMEM (NSTAGE*STAGE_B)   // 72 KB

__device__ __forceinline__ uint32_t phys_off(int r, int c) {
    return (uint32_t)(r * 64 + (((c ^ (r >> 1)) & 3) << 4));
}

__device__ __forceinline__ void gemm_issue_stage(
    uint32_t sbase, int st, int it, int row0, int col0, int tid, int K,
    const __half* Ah, const __half* Al, const __half* Bh)
{
    int k0 = it * BKK;
    uint32_t dst0 = sbase + (uint32_t)st * STAGE_B;
    const __half* srcs[3] = {Ah, Al, Bh};
    #pragma unroll
    for (int u = 0; u < 6; ++u) {
        int idx = tid + u * 256;          // 0..1535
        int t = idx >> 9;
        int win = idx & 511;
        int r = win >> 2, c = win & 3;
        int gr = ((t < 2) ? row0 : col0) + r;
        const __half* gp = srcs[t] + (size_t)gr * K + k0 + c * 8;
        uint32_t d = dst0 + (uint32_t)t * TILE_B + phys_off(r, c);
        asm volatile("cp.async.cg.shared.global [%0], [%1], 16;"
                     :: "r"(d), "l"(gp));
    }
    asm volatile("cp.async.commit_group;" ::: "memory");
}

template <int EPI>
__global__ __launch_bounds__(256)
void gemm_mma_kernel(const __half* __restrict__ Ah,
                     const __half* __restrict__ Al,
                     const __half* __restrict__ Bh,
                     float* __restrict__ C,
                     __half* __restrict__ Dh,
                     __half* __restrict__ Dl,
                     const int* __restrict__ positions,
                     int M, int N, int K)
{
    extern __shared__ char smem[];
    uint32_t sbase = (uint32_t)__cvta_generic_to_shared(smem);

    int tid = threadIdx.x;
    int lane = tid & 31;
    int w = tid >> 5;
    int wm = w & 3;
    int wn = w >> 2;
    int row0 = blockIdx.y * 128;
    int col0 = blockIdx.x * 128;

    float acc[2][8][4];
    #pragma unroll
    for (int i = 0; i < 2; i++)
        #pragma unroll
        for (int j = 0; j < 8; j++)
            #pragma unroll
            for (int q = 0; q < 4; q++) acc[i][j][q] = 0.f;

    const int nIter = K / BKK;

    gemm_issue_stage(sbase, 0, 0, row0, col0, tid, K, Ah, Al, Bh);
    gemm_issue_stage(sbase, 1, 1, row0, col0, tid, K, Ah, Al, Bh);

    int lrow = (lane & 7) + ((lane >> 4) << 3);
    int lsel = (lane >> 3) & 1;

    for (int it = 0; it < nIter; ++it) {
        if (it + 1 < nIter)
            asm volatile("cp.async.wait_group 1;" ::: "memory");
        else
            asm volatile("cp.async.wait_group 0;" ::: "memory");
        __syncthreads();
        // safe: all warps finished reading stage (it-1) whose buffer (it+2)%3 reuses
        if (it + 2 < nIter)
            gemm_issue_stage(sbase, (it + 2) % NSTAGE, it + 2, row0, col0, tid, K,
                             Ah, Al, Bh);

        uint32_t tb = sbase + (uint32_t)(it % NSTAGE) * STAGE_B;
        uint32_t aH = tb;
        uint32_t aL = tb + TILE_B;
        uint32_t bHb = tb + 2 * TILE_B;

        #pragma unroll
        for (int kk = 0; kk < 2; ++kk) {
            int c = 2 * kk + lsel;
            uint32_t ah2[2][4], al2[2][4], b[4][4];

            #pragma unroll
            for (int mf = 0; mf < 2; ++mf) {
                int r = wm * 32 + mf * 16 + lrow;
                LDSM4(al2[mf], aL + phys_off(r, c));
                LDSM4(ah2[mf], aH + phys_off(r, c));
            }
            #pragma unroll
            for (int p = 0; p < 4; ++p) {
                int r = wn * 64 + p * 16 + lrow;
                LDSM4(b[p], bHb + phys_off(r, c));
            }
            #pragma unroll
            for (int mf = 0; mf < 2; ++mf)
                #pragma unroll
                for (int p = 0; p < 4; ++p) {
                    MMA16816(acc[mf][2*p],   al2[mf], b[p][0], b[p][1]);
                    MMA16816(acc[mf][2*p+1], al2[mf], b[p][2], b[p][3]);
                }
            #pragma unroll
            for (int mf = 0; mf < 2; ++mf)
                #pragma unroll
                for (int p = 0; p < 4; ++p) {
                    MMA16816(acc[mf][2*p],   ah2[mf], b[p][0], b[p][1]);
                    MMA16816(acc[mf][2*p+1], ah2[mf], b[p][2], b[p][3]);
                }
        }
    }

    if (EPI == 0) {
        #pragma unroll
        for (int mf = 0; mf < 2; ++mf) {
            int rbase = row0 + wm * 32 + mf * 16 + (lane >> 2);
            #pragma unroll
            for (int nf = 0; nf < 8; ++nf) {
                int cc = col0 + wn * 64 + nf * 8 + (lane & 3) * 2;
                float2 v0 = make_float2(acc[mf][nf][0], acc[mf][nf][1]);
                float2 v1 = make_float2(acc[mf][nf][2], acc[mf][nf][3]);
                *reinterpret_cast<float2*>(&C[(size_t)rbase * N + cc]) = v0;
                *reinterpret_cast<float2*>(&C[(size_t)(rbase + 8) * N + cc]) = v1;
            }
        }
    } else if (EPI == 1) {
        #pragma unroll
        for (int mf = 0; mf < 2; ++mf) {
            int rbase = row0 + wm * 32 + mf * 16 + (lane >> 2);
            #pragma unroll
            for (int nf = 0; nf < 8; ++nf) {
                int cc = col0 + wn * 64 + nf * 8 + (lane & 3) * 2;
                *reinterpret_cast<uint32_t*>(&Dh[(size_t)rbase * N + cc]) =
                    pack_h2(acc[mf][nf][0], acc[mf][nf][1]);
                *reinterpret_cast<uint32_t*>(&Dh[(size_t)(rbase + 8) * N + cc]) =
                    pack_h2(acc[mf][nf][2], acc[mf][nf][3]);
            }
        }
    } else {
        // rope + store. Dl != nullptr -> hi/lo pair (Q); else hi only (K).
        __syncthreads();   // all warps done with smem frags before reuse
        float* S = reinterpret_cast<float*>(smem);
        #pragma unroll
        for (int mf = 0; mf < 2; ++mf) {
            int rl = wm * 32 + mf * 16 + (lane >> 2);
            #pragma unroll
            for (int nf = 0; nf < 8; ++nf) {
                int cl2 = wn * 64 + nf * 8 + (lane & 3) * 2;
                S[rl * 132 + cl2]           = acc[mf][nf][0];
                S[rl * 132 + cl2 + 1]       = acc[mf][nf][1];
                S[(rl + 8) * 132 + cl2]     = acc[mf][nf][2];
                S[(rl + 8) * 132 + cl2 + 1] = acc[mf][nf][3];
            }
        }
        __syncthreads();
        #pragma unroll
        for (int u = 0; u < 32; ++u) {
            int idx = tid + u * 256;          // 0..8191
            int r = idx >> 6, j = idx & 63;
            float x1 = S[r * 132 + j];
            float x2 = S[r * 132 + j + 64];
            float pos = (float)positions[row0 + r];
            float inv = expf(-9.210340371976184f * (float)j * (1.0f / 64.0f));
            float sn, cs;
            sincosf(pos * inv, &sn, &cs);
            float y1 = x1 * cs - x2 * sn;
            float y2 = x1 * sn + x2 * cs;
            size_t base = (size_t)(row0 + r) * N + col0 + j;
            __half h1 = __float2half_rn(y1);
            __half h2 = __float2half_rn(y2);
            Dh[base]      = h1;
            Dh[base + 64] = h2;
            if (Dl) {
                Dl[base]      = __float2half_rn(y1 - __half2float(h1));
                Dl[base + 64] = __float2half_rn(y2 - __half2float(h2));
            }
        }
    }
}

// ---------------------------------------------------------------------------
// Tensor-core flash attention, fp16 2-pass compensated, double-buffered KV.
// CTA: 64 queries x (head, batch). 4 warps. K tile = 64, 2 stages.
// smem: qh,ql (16KB each) + 2 stages x {kh,vh} (16KB each) = 96KB.
// LPT: qt reversed so longest CTAs start first.
// ---------------------------------------------------------------------------
#define AQ 64
#define AKT 64
#define QTILE 16384u
#define KVTILE 16384u
#define KVSTAGE (2u*KVTILE)
#define ATT_SMEM (2u*QTILE + 2u*KVSTAGE)   // 96 KB

__device__ __forceinline__ uint32_t off256(int r, int c) {
    return (uint32_t)(r * 256 + (((c ^ (r & 7)) & 15) << 4));
}

__device__ __forceinline__ void attn_load_kv(
    uint32_t dst, int tid, int b, int kvh, int k0,
    const __half* kh, const __half* vh)
{
    const __half* srcs[2] = {kh, vh};
    #pragma unroll
    for (int u = 0; u < 16; ++u) {
        int idx = tid + u * 128;          // 0..2047
        int t = idx >> 10, win = idx & 1023;
        int r = win >> 4, c = win & 15;
        const __half* gp = srcs[t] +
            (((size_t)(b * SEQ + k0 + r) * KVH + kvh) * HD + c * 8);
        uint32_t d = dst + (uint32_t)t * KVTILE + off256(r, c);
        asm volatile("cp.async.cg.shared.global [%0], [%1], 16;" :: "r"(d), "l"(gp));
    }
}

__global__ __launch_bounds__(128)
void attn_mma_kernel(const __half* __restrict__ qh, const __half* __restrict__ ql,
                     const __half* __restrict__ kh, const __half* __restrict__ vh,
                     __half* __restrict__ ch, __half* __restrict__ cl)
{
    extern __shared__ char asmem[];
    uint32_t sb = (uint32_t)__cvta_generic_to_shared(asmem);
    uint32_t sqh = sb, sql = sb + QTILE;
    uint32_t kvs0 = sb + 2 * QTILE;

    int qt = gridDim.x - 1 - blockIdx.x;   // LPT: longest CTAs first
    int h = blockIdx.y, b = blockIdx.z;
    int tid = threadIdx.x, lane = tid & 31, w = tid >> 5;
    int q0 = qt * AQ;
    int kvh = h >> 2;
    const float SC = 0.08838834764831845f;   // 1/sqrt(128)

    int lrow = (lane & 7) | ((lane >> 4) << 3);
    int lsel = (lane >> 3) & 1;
    int vrow = (lane & 7) | (((lane >> 3) & 1) << 3);
    int vcol = lane >> 4;

    const int nt = qt + 1;   // number of 64-key tiles

    // group 0: Q (hi+lo) + KV tile 0
    {
        const __half* srcs[2] = {qh, ql};
        uint32_t dsts[2] = {sqh, sql};
        #pragma unroll
        for (int u = 0; u < 16; ++u) {
            int idx = tid + u * 128;
            int t = idx >> 10, win = idx & 1023;
            int r = win >> 4, c = win & 15;
            const __half* gp = srcs[t] +
                (((size_t)(b * SEQ + q0 + r) * QH + h) * HD + c * 8);
            uint32_t d = dsts[t] + off256(r, c);
            asm volatile("cp.async.cg.shared.global [%0], [%1], 16;" :: "r"(d), "l"(gp));
        }
        attn_load_kv(kvs0, tid, b, kvh, 0, kh, vh);
        asm volatile("cp.async.commit_group;" ::: "memory");
    }
    // group 1: KV tile 1 (prefetch; reads valid memory even when nt == 1)
    {
        int k1 = (1 < nt) ? AKT : 0;
        attn_load_kv(kvs0 + KVSTAGE, tid, b, kvh, k1, kh, vh);
        asm volatile("cp.async.commit_group;" ::: "memory");
    }

    float o[16][4];
    #pragma unroll
    for (int i = 0; i < 16; i++) {
        o[i][0] = 0.f; o[i][1] = 0.f; o[i][2] = 0.f; o[i][3] = 0.f;
    }
    float mrun0 = -1e30f, mrun1 = -1e30f, l0 = 0.f, l1 = 0.f;

    for (int kt = 0; kt < nt; ++kt) {
        int k0 = kt * AKT;
        if (kt + 1 < nt)
            asm volatile("cp.async.wait_group 1;" ::: "memory");
        else
            asm volatile("cp.async.wait_group 0;" ::: "memory");
        __syncthreads();

        uint32_t st = kvs0 + (uint32_t)(kt & 1) * KVSTAGE;
        uint32_t skh = st, svh = st + KVTILE;

        // ---- S = Q K^T (2 compensated passes), 64 keys ----
        float s[8][4];
        #pragma unroll
        for (int f = 0; f < 8; f++) {
            s[f][0] = 0.f; s[f][1] = 0.f; s[f][2] = 0.f; s[f][3] = 0.f;
        }
        #pragma unroll
        for (int kk = 0; kk < 8; ++kk) {
            int c = 2 * kk + lsel;
            uint32_t qa[4], qb[4], kbf[4][4];
            LDSM4(qa, sqh + off256(w * 16 + lrow, c));
            LDSM4(qb, sql + off256(w * 16 + lrow, c));
            #pragma unroll
            for (int p = 0; p < 4; ++p)
                LDSM4(kbf[p], skh + off256(p * 16 + lrow, c));
            #pragma unroll
            for (int p = 0; p < 4; ++p) {
                MMA16816(s[2*p],   qa, kbf[p][0], kbf[p][1]);
                MMA16816(s[2*p+1], qa, kbf[p][2], kbf[p][3]);
                MMA16816(s[2*p],   qb, kbf[p][0], kbf[p][1]);
                MMA16816(s[2*p+1], qb, kbf[p][2], kbf[p][3]);
            }
        }

        // ---- scale (fp32) then causal mask (diagonal tile only) ----
        #pragma unroll
        for (int f = 0; f < 8; f++) {
            s[f][0] *= SC; s[f][1] *= SC; s[f][2] *= SC; s[f][3] *= SC;
        }
        if (k0 + AKT - 1 > q0) {
            #pragma unroll
            for (int f = 0; f < 8; ++f) {
                #pragma unroll
                for (int cc = 0; cc < 4; ++cc) {
                    int col = f * 8 + (lane & 3) * 2 + (cc & 1);
                    int row = w * 16 + (lane >> 2) + ((cc >> 1) << 3);
                    if (k0 + col > q0 + row) s[f][cc] = -1e30f;
                }
            }
        }

        // ---- online softmax ----
        float mx0 = -1e30f, mx1 = -1e30f;
        #pragma unroll
        for (int f = 0; f < 8; f++) {
            mx0 = fmaxf(mx0, fmaxf(s[f][0], s[f][1]));
            mx1 = fmaxf(mx1, fmaxf(s[f][2], s[f][3]));
        }
        mx0 = fmaxf(mx0, __shfl_xor_sync(0xffffffffu, mx0, 1));
        mx0 = fmaxf(mx0, __shfl_xor_sync(0xffffffffu, mx0, 2));
        mx1 = fmaxf(mx1, __shfl_xor_sync(0xffffffffu, mx1, 1));
        mx1 = fmaxf(mx1, __shfl_xor_sync(0xffffffffu, mx1, 2));

        float mn0 = fmaxf(mrun0, mx0), mn1 = fmaxf(mrun1, mx1);
        float al0 = __expf(mrun0 - mn0), al1 = __expf(mrun1 - mn1);
        mrun0 = mn0; mrun1 = mn1;

        float sum0 = 0.f, sum1 = 0.f;
        #pragma unroll
        for (int f = 0; f < 8; f++) {
            s[f][0] = __expf(s[f][0] - mn0); sum0 += s[f][0];
            s[f][1] = __expf(s[f][1] - mn0); sum0 += s[f][1];
            s[f][2] = __expf(s[f][2] - mn1); sum1 += s[f][2];
            s[f][3] = __expf(s[f][3] - mn1); sum1 += s[f][3];
        }
        sum0 += __shfl_xor_sync(0xffffffffu, sum0, 1);
        sum0 += __shfl_xor_sync(0xffffffffu, sum0, 2);
        sum1 += __shfl_xor_sync(0xffffffffu, sum1, 1);
        sum1 += __shfl_xor_sync(0xffffffffu, sum1, 2);
        l0 = l0 * al0 + sum0;
        l1 = l1 * al1 + sum1;

        #pragma unroll
        for (int nf = 0; nf < 16; ++nf) {
            o[nf][0] *= al0; o[nf][1] *= al0;
            o[nf][2] *= al1; o[nf][3] *= al1;
        }

        // ---- O += P V (2 compensated passes) ----
        #pragma unroll
        for (int j = 0; j < 4; ++j) {
            uint32_t ph[4], pl[4];
            split_pack(s[2*j][0],   s[2*j][1],   ph[0], pl[0]);
            split_pack(s[2*j][2],   s[2*j][3],   ph[1], pl[1]);
            split_pack(s[2*j+1][0], s[2*j+1][1], ph[2], pl[2]);
            split_pack(s[2*j+1][2], s[2*j+1][3], ph[3], pl[3]);
            #pragma unroll
            for (int nb = 0; nb < 8; ++nb) {
                uint32_t vb[4];
                LDSM4T(vb, svh + off256(16 * j + vrow, nb * 2 + vcol));
                MMA_PV(o[2*nb],   ph, vb[0], vb[1]);
                MMA_PV(o[2*nb+1], ph, vb[2], vb[3]);
                MMA_PV(o[2*nb],   pl, vb[0], vb[1]);
                MMA_PV(o[2*nb+1], pl, vb[2], vb[3]);
            }
        }

        __syncthreads();
        if (kt + 2 < nt) {
            attn_load_kv(kvs0 + (uint32_t)(kt & 1) * KVSTAGE, tid, b, kvh,
                         (kt + 2) * AKT, kh, vh);
            asm volatile("cp.async.commit_group;" ::: "memory");
        }
    }

    // ---- normalize + write fp16 hi/lo ctx ----
    float inv0 = 1.f / l0, inv1 = 1.f / l1;
    int r0g = q0 + w * 16 + (lane >> 2);
    #pragma unroll
    for (int nf = 0; nf < 16; ++nf) {
        int col = nf * 8 + (lane & 3) * 2;
        size_t base0 = ((size_t)(b * SEQ + r0g) * QH + h) * HD + col;
        size_t base1 = ((size_t)(b * SEQ + r0g + 8) * QH + h) * HD + col;
        uint32_t hh, ll;
        split_pack(o[nf][0] * inv0, o[nf][1] * inv0, hh, ll);
        *reinterpret_cast<uint32_t*>(&ch[base0]) = hh;
        *reinterpret_cast<uint32_t*>(&cl[base0]) = ll;
        split_pack(o[nf][2] * inv1, o[nf][3] * inv1, hh, ll);
        *reinterpret_cast<uint32_t*>(&ch[base1]) = hh;
        *reinterpret_cast<uint32_t*>(&cl[base1]) = ll;
    }
}

// ---------------------------------------------------------------------------
// Launch
// ---------------------------------------------------------------------------
extern "C" void kernel_launch(void* const* d_in, const int* in_sizes, int n_in,
                              void* d_out, int out_size)
{
    const float* x         = (const float*)d_in[0];
    const int*   positions = (const int*)  d_in[1];
    const float* wq        = (const float*)d_in[2];
    const float* wk        = (const float*)d_in[3];
    const float* wv        = (const float*)d_in[4];
    const float* wo        = (const float*)d_in[5];
    float* out = (float*)d_out;

    __half *xh, *xl, *wqh, *wkh, *wvh, *woh, *ch, *cl;
    __half *aqh, *aql, *akh, *avh;
    cudaGetSymbolAddress((void**)&xh,  g_xh);  cudaGetSymbolAddress((void**)&xl,  g_xl);
    cudaGetSymbolAddress((void**)&wqh, g_wqh);
    cudaGetSymbolAddress((void**)&wkh, g_wkh);
    cudaGetSymbolAddress((void**)&wvh, g_wvh);
    cudaGetSymbolAddress((void**)&woh, g_woh);
    cudaGetSymbolAddress((void**)&ch,  g_ch);  cudaGetSymbolAddress((void**)&cl,  g_cl);
    cudaGetSymbolAddress((void**)&aqh, g_aqh); cudaGetSymbolAddress((void**)&aql, g_aql);
    cudaGetSymbolAddress((void**)&akh, g_akh);
    cudaGetSymbolAddress((void**)&avh, g_avh);

    cudaFuncSetAttribute(gemm_mma_kernel<0>, cudaFuncAttributeMaxDynamicSharedMemorySize, GEMM_SMEM);
    cudaFuncSetAttribute(gemm_mma_kernel<1>, cudaFuncAttributeMaxDynamicSharedMemorySize, GEMM_SMEM);
    cudaFuncSetAttribute(gemm_mma_kernel<2>, cudaFuncAttributeMaxDynamicSharedMemorySize, GEMM_SMEM);
    cudaFuncSetAttribute(attn_mma_kernel, cudaFuncAttributeMaxDynamicSharedMemorySize, (int)ATT_SMEM);

    // Splits / converts
    {
        int n4;
        n4 = NT * DMODEL / 4;
        split_h_kernel<<<(n4 + 255) / 256, 256>>>((const float4*)x, (uint2*)xh, (uint2*)xl, n4);
        n4 = QH * HD * DMODEL / 4;
        tohalf_kernel<<<(n4 + 255) / 256, 256>>>((const float4*)wq, (uint2*)wqh, n4);
        n4 = KVH * HD * DMODEL / 4;
        tohalf_kernel<<<(n4 + 255) / 256, 256>>>((const float4*)wk, (uint2*)wkh, n4);
        tohalf_kernel<<<(n4 + 255) / 256, 256>>>((const float4*)wv, (uint2*)wvh, n4);
        n4 = DMODEL * QH * HD / 4;
        tohalf_kernel<<<(n4 + 255) / 256, 256>>>((const float4*)wo, (uint2*)woh, n4);
    }

    // Projections with fused epilogues
    {
        dim3 blk(256);
        dim3 gq_grid((QH * HD) / 128, NT / 128);
        gemm_mma_kernel<2><<<gq_grid, blk, GEMM_SMEM>>>(
            xh, xl, wqh, nullptr, aqh, aql, positions, NT, QH * HD, DMODEL);
        dim3 gkv_grid((KVH * HD) / 128, NT / 128);
        gemm_mma_kernel<2><<<gkv_grid, blk, GEMM_SMEM>>>(
            xh, xl, wkh, nullptr, akh, nullptr, positions, NT, KVH * HD, DMODEL);
        gemm_mma_kernel<1><<<gkv_grid, blk, GEMM_SMEM>>>(
            xh, xl, wvh, nullptr, avh, nullptr, nullptr, NT, KVH * HD, DMODEL);
    }

    // Attention (fp16 2-pass, 64-key tiles, LPT) -> ctx fp16 hi/lo
    {
        dim3 grid(SEQ / AQ, QH, BATCH);
        attn_mma_kernel<<<grid, 128, ATT_SMEM>>>(aqh, aql, akh, avh, ch, cl);
    }

    // Output projection (fp32 epilogue)
    {
        dim3 blk(256);
        dim3 grid(DMODEL / 128, NT / 128);
        gemm_mma_kernel<0><<<grid, blk, GEMM_SMEM>>>(
            ch, cl, woh, out, nullptr, nullptr, nullptr, NT, DMODEL, DMODEL);
    }
}

// round 13
// speedup vs baseline: 7.6689x; 1.1709x over previous
#include <cuda_runtime.h>
#include <cuda_fp16.h>
#include <math.h>
#include <stdint.h>

// Problem constants
#define BATCH 2
#define SEQ   2048
#define DMODEL 2048
#define QH 16
#define KVH 4
#define HD 128
#define NT (BATCH*SEQ)          // 4096 rows

// ---------------------------------------------------------------------------
// Scratch buffers (device globals: no allocation allowed)
// ---------------------------------------------------------------------------
__device__ __half g_xh[(size_t)NT * DMODEL];
__device__ __half g_xl[(size_t)NT * DMODEL];
__device__ __half g_wqh[(size_t)(QH*HD) * DMODEL];
__device__ __half g_wkh[(size_t)(KVH*HD) * DMODEL];
__device__ __half g_wvh[(size_t)(KVH*HD) * DMODEL];
__device__ __half g_woh[(size_t)DMODEL * (QH*HD)];
__device__ __half g_ch[(size_t)NT * (QH*HD)];

// attention inputs (post-RoPE)
__device__ __half g_aqh[(size_t)NT * QH * HD];
__device__ __half g_aql[(size_t)NT * QH * HD];
__device__ __half g_akh[(size_t)NT * KVH * HD];
__device__ __half g_avh[(size_t)NT * KVH * HD];

// ---------------------------------------------------------------------------
// helpers
// ---------------------------------------------------------------------------
__device__ __forceinline__ void split_pack(float e0, float e1,
                                           uint32_t& hi, uint32_t& lo)
{
    __half h0 = __float2half_rn(e0);
    __half h1 = __float2half_rn(e1);
    hi = ((uint32_t)__half_as_ushort(h1) << 16) | __half_as_ushort(h0);
    __half g0 = __float2half_rn(e0 - __half2float(h0));
    __half g1 = __float2half_rn(e1 - __half2float(h1));
    lo = ((uint32_t)__half_as_ushort(g1) << 16) | __half_as_ushort(g0);
}

__device__ __forceinline__ uint32_t pack_h2(float e0, float e1)
{
    __half h0 = __float2half_rn(e0);
    __half h1 = __float2half_rn(e1);
    return ((uint32_t)__half_as_ushort(h1) << 16) | __half_as_ushort(h0);
}

__global__ void split_h_kernel(const float4* __restrict__ in,
                               uint2* __restrict__ hi,
                               uint2* __restrict__ lo, int n4)
{
    int i = blockIdx.x * blockDim.x + threadIdx.x;
    if (i >= n4) return;
    float4 v = in[i];
    uint2 h, l;
    split_pack(v.x, v.y, h.x, l.x);
    split_pack(v.z, v.w, h.y, l.y);
    hi[i] = h;
    lo[i] = l;
}

__global__ void tohalf_kernel(const float4* __restrict__ in,
                              uint2* __restrict__ hi, int n4)
{
    int i = blockIdx.x * blockDim.x + threadIdx.x;
    if (i >= n4) return;
    float4 v = in[i];
    uint2 h;
    h.x = pack_h2(v.x, v.y);
    h.y = pack_h2(v.z, v.w);
    hi[i] = h;
}

#define LDSM4(r, addr) \
    asm volatile("ldmatrix.sync.aligned.m8n8.x4.shared.b16 {%0,%1,%2,%3}, [%4];" \
        : "=r"((r)[0]), "=r"((r)[1]), "=r"((r)[2]), "=r"((r)[3]) : "r"(addr))

#define LDSM4T(r, addr) \
    asm volatile("ldmatrix.sync.aligned.m8n8.x4.trans.shared.b16 {%0,%1,%2,%3}, [%4];" \
        : "=r"((r)[0]), "=r"((r)[1]), "=r"((r)[2]), "=r"((r)[3]) : "r"(addr))

// A from ldmatrix (reorder 0,2,1,3)
#define MMA16816(acc, A, B0, B1) \
    asm volatile("mma.sync.aligned.m16n8k16.row.col.f32.f16.f16.f32 " \
        "{%0,%1,%2,%3}, {%4,%5,%6,%7}, {%8,%9}, {%0,%1,%2,%3};" \
        : "+f"((acc)[0]), "+f"((acc)[1]), "+f"((acc)[2]), "+f"((acc)[3]) \
        : "r"((A)[0]), "r"((A)[2]), "r"((A)[1]), "r"((A)[3]), "r"(B0), "r"(B1))

// A already in mma register order
#define MMA_PV(acc, A, B0, B1) \
    asm volatile("mma.sync.aligned.m16n8k16.row.col.f32.f16.f16.f32 " \
        "{%0,%1,%2,%3}, {%4,%5,%6,%7}, {%8,%9}, {%0,%1,%2,%3};" \
        : "+f"((acc)[0]), "+f"((acc)[1]), "+f"((acc)[2]), "+f"((acc)[3]) \
        : "r"((A)[0]), "r"((A)[1]), "r"((A)[2]), "r"((A)[3]), "r"(B0), "r"(B1))

// ---------------------------------------------------------------------------
// mma.sync fp16 GEMM.  LO=true: 2-pass compensation (AhBh + AlBh);
// LO=false: plain 1-pass fp16 (AhBh).
// C[M,N] = A[M,K] * B[N,K]^T.  CTA tile 128x128, BK=32, 3-stage cp.async,
// single __syncthreads per mainloop iteration.
// EPI: 0 = fp32 C store, 1 = fp16 store (hi only), 2 = rope+split store.
// ---------------------------------------------------------------------------
#define BKK 32
#define TILE_B 8192u
#define NSTAGE 3

__device__ __forceinline__ uint32_t phys_off(int r, int c) {
    return (uint32_t)(r * 64 + (((c ^ (r >> 1)) & 3) << 4));
}

template <bool LO>
__device__ __forceinline__ void gemm_issue_stage(
    uint32_t sbase, int st, int it, int row0, int col0, int tid, int K,
    const __half* Ah, const __half* Al, const __half* Bh)
{
    const uint32_t STAGE_B = (LO ? 3u : 2u) * TILE_B;
    int k0 = it * BKK;
    uint32_t dst0 = sbase + (uint32_t)st * STAGE_B;
    const int NU = LO ? 6 : 4;
    #pragma unroll
    for (int u = 0; u < NU; ++u) {
        int idx = tid + u * 256;          // 0..(NU*256-1)
        int t = idx >> 9;                 // LO: 0=Ah,1=Al,2=Bh ; !LO: 0=Ah,1=Bh
        int win = idx & 511;
        int r = win >> 2, c = win & 3;
        const __half* src;
        if (LO) src = (t == 0) ? Ah : (t == 1) ? Al : Bh;
        else    src = (t == 0) ? Ah : Bh;
        bool isB = LO ? (t == 2) : (t == 1);
        int gr = (isB ? col0 : row0) + r;
        const __half* gp = src + (size_t)gr * K + k0 + c * 8;
        uint32_t d = dst0 + (uint32_t)t * TILE_B + phys_off(r, c);
        asm volatile("cp.async.cg.shared.global [%0], [%1], 16;"
                     :: "r"(d), "l"(gp));
    }
    asm volatile("cp.async.commit_group;" ::: "memory");
}

template <int EPI, bool LO>
__global__ __launch_bounds__(256)
void gemm_mma_kernel(const __half* __restrict__ Ah,
                     const __half* __restrict__ Al,
                     const __half* __restrict__ Bh,
                     float* __restrict__ C,
                     __half* __restrict__ Dh,
                     __half* __restrict__ Dl,
                     const int* __restrict__ positions,
                     int M, int N, int K)
{
    extern __shared__ char smem[];
    uint32_t sbase = (uint32_t)__cvta_generic_to_shared(smem);
    const uint32_t STAGE_B = (LO ? 3u : 2u) * TILE_B;

    int tid = threadIdx.x;
    int lane = tid & 31;
    int w = tid >> 5;
    int wm = w & 3;
    int wn = w >> 2;
    int row0 = blockIdx.y * 128;
    int col0 = blockIdx.x * 128;

    float acc[2][8][4];
    #pragma unroll
    for (int i = 0; i < 2; i++)
        #pragma unroll
        for (int j = 0; j < 8; j++)
            #pragma unroll
            for (int q = 0; q < 4; q++) acc[i][j][q] = 0.f;

    const int nIter = K / BKK;

    gemm_issue_stage<LO>(sbase, 0, 0, row0, col0, tid, K, Ah, Al, Bh);
    gemm_issue_stage<LO>(sbase, 1, 1, row0, col0, tid, K, Ah, Al, Bh);

    int lrow = (lane & 7) + ((lane >> 4) << 3);
    int lsel = (lane >> 3) & 1;

    for (int it = 0; it < nIter; ++it) {
        if (it + 1 < nIter)
            asm volatile("cp.async.wait_group 1;" ::: "memory");
        else
            asm volatile("cp.async.wait_group 0;" ::: "memory");
        __syncthreads();
        // safe: all warps finished reading stage (it-1) whose buffer (it+2)%3 reuses
        if (it + 2 < nIter)
            gemm_issue_stage<LO>(sbase, (it + 2) % NSTAGE, it + 2, row0, col0, tid, K,
                                 Ah, Al, Bh);

        uint32_t tb = sbase + (uint32_t)(it % NSTAGE) * STAGE_B;
        uint32_t aH = tb;
        uint32_t aL = tb + TILE_B;                       // valid when LO
        uint32_t bHb = tb + (LO ? 2u : 1u) * TILE_B;

        #pragma unroll
        for (int kk = 0; kk < 2; ++kk) {
            int c = 2 * kk + lsel;
            uint32_t ah2[2][4], al2[2][4], b[4][4];

            #pragma unroll
            for (int mf = 0; mf < 2; ++mf) {
                int r = wm * 32 + mf * 16 + lrow;
                if (LO) LDSM4(al2[mf], aL + phys_off(r, c));
                LDSM4(ah2[mf], aH + phys_off(r, c));
            }
            #pragma unroll
            for (int p = 0; p < 4; ++p) {
                int r = wn * 64 + p * 16 + lrow;
                LDSM4(b[p], bHb + phys_off(r, c));
            }
            if (LO) {
                #pragma unroll
                for (int mf = 0; mf < 2; ++mf)
                    #pragma unroll
                    for (int p = 0; p < 4; ++p) {
                        MMA16816(acc[mf][2*p],   al2[mf], b[p][0], b[p][1]);
                        MMA16816(acc[mf][2*p+1], al2[mf], b[p][2], b[p][3]);
                    }
            }
            #pragma unroll
            for (int mf = 0; mf < 2; ++mf)
                #pragma unroll
                for (int p = 0; p < 4; ++p) {
                    MMA16816(acc[mf][2*p],   ah2[mf], b[p][0], b[p][1]);
                    MMA16816(acc[mf][2*p+1], ah2[mf], b[p][2], b[p][3]);
                }
        }
    }

    if (EPI == 0) {
        #pragma unroll
        for (int mf = 0; mf < 2; ++mf) {
            int rbase = row0 + wm * 32 + mf * 16 + (lane >> 2);
            #pragma unroll
            for (int nf = 0; nf < 8; ++nf) {
                int cc = col0 + wn * 64 + nf * 8 + (lane & 3) * 2;
                float2 v0 = make_float2(acc[mf][nf][0], acc[mf][nf][1]);
                float2 v1 = make_float2(acc[mf][nf][2], acc[mf][nf][3]);
                *reinterpret_cast<float2*>(&C[(size_t)rbase * N + cc]) = v0;
                *reinterpret_cast<float2*>(&C[(size_t)(rbase + 8) * N + cc]) = v1;
            }
        }
    } else if (EPI == 1) {
        #pragma unroll
        for (int mf = 0; mf < 2; ++mf) {
            int rbase = row0 + wm * 32 + mf * 16 + (lane >> 2);
            #pragma unroll
            for (int nf = 0; nf < 8; ++nf) {
                int cc = col0 + wn * 64 + nf * 8 + (lane & 3) * 2;
                *reinterpret_cast<uint32_t*>(&Dh[(size_t)rbase * N + cc]) =
                    pack_h2(acc[mf][nf][0], acc[mf][nf][1]);
                *reinterpret_cast<uint32_t*>(&Dh[(size_t)(rbase + 8) * N + cc]) =
                    pack_h2(acc[mf][nf][2], acc[mf][nf][3]);
            }
        }
    } else {
        // rope + store. Dl != nullptr -> hi/lo pair (Q); else hi only (K).
        __syncthreads();   // all warps done with smem frags before reuse
        float* S = reinterpret_cast<float*>(smem);
        #pragma unroll
        for (int mf = 0; mf < 2; ++mf) {
            int rl = wm * 32 + mf * 16 + (lane >> 2);
            #pragma unroll
            for (int nf = 0; nf < 8; ++nf) {
                int cl2 = wn * 64 + nf * 8 + (lane & 3) * 2;
                S[rl * 132 + cl2]           = acc[mf][nf][0];
                S[rl * 132 + cl2 + 1]       = acc[mf][nf][1];
                S[(rl + 8) * 132 + cl2]     = acc[mf][nf][2];
                S[(rl + 8) * 132 + cl2 + 1] = acc[mf][nf][3];
            }
        }
        __syncthreads();
        #pragma unroll
        for (int u = 0; u < 32; ++u) {
            int idx = tid + u * 256;          // 0..8191
            int r = idx >> 6, j = idx & 63;
            float x1 = S[r * 132 + j];
            float x2 = S[r * 132 + j + 64];
            float pos = (float)positions[row0 + r];
            float inv = expf(-9.210340371976184f * (float)j * (1.0f / 64.0f));
            float sn, cs;
            sincosf(pos * inv, &sn, &cs);
            float y1 = x1 * cs - x2 * sn;
            float y2 = x1 * sn + x2 * cs;
            size_t base = (size_t)(row0 + r) * N + col0 + j;
            __half h1 = __float2half_rn(y1);
            __half h2 = __float2half_rn(y2);
            Dh[base]      = h1;
            Dh[base + 64] = h2;
            if (Dl) {
                Dl[base]      = __float2half_rn(y1 - __half2float(h1));
                Dl[base + 64] = __float2half_rn(y2 - __half2float(h2));
            }
        }
    }
}

#define GEMM_SMEM_LO (NSTAGE*3u*TILE_B)   // 72 KB
#define GEMM_SMEM_1P (NSTAGE*2u*TILE_B)   // 48 KB

// ---------------------------------------------------------------------------
// Tensor-core flash attention, fp16 (QK 2-pass, PV 1-pass), double-buffered KV.
// CTA: 64 queries x (head, batch). 4 warps. K tile = 64, 2 stages.
// smem: qh,ql (16KB each) + 2 stages x {kh,vh} (16KB each) = 96KB.
// LPT: qt reversed so longest CTAs start first.  ctx written fp16 hi only.
// ---------------------------------------------------------------------------
#define AQ 64
#define AKT 64
#define QTILE 16384u
#define KVTILE 16384u
#define KVSTAGE (2u*KVTILE)
#define ATT_SMEM (2u*QTILE + 2u*KVSTAGE)   // 96 KB

__device__ __forceinline__ uint32_t off256(int r, int c) {
    return (uint32_t)(r * 256 + (((c ^ (r & 7)) & 15) << 4));
}

__device__ __forceinline__ void attn_load_kv(
    uint32_t dst, int tid, int b, int kvh, int k0,
    const __half* kh, const __half* vh)
{
    const __half* srcs[2] = {kh, vh};
    #pragma unroll
    for (int u = 0; u < 16; ++u) {
        int idx = tid + u * 128;          // 0..2047
        int t = idx >> 10, win = idx & 1023;
        int r = win >> 4, c = win & 15;
        const __half* gp = srcs[t] +
            (((size_t)(b * SEQ + k0 + r) * KVH + kvh) * HD + c * 8);
        uint32_t d = dst + (uint32_t)t * KVTILE + off256(r, c);
        asm volatile("cp.async.cg.shared.global [%0], [%1], 16;" :: "r"(d), "l"(gp));
    }
}

__global__ __launch_bounds__(128)
void attn_mma_kernel(const __half* __restrict__ qh, const __half* __restrict__ ql,
                     const __half* __restrict__ kh, const __half* __restrict__ vh,
                     __half* __restrict__ ch)
{
    extern __shared__ char asmem[];
    uint32_t sb = (uint32_t)__cvta_generic_to_shared(asmem);
    uint32_t sqh = sb, sql = sb + QTILE;
    uint32_t kvs0 = sb + 2 * QTILE;

    int qt = gridDim.x - 1 - blockIdx.x;   // LPT: longest CTAs first
    int h = blockIdx.y, b = blockIdx.z;
    int tid = threadIdx.x, lane = tid & 31, w = tid >> 5;
    int q0 = qt * AQ;
    int kvh = h >> 2;
    const float SC = 0.08838834764831845f;   // 1/sqrt(128)

    int lrow = (lane & 7) | ((lane >> 4) << 3);
    int lsel = (lane >> 3) & 1;
    int vrow = (lane & 7) | (((lane >> 3) & 1) << 3);
    int vcol = lane >> 4;

    const int nt = qt + 1;   // number of 64-key tiles

    // group 0: Q (hi+lo) + KV tile 0
    {
        const __half* srcs[2] = {qh, ql};
        uint32_t dsts[2] = {sqh, sql};
        #pragma unroll
        for (int u = 0; u < 16; ++u) {
            int idx = tid + u * 128;
            int t = idx >> 10, win = idx & 1023;
            int r = win >> 4, c = win & 15;
            const __half* gp = srcs[t] +
                (((size_t)(b * SEQ + q0 + r) * QH + h) * HD + c * 8);
            uint32_t d = dsts[t] + off256(r, c);
            asm volatile("cp.async.cg.shared.global [%0], [%1], 16;" :: "r"(d), "l"(gp));
        }
        attn_load_kv(kvs0, tid, b, kvh, 0, kh, vh);
        asm volatile("cp.async.commit_group;" ::: "memory");
    }
    // group 1: KV tile 1 (prefetch; reads valid memory even when nt == 1)
    {
        int k1 = (1 < nt) ? AKT : 0;
        attn_load_kv(kvs0 + KVSTAGE, tid, b, kvh, k1, kh, vh);
        asm volatile("cp.async.commit_group;" ::: "memory");
    }

    float o[16][4];
    #pragma unroll
    for (int i = 0; i < 16; i++) {
        o[i][0] = 0.f; o[i][1] = 0.f; o[i][2] = 0.f; o[i][3] = 0.f;
    }
    float mrun0 = -1e30f, mrun1 = -1e30f, l0 = 0.f, l1 = 0.f;

    for (int kt = 0; kt < nt; ++kt) {
        int k0 = kt * AKT;
        if (kt + 1 < nt)
            asm volatile("cp.async.wait_group 1;" ::: "memory");
        else
            asm volatile("cp.async.wait_group 0;" ::: "memory");
        __syncthreads();

        uint32_t st = kvs0 + (uint32_t)(kt & 1) * KVSTAGE;
        uint32_t skh = st, svh = st + KVTILE;

        // ---- S = Q K^T (2 compensated passes), 64 keys ----
        float s[8][4];
        #pragma unroll
        for (int f = 0; f < 8; f++) {
            s[f][0] = 0.f; s[f][1] = 0.f; s[f][2] = 0.f; s[f][3] = 0.f;
        }
        #pragma unroll
        for (int kk = 0; kk < 8; ++kk) {
            int c = 2 * kk + lsel;
            uint32_t qa[4], qb[4], kbf[4][4];
            LDSM4(qa, sqh + off256(w * 16 + lrow, c));
            LDSM4(qb, sql + off256(w * 16 + lrow, c));
            #pragma unroll
            for (int p = 0; p < 4; ++p)
                LDSM4(kbf[p], skh + off256(p * 16 + lrow, c));
            #pragma unroll
            for (int p = 0; p < 4; ++p) {
                MMA16816(s[2*p],   qa, kbf[p][0], kbf[p][1]);
                MMA16816(s[2*p+1], qa, kbf[p][2], kbf[p][3]);
                MMA16816(s[2*p],   qb, kbf[p][0], kbf[p][1]);
                MMA16816(s[2*p+1], qb, kbf[p][2], kbf[p][3]);
            }
        }

        // ---- scale (fp32) then causal mask (diagonal tile only) ----
        #pragma unroll
        for (int f = 0; f < 8; f++) {
            s[f][0] *= SC; s[f][1] *= SC; s[f][2] *= SC; s[f][3] *= SC;
        }
        if (k0 + AKT - 1 > q0) {
            #pragma unroll
            for (int f = 0; f < 8; ++f) {
                #pragma unroll
                for (int cc = 0; cc < 4; ++cc) {
                    int col = f * 8 + (lane & 3) * 2 + (cc & 1);
                    int row = w * 16 + (lane >> 2) + ((cc >> 1) << 3);
                    if (k0 + col > q0 + row) s[f][cc] = -1e30f;
                }
            }
        }

        // ---- online softmax ----
        float mx0 = -1e30f, mx1 = -1e30f;
        #pragma unroll
        for (int f = 0; f < 8; f++) {
            mx0 = fmaxf(mx0, fmaxf(s[f][0], s[f][1]));
            mx1 = fmaxf(mx1, fmaxf(s[f][2], s[f][3]));
        }
        mx0 = fmaxf(mx0, __shfl_xor_sync(0xffffffffu, mx0, 1));
        mx0 = fmaxf(mx0, __shfl_xor_sync(0xffffffffu, mx0, 2));
        mx1 = fmaxf(mx1, __shfl_xor_sync(0xffffffffu, mx1, 1));
        mx1 = fmaxf(mx1, __shfl_xor_sync(0xffffffffu, mx1, 2));

        float mn0 = fmaxf(mrun0, mx0), mn1 = fmaxf(mrun1, mx1);
        float al0 = __expf(mrun0 - mn0), al1 = __expf(mrun1 - mn1);
        mrun0 = mn0; mrun1 = mn1;

        float sum0 = 0.f, sum1 = 0.f;
        #pragma unroll
        for (int f = 0; f < 8; f++) {
            s[f][0] = __expf(s[f][0] - mn0); sum0 += s[f][0];
            s[f][1] = __expf(s[f][1] - mn0); sum0 += s[f][1];
            s[f][2] = __expf(s[f][2] - mn1); sum1 += s[f][2];
            s[f][3] = __expf(s[f][3] - mn1); sum1 += s[f][3];
        }
        sum0 += __shfl_xor_sync(0xffffffffu, sum0, 1);
        sum0 += __shfl_xor_sync(0xffffffffu, sum0, 2);
        sum1 += __shfl_xor_sync(0xffffffffu, sum1, 1);
        sum1 += __shfl_xor_sync(0xffffffffu, sum1, 2);
        l0 = l0 * al0 + sum0;
        l1 = l1 * al1 + sum1;

        #pragma unroll
        for (int nf = 0; nf < 16; ++nf) {
            o[nf][0] *= al0; o[nf][1] *= al0;
            o[nf][2] *= al1; o[nf][3] *= al1;
        }

        // ---- O += P V (1 pass, fp16 P) ----
        #pragma unroll
        for (int j = 0; j < 4; ++j) {
            uint32_t ph[4];
            ph[0] = pack_h2(s[2*j][0],   s[2*j][1]);
            ph[1] = pack_h2(s[2*j][2],   s[2*j][3]);
            ph[2] = pack_h2(s[2*j+1][0], s[2*j+1][1]);
            ph[3] = pack_h2(s[2*j+1][2], s[2*j+1][3]);
            #pragma unroll
            for (int nb = 0; nb < 8; ++nb) {
                uint32_t vb[4];
                LDSM4T(vb, svh + off256(16 * j + vrow, nb * 2 + vcol));
                MMA_PV(o[2*nb],   ph, vb[0], vb[1]);
                MMA_PV(o[2*nb+1], ph, vb[2], vb[3]);
            }
        }

        __syncthreads();
        if (kt + 2 < nt) {
            attn_load_kv(kvs0 + (uint32_t)(kt & 1) * KVSTAGE, tid, b, kvh,
                         (kt + 2) * AKT, kh, vh);
            asm volatile("cp.async.commit_group;" ::: "memory");
        }
    }

    // ---- normalize + write fp16 ctx (hi only) ----
    float inv0 = 1.f / l0, inv1 = 1.f / l1;
    int r0g = q0 + w * 16 + (lane >> 2);
    #pragma unroll
    for (int nf = 0; nf < 16; ++nf) {
        int col = nf * 8 + (lane & 3) * 2;
        size_t base0 = ((size_t)(b * SEQ + r0g) * QH + h) * HD + col;
        size_t base1 = ((size_t)(b * SEQ + r0g + 8) * QH + h) * HD + col;
        *reinterpret_cast<uint32_t*>(&ch[base0]) =
            pack_h2(o[nf][0] * inv0, o[nf][1] * inv0);
        *reinterpret_cast<uint32_t*>(&ch[base1]) =
            pack_h2(o[nf][2] * inv1, o[nf][3] * inv1);
    }
}

// ---------------------------------------------------------------------------
// Launch
// ---------------------------------------------------------------------------
extern "C" void kernel_launch(void* const* d_in, const int* in_sizes, int n_in,
                              void* d_out, int out_size)
{
    const float* x         = (const float*)d_in[0];
    const int*   positions = (const int*)  d_in[1];
    const float* wq        = (const float*)d_in[2];
    const float* wk        = (const float*)d_in[3];
    const float* wv        = (const float*)d_in[4];
    const float* wo        = (const float*)d_in[5];
    float* out = (float*)d_out;

    __half *xh, *xl, *wqh, *wkh, *wvh, *woh, *ch;
    __half *aqh, *aql, *akh, *avh;
    cudaGetSymbolAddress((void**)&xh,  g_xh);  cudaGetSymbolAddress((void**)&xl,  g_xl);
    cudaGetSymbolAddress((void**)&wqh, g_wqh);
    cudaGetSymbolAddress((void**)&wkh, g_wkh);
    cudaGetSymbolAddress((void**)&wvh, g_wvh);
    cudaGetSymbolAddress((void**)&woh, g_woh);
    cudaGetSymbolAddress((void**)&ch,  g_ch);
    cudaGetSymbolAddress((void**)&aqh, g_aqh); cudaGetSymbolAddress((void**)&aql, g_aql);
    cudaGetSymbolAddress((void**)&akh, g_akh);
    cudaGetSymbolAddress((void**)&avh, g_avh);

    cudaFuncSetAttribute((const void*)gemm_mma_kernel<1, true>,
                         cudaFuncAttributeMaxDynamicSharedMemorySize, GEMM_SMEM_LO);
    cudaFuncSetAttribute((const void*)gemm_mma_kernel<2, true>,
                         cudaFuncAttributeMaxDynamicSharedMemorySize, GEMM_SMEM_LO);
    cudaFuncSetAttribute((const void*)gemm_mma_kernel<0, false>,
                         cudaFuncAttributeMaxDynamicSharedMemorySize, GEMM_SMEM_1P);
    cudaFuncSetAttribute(attn_mma_kernel,
                         cudaFuncAttributeMaxDynamicSharedMemorySize, (int)ATT_SMEM);

    // Splits / converts
    {
        int n4;
        n4 = NT * DMODEL / 4;
        split_h_kernel<<<(n4 + 255) / 256, 256>>>((const float4*)x, (uint2*)xh, (uint2*)xl, n4);
        n4 = QH * HD * DMODEL / 4;
        tohalf_kernel<<<(n4 + 255) / 256, 256>>>((const float4*)wq, (uint2*)wqh, n4);
        n4 = KVH * HD * DMODEL / 4;
        tohalf_kernel<<<(n4 + 255) / 256, 256>>>((const float4*)wk, (uint2*)wkh, n4);
        tohalf_kernel<<<(n4 + 255) / 256, 256>>>((const float4*)wv, (uint2*)wvh, n4);
        n4 = DMODEL * QH * HD / 4;
        tohalf_kernel<<<(n4 + 255) / 256, 256>>>((const float4*)wo, (uint2*)woh, n4);
    }

    // Projections with fused epilogues (x 2-pass compensated)
    {
        dim3 blk(256);
        dim3 gq_grid((QH * HD) / 128, NT / 128);
        gemm_mma_kernel<2, true><<<gq_grid, blk, GEMM_SMEM_LO>>>(
            xh, xl, wqh, nullptr, aqh, aql, positions, NT, QH * HD, DMODEL);
        dim3 gkv_grid((KVH * HD) / 128, NT / 128);
        gemm_mma_kernel<2, true><<<gkv_grid, blk, GEMM_SMEM_LO>>>(
            xh, xl, wkh, nullptr, akh, nullptr, positions, NT, KVH * HD, DMODEL);
        gemm_mma_kernel<1, true><<<gkv_grid, blk, GEMM_SMEM_LO>>>(
            xh, xl, wvh, nullptr, avh, nullptr, nullptr, NT, KVH * HD, DMODEL);
    }

    // Attention (QK 2-pass, PV 1-pass) -> ctx fp16
    {
        dim3 grid(SEQ / AQ, QH, BATCH);
        attn_mma_kernel<<<grid, 128, ATT_SMEM>>>(aqh, aql, akh, avh, ch);
    }

    // Output projection (plain fp16 1-pass, fp32 epilogue)
    {
        dim3 blk(256);
        dim3 grid(DMODEL / 128, NT / 128);
        gemm_mma_kernel<0, false><<<grid, blk, GEMM_SMEM_1P>>>(
            ch, nullptr, woh, out, nullptr, nullptr, nullptr, NT, DMODEL, DMODEL);
    }
}

// round 14
// speedup vs baseline: 8.0333x; 1.0475x over previous
#include <cuda_runtime.h>
#include <cuda_fp16.h>
#include <math.h>
#include <stdint.h>

// Problem constants
#define BATCH 2
#define SEQ   2048
#define DMODEL 2048
#define QH 16
#define KVH 4
#define HD 128
#define NT (BATCH*SEQ)          // 4096 rows

// ---------------------------------------------------------------------------
// Scratch buffers (device globals: no allocation allowed)
// ---------------------------------------------------------------------------
__device__ __half g_xh[(size_t)NT * DMODEL];
__device__ __half g_xl[(size_t)NT * DMODEL];
__device__ __half g_wqh[(size_t)(QH*HD) * DMODEL];
__device__ __half g_wkh[(size_t)(KVH*HD) * DMODEL];
__device__ __half g_wvh[(size_t)(KVH*HD) * DMODEL];
__device__ __half g_woh[(size_t)DMODEL * (QH*HD)];
__device__ __half g_ch[(size_t)NT * (QH*HD)];

// attention inputs (post-RoPE)
__device__ __half g_aqh[(size_t)NT * QH * HD];
__device__ __half g_aql[(size_t)NT * QH * HD];
__device__ __half g_akh[(size_t)NT * KVH * HD];
__device__ __half g_avh[(size_t)NT * KVH * HD];

// ---------------------------------------------------------------------------
// helpers
// ---------------------------------------------------------------------------
__device__ __forceinline__ void split_pack(float e0, float e1,
                                           uint32_t& hi, uint32_t& lo)
{
    __half h0 = __float2half_rn(e0);
    __half h1 = __float2half_rn(e1);
    hi = ((uint32_t)__half_as_ushort(h1) << 16) | __half_as_ushort(h0);
    __half g0 = __float2half_rn(e0 - __half2float(h0));
    __half g1 = __float2half_rn(e1 - __half2float(h1));
    lo = ((uint32_t)__half_as_ushort(g1) << 16) | __half_as_ushort(g0);
}

__device__ __forceinline__ uint32_t pack_h2(float e0, float e1)
{
    __half h0 = __float2half_rn(e0);
    __half h1 = __float2half_rn(e1);
    return ((uint32_t)__half_as_ushort(h1) << 16) | __half_as_ushort(h0);
}

// One launch: x hi/lo split + all four weight fp16 converts (range dispatch).
#define NX4  ((NT*DMODEL)/4)
#define NQ4  ((QH*HD*DMODEL)/4)
#define NKV4 ((KVH*HD*DMODEL)/4)
#define NO4  ((DMODEL*QH*HD)/4)
#define PREP_TOTAL (NX4 + NQ4 + 2*NKV4 + NO4)

__global__ void prep_kernel(const float4* __restrict__ x,
                            uint2* __restrict__ xh, uint2* __restrict__ xl,
                            const float4* __restrict__ wq, uint2* __restrict__ wqh,
                            const float4* __restrict__ wk, uint2* __restrict__ wkh,
                            const float4* __restrict__ wv, uint2* __restrict__ wvh,
                            const float4* __restrict__ wo, uint2* __restrict__ woh)
{
    int i = blockIdx.x * blockDim.x + threadIdx.x;
    if (i >= PREP_TOTAL) return;
    if (i < NX4) {
        float4 v = x[i];
        uint2 h, l;
        split_pack(v.x, v.y, h.x, l.x);
        split_pack(v.z, v.w, h.y, l.y);
        xh[i] = h;
        xl[i] = l;
        return;
    }
    int j = i - NX4;
    const float4* src;
    uint2* dst;
    if (j < NQ4)                { src = wq; dst = wqh; }
    else if (j < NQ4 + NKV4)    { src = wk; dst = wkh; j -= NQ4; }
    else if (j < NQ4 + 2*NKV4)  { src = wv; dst = wvh; j -= NQ4 + NKV4; }
    else                        { src = wo; dst = woh; j -= NQ4 + 2*NKV4; }
    float4 v = src[j];
    uint2 h;
    h.x = pack_h2(v.x, v.y);
    h.y = pack_h2(v.z, v.w);
    dst[j] = h;
}

#define LDSM4(r, addr) \
    asm volatile("ldmatrix.sync.aligned.m8n8.x4.shared.b16 {%0,%1,%2,%3}, [%4];" \
        : "=r"((r)[0]), "=r"((r)[1]), "=r"((r)[2]), "=r"((r)[3]) : "r"(addr))

#define LDSM4T(r, addr) \
    asm volatile("ldmatrix.sync.aligned.m8n8.x4.trans.shared.b16 {%0,%1,%2,%3}, [%4];" \
        : "=r"((r)[0]), "=r"((r)[1]), "=r"((r)[2]), "=r"((r)[3]) : "r"(addr))

// A from ldmatrix (reorder 0,2,1,3)
#define MMA16816(acc, A, B0, B1) \
    asm volatile("mma.sync.aligned.m16n8k16.row.col.f32.f16.f16.f32 " \
        "{%0,%1,%2,%3}, {%4,%5,%6,%7}, {%8,%9}, {%0,%1,%2,%3};" \
        : "+f"((acc)[0]), "+f"((acc)[1]), "+f"((acc)[2]), "+f"((acc)[3]) \
        : "r"((A)[0]), "r"((A)[2]), "r"((A)[1]), "r"((A)[3]), "r"(B0), "r"(B1))

// A already in mma register order
#define MMA_PV(acc, A, B0, B1) \
    asm volatile("mma.sync.aligned.m16n8k16.row.col.f32.f16.f16.f32 " \
        "{%0,%1,%2,%3}, {%4,%5,%6,%7}, {%8,%9}, {%0,%1,%2,%3};" \
        : "+f"((acc)[0]), "+f"((acc)[1]), "+f"((acc)[2]), "+f"((acc)[3]) \
        : "r"((A)[0]), "r"((A)[1]), "r"((A)[2]), "r"((A)[3]), "r"(B0), "r"(B1))

// ---------------------------------------------------------------------------
// GEMM constants
// ---------------------------------------------------------------------------
#define BKK 32
#define TILE_B 8192u
#define NSTAGE 3
#define GEMM_SMEM_LO (NSTAGE*3u*TILE_B)   // 72 KB
#define GEMM_SMEM_1P (NSTAGE*2u*TILE_B)   // 48 KB

__device__ __forceinline__ uint32_t phys_off(int r, int c) {
    return (uint32_t)(r * 64 + (((c ^ (r >> 1)) & 3) << 4));
}

// Issue one 3-tile stage (Ah, Al, B) for the 2-pass GEMM.
__device__ __forceinline__ void issue_stage_lo(
    uint32_t sbase, int st, int it, int row0, int col0, int tid, int K,
    const __half* Ah, const __half* Al, const __half* Bh)
{
    int k0 = it * BKK;
    uint32_t dst0 = sbase + (uint32_t)st * (3u * TILE_B);
    #pragma unroll
    for (int u = 0; u < 6; ++u) {
        int idx = tid + u * 256;
        int t = idx >> 9;
        int win = idx & 511;
        int r = win >> 2, c = win & 3;
        const __half* src = (t == 0) ? Ah : (t == 1) ? Al : Bh;
        int gr = ((t == 2) ? col0 : row0) + r;
        const __half* gp = src + (size_t)gr * K + k0 + c * 8;
        uint32_t d = dst0 + (uint32_t)t * TILE_B + phys_off(r, c);
        asm volatile("cp.async.cg.shared.global [%0], [%1], 16;" :: "r"(d), "l"(gp));
    }
    asm volatile("cp.async.commit_group;" ::: "memory");
}

// Issue one 2-tile stage (Ah, B) for the 1-pass GEMM.
__device__ __forceinline__ void issue_stage_1p(
    uint32_t sbase, int st, int it, int row0, int col0, int tid, int K,
    const __half* Ah, const __half* Bh)
{
    int k0 = it * BKK;
    uint32_t dst0 = sbase + (uint32_t)st * (2u * TILE_B);
    #pragma unroll
    for (int u = 0; u < 4; ++u) {
        int idx = tid + u * 256;
        int t = idx >> 9;
        int win = idx & 511;
        int r = win >> 2, c = win & 3;
        const __half* src = (t == 0) ? Ah : Bh;
        int gr = ((t == 1) ? col0 : row0) + r;
        const __half* gp = src + (size_t)gr * K + k0 + c * 8;
        uint32_t d = dst0 + (uint32_t)t * TILE_B + phys_off(r, c);
        asm volatile("cp.async.cg.shared.global [%0], [%1], 16;" :: "r"(d), "l"(gp));
    }
    asm volatile("cp.async.commit_group;" ::: "memory");
}

// ---------------------------------------------------------------------------
// Fused QKV projection. One launch covers all three outputs:
// grid.x 0-15 -> Q cols (rope + hi/lo), 16-19 -> K cols (rope, hi only),
// 20-23 -> V cols (plain fp16). 2-pass compensated mainloop, BK=32, 3 stages.
// ---------------------------------------------------------------------------
__global__ __launch_bounds__(256)
void qkv_mma_kernel(const __half* __restrict__ Ah,
                    const __half* __restrict__ Al,
                    const __half* __restrict__ Wq,
                    const __half* __restrict__ Wk,
                    const __half* __restrict__ Wv,
                    __half* __restrict__ Daqh, __half* __restrict__ Daql,
                    __half* __restrict__ Dakh, __half* __restrict__ Davh,
                    const int* __restrict__ positions)
{
    extern __shared__ char smem[];
    uint32_t sbase = (uint32_t)__cvta_generic_to_shared(smem);

    int tid = threadIdx.x;
    int lane = tid & 31;
    int w = tid >> 5;
    int wm = w & 3;
    int wn = w >> 2;
    int row0 = blockIdx.y * 128;

    // region select
    int bx = blockIdx.x;
    const __half* Bh;
    __half *Dh, *Dl;
    int col0, Nout;
    bool do_rope;
    if (bx < 16)      { Bh = Wq; col0 = bx * 128;        Nout = QH * HD;  Dh = Daqh; Dl = Daql; do_rope = true; }
    else if (bx < 20) { Bh = Wk; col0 = (bx - 16) * 128; Nout = KVH * HD; Dh = Dakh; Dl = nullptr; do_rope = true; }
    else              { Bh = Wv; col0 = (bx - 20) * 128; Nout = KVH * HD; Dh = Davh; Dl = nullptr; do_rope = false; }

    const int K = DMODEL;
    float acc[2][8][4];
    #pragma unroll
    for (int i = 0; i < 2; i++)
        #pragma unroll
        for (int j = 0; j < 8; j++)
            #pragma unroll
            for (int q = 0; q < 4; q++) acc[i][j][q] = 0.f;

    const int nIter = K / BKK;   // 64

    issue_stage_lo(sbase, 0, 0, row0, col0, tid, K, Ah, Al, Bh);
    issue_stage_lo(sbase, 1, 1, row0, col0, tid, K, Ah, Al, Bh);

    int lrow = (lane & 7) + ((lane >> 4) << 3);
    int lsel = (lane >> 3) & 1;

    for (int it = 0; it < nIter; ++it) {
        if (it + 1 < nIter)
            asm volatile("cp.async.wait_group 1;" ::: "memory");
        else
            asm volatile("cp.async.wait_group 0;" ::: "memory");
        __syncthreads();
        if (it + 2 < nIter)
            issue_stage_lo(sbase, (it + 2) % NSTAGE, it + 2, row0, col0, tid, K,
                           Ah, Al, Bh);

        uint32_t tb = sbase + (uint32_t)(it % NSTAGE) * (3u * TILE_B);
        uint32_t aH = tb;
        uint32_t aL = tb + TILE_B;
        uint32_t bHb = tb + 2 * TILE_B;

        #pragma unroll
        for (int kk = 0; kk < 2; ++kk) {
            int c = 2 * kk + lsel;
            uint32_t ah2[2][4], al2[2][4], b[4][4];

            #pragma unroll
            for (int mf = 0; mf < 2; ++mf) {
                int r = wm * 32 + mf * 16 + lrow;
                LDSM4(al2[mf], aL + phys_off(r, c));
                LDSM4(ah2[mf], aH + phys_off(r, c));
            }
            #pragma unroll
            for (int p = 0; p < 4; ++p) {
                int r = wn * 64 + p * 16 + lrow;
                LDSM4(b[p], bHb + phys_off(r, c));
            }
            #pragma unroll
            for (int mf = 0; mf < 2; ++mf)
                #pragma unroll
                for (int p = 0; p < 4; ++p) {
                    MMA16816(acc[mf][2*p],   al2[mf], b[p][0], b[p][1]);
                    MMA16816(acc[mf][2*p+1], al2[mf], b[p][2], b[p][3]);
                }
            #pragma unroll
            for (int mf = 0; mf < 2; ++mf)
                #pragma unroll
                for (int p = 0; p < 4; ++p) {
                    MMA16816(acc[mf][2*p],   ah2[mf], b[p][0], b[p][1]);
                    MMA16816(acc[mf][2*p+1], ah2[mf], b[p][2], b[p][3]);
                }
        }
    }

    if (!do_rope) {
        // V: plain fp16 store
        #pragma unroll
        for (int mf = 0; mf < 2; ++mf) {
            int rbase = row0 + wm * 32 + mf * 16 + (lane >> 2);
            #pragma unroll
            for (int nf = 0; nf < 8; ++nf) {
                int cc = col0 + wn * 64 + nf * 8 + (lane & 3) * 2;
                *reinterpret_cast<uint32_t*>(&Dh[(size_t)rbase * Nout + cc]) =
                    pack_h2(acc[mf][nf][0], acc[mf][nf][1]);
                *reinterpret_cast<uint32_t*>(&Dh[(size_t)(rbase + 8) * Nout + cc]) =
                    pack_h2(acc[mf][nf][2], acc[mf][nf][3]);
            }
        }
    } else {
        // Q/K: rope + store (Q also stores lo)
        __syncthreads();
        float* S = reinterpret_cast<float*>(smem);
        #pragma unroll
        for (int mf = 0; mf < 2; ++mf) {
            int rl = wm * 32 + mf * 16 + (lane >> 2);
            #pragma unroll
            for (int nf = 0; nf < 8; ++nf) {
                int cl2 = wn * 64 + nf * 8 + (lane & 3) * 2;
                S[rl * 132 + cl2]           = acc[mf][nf][0];
                S[rl * 132 + cl2 + 1]       = acc[mf][nf][1];
                S[(rl + 8) * 132 + cl2]     = acc[mf][nf][2];
                S[(rl + 8) * 132 + cl2 + 1] = acc[mf][nf][3];
            }
        }
        __syncthreads();
        #pragma unroll
        for (int u = 0; u < 32; ++u) {
            int idx = tid + u * 256;          // 0..8191
            int r = idx >> 6, j = idx & 63;
            float x1 = S[r * 132 + j];
            float x2 = S[r * 132 + j + 64];
            float pos = (float)positions[row0 + r];
            float inv = expf(-9.210340371976184f * (float)j * (1.0f / 64.0f));
            float sn, cs;
            sincosf(pos * inv, &sn, &cs);
            float y1 = x1 * cs - x2 * sn;
            float y2 = x1 * sn + x2 * cs;
            size_t base = (size_t)(row0 + r) * Nout + col0 + j;
            __half h1 = __float2half_rn(y1);
            __half h2 = __float2half_rn(y2);
            Dh[base]      = h1;
            Dh[base + 64] = h2;
            if (Dl) {
                Dl[base]      = __float2half_rn(y1 - __half2float(h1));
                Dl[base + 64] = __float2half_rn(y2 - __half2float(h2));
            }
        }
    }
}

// ---------------------------------------------------------------------------
// Output projection: plain 1-pass fp16 GEMM, fp32 store.
// ---------------------------------------------------------------------------
__global__ __launch_bounds__(256)
void out_mma_kernel(const __half* __restrict__ Ah,
                    const __half* __restrict__ Bh,
                    float* __restrict__ C, int M, int N, int K)
{
    extern __shared__ char smem[];
    uint32_t sbase = (uint32_t)__cvta_generic_to_shared(smem);

    int tid = threadIdx.x;
    int lane = tid & 31;
    int w = tid >> 5;
    int wm = w & 3;
    int wn = w >> 2;
    int row0 = blockIdx.y * 128;
    int col0 = blockIdx.x * 128;

    float acc[2][8][4];
    #pragma unroll
    for (int i = 0; i < 2; i++)
        #pragma unroll
        for (int j = 0; j < 8; j++)
            #pragma unroll
            for (int q = 0; q < 4; q++) acc[i][j][q] = 0.f;

    const int nIter = K / BKK;

    issue_stage_1p(sbase, 0, 0, row0, col0, tid, K, Ah, Bh);
    issue_stage_1p(sbase, 1, 1, row0, col0, tid, K, Ah, Bh);

    int lrow = (lane & 7) + ((lane >> 4) << 3);
    int lsel = (lane >> 3) & 1;

    for (int it = 0; it < nIter; ++it) {
        if (it + 1 < nIter)
            asm volatile("cp.async.wait_group 1;" ::: "memory");
        else
            asm volatile("cp.async.wait_group 0;" ::: "memory");
        __syncthreads();
        if (it + 2 < nIter)
            issue_stage_1p(sbase, (it + 2) % NSTAGE, it + 2, row0, col0, tid, K,
                           Ah, Bh);

        uint32_t tb = sbase + (uint32_t)(it % NSTAGE) * (2u * TILE_B);
        uint32_t aH = tb;
        uint32_t bHb = tb + TILE_B;

        #pragma unroll
        for (int kk = 0; kk < 2; ++kk) {
            int c = 2 * kk + lsel;
            uint32_t ah2[2][4], b[4][4];

            #pragma unroll
            for (int mf = 0; mf < 2; ++mf) {
                int r = wm * 32 + mf * 16 + lrow;
                LDSM4(ah2[mf], aH + phys_off(r, c));
            }
            #pragma unroll
            for (int p = 0; p < 4; ++p) {
                int r = wn * 64 + p * 16 + lrow;
                LDSM4(b[p], bHb + phys_off(r, c));
            }
            #pragma unroll
            for (int mf = 0; mf < 2; ++mf)
                #pragma unroll
                for (int p = 0; p < 4; ++p) {
                    MMA16816(acc[mf][2*p],   ah2[mf], b[p][0], b[p][1]);
                    MMA16816(acc[mf][2*p+1], ah2[mf], b[p][2], b[p][3]);
                }
        }
    }

    #pragma unroll
    for (int mf = 0; mf < 2; ++mf) {
        int rbase = row0 + wm * 32 + mf * 16 + (lane >> 2);
        #pragma unroll
        for (int nf = 0; nf < 8; ++nf) {
            int cc = col0 + wn * 64 + nf * 8 + (lane & 3) * 2;
            float2 v0 = make_float2(acc[mf][nf][0], acc[mf][nf][1]);
            float2 v1 = make_float2(acc[mf][nf][2], acc[mf][nf][3]);
            *reinterpret_cast<float2*>(&C[(size_t)rbase * N + cc]) = v0;
            *reinterpret_cast<float2*>(&C[(size_t)(rbase + 8) * N + cc]) = v1;
        }
    }
}

// ---------------------------------------------------------------------------
// Tensor-core flash attention, fp16 (QK 2-pass, PV 1-pass), double-buffered KV.
// CTA: 64 queries x (head, batch). 4 warps. K tile = 64, 2 stages.
// smem: qh,ql (16KB each) + 2 stages x {kh,vh} (16KB each) = 96KB.
// LPT: qt reversed so longest CTAs start first.  ctx written fp16 hi only.
// ---------------------------------------------------------------------------
#define AQ 64
#define AKT 64
#define QTILE 16384u
#define KVTILE 16384u
#define KVSTAGE (2u*KVTILE)
#define ATT_SMEM (2u*QTILE + 2u*KVSTAGE)   // 96 KB

__device__ __forceinline__ uint32_t off256(int r, int c) {
    return (uint32_t)(r * 256 + (((c ^ (r & 7)) & 15) << 4));
}

__device__ __forceinline__ void attn_load_kv(
    uint32_t dst, int tid, int b, int kvh, int k0,
    const __half* kh, const __half* vh)
{
    const __half* srcs[2] = {kh, vh};
    #pragma unroll
    for (int u = 0; u < 16; ++u) {
        int idx = tid + u * 128;          // 0..2047
        int t = idx >> 10, win = idx & 1023;
        int r = win >> 4, c = win & 15;
        const __half* gp = srcs[t] +
            (((size_t)(b * SEQ + k0 + r) * KVH + kvh) * HD + c * 8);
        uint32_t d = dst + (uint32_t)t * KVTILE + off256(r, c);
        asm volatile("cp.async.cg.shared.global [%0], [%1], 16;" :: "r"(d), "l"(gp));
    }
}

__global__ __launch_bounds__(128)
void attn_mma_kernel(const __half* __restrict__ qh, const __half* __restrict__ ql,
                     const __half* __restrict__ kh, const __half* __restrict__ vh,
                     __half* __restrict__ ch)
{
    extern __shared__ char asmem[];
    uint32_t sb = (uint32_t)__cvta_generic_to_shared(asmem);
    uint32_t sqh = sb, sql = sb + QTILE;
    uint32_t kvs0 = sb + 2 * QTILE;

    int qt = gridDim.x - 1 - blockIdx.x;   // LPT: longest CTAs first
    int h = blockIdx.y, b = blockIdx.z;
    int tid = threadIdx.x, lane = tid & 31, w = tid >> 5;
    int q0 = qt * AQ;
    int kvh = h >> 2;
    const float SC = 0.08838834764831845f;   // 1/sqrt(128)

    int lrow = (lane & 7) | ((lane >> 4) << 3);
    int lsel = (lane >> 3) & 1;
    int vrow = (lane & 7) | (((lane >> 3) & 1) << 3);
    int vcol = lane >> 4;

    const int nt = qt + 1;   // number of 64-key tiles

    // group 0: Q (hi+lo) + KV tile 0
    {
        const __half* srcs[2] = {qh, ql};
        uint32_t dsts[2] = {sqh, sql};
        #pragma unroll
        for (int u = 0; u < 16; ++u) {
            int idx = tid + u * 128;
            int t = idx >> 10, win = idx & 1023;
            int r = win >> 4, c = win & 15;
            const __half* gp = srcs[t] +
                (((size_t)(b * SEQ + q0 + r) * QH + h) * HD + c * 8);
            uint32_t d = dsts[t] + off256(r, c);
            asm volatile("cp.async.cg.shared.global [%0], [%1], 16;" :: "r"(d), "l"(gp));
        }
        attn_load_kv(kvs0, tid, b, kvh, 0, kh, vh);
        asm volatile("cp.async.commit_group;" ::: "memory");
    }
    // group 1: KV tile 1 (prefetch; reads valid memory even when nt == 1)
    {
        int k1 = (1 < nt) ? AKT : 0;
        attn_load_kv(kvs0 + KVSTAGE, tid, b, kvh, k1, kh, vh);
        asm volatile("cp.async.commit_group;" ::: "memory");
    }

    float o[16][4];
    #pragma unroll
    for (int i = 0; i < 16; i++) {
        o[i][0] = 0.f; o[i][1] = 0.f; o[i][2] = 0.f; o[i][3] = 0.f;
    }
    float mrun0 = -1e30f, mrun1 = -1e30f, l0 = 0.f, l1 = 0.f;

    for (int kt = 0; kt < nt; ++kt) {
        int k0 = kt * AKT;
        if (kt + 1 < nt)
            asm volatile("cp.async.wait_group 1;" ::: "memory");
        else
            asm volatile("cp.async.wait_group 0;" ::: "memory");
        __syncthreads();

        uint32_t st = kvs0 + (uint32_t)(kt & 1) * KVSTAGE;
        uint32_t skh = st, svh = st + KVTILE;

        // ---- S = Q K^T (2 compensated passes), 64 keys ----
        float s[8][4];
        #pragma unroll
        for (int f = 0; f < 8; f++) {
            s[f][0] = 0.f; s[f][1] = 0.f; s[f][2] = 0.f; s[f][3] = 0.f;
        }
        #pragma unroll
        for (int kk = 0; kk < 8; ++kk) {
            int c = 2 * kk + lsel;
            uint32_t qa[4], qb[4], kbf[4][4];
            LDSM4(qa, sqh + off256(w * 16 + lrow, c));
            LDSM4(qb, sql + off256(w * 16 + lrow, c));
            #pragma unroll
            for (int p = 0; p < 4; ++p)
                LDSM4(kbf[p], skh + off256(p * 16 + lrow, c));
            #pragma unroll
            for (int p = 0; p < 4; ++p) {
                MMA16816(s[2*p],   qa, kbf[p][0], kbf[p][1]);
                MMA16816(s[2*p+1], qa, kbf[p][2], kbf[p][3]);
                MMA16816(s[2*p],   qb, kbf[p][0], kbf[p][1]);
                MMA16816(s[2*p+1], qb, kbf[p][2], kbf[p][3]);
            }
        }

        // ---- scale (fp32) then causal mask (diagonal tile only) ----
        #pragma unroll
        for (int f = 0; f < 8; f++) {
            s[f][0] *= SC; s[f][1] *= SC; s[f][2] *= SC; s[f][3] *= SC;
        }
        if (k0 + AKT - 1 > q0) {
            #pragma unroll
            for (int f = 0; f < 8; ++f) {
                #pragma unroll
                for (int cc = 0; cc < 4; ++cc) {
                    int col = f * 8 + (lane & 3) * 2 + (cc & 1);
                    int row = w * 16 + (lane >> 2) + ((cc >> 1) << 3);
                    if (k0 + col > q0 + row) s[f][cc] = -1e30f;
                }
            }
        }

        // ---- online softmax ----
        float mx0 = -1e30f, mx1 = -1e30f;
        #pragma unroll
        for (int f = 0; f < 8; f++) {
            mx0 = fmaxf(mx0, fmaxf(s[f][0], s[f][1]));
            mx1 = fmaxf(mx1, fmaxf(s[f][2], s[f][3]));
        }
        mx0 = fmaxf(mx0, __shfl_xor_sync(0xffffffffu, mx0, 1));
        mx0 = fmaxf(mx0, __shfl_xor_sync(0xffffffffu, mx0, 2));
        mx1 = fmaxf(mx1, __shfl_xor_sync(0xffffffffu, mx1, 1));
        mx1 = fmaxf(mx1, __shfl_xor_sync(0xffffffffu, mx1, 2));

        float mn0 = fmaxf(mrun0, mx0), mn1 = fmaxf(mrun1, mx1);
        float al0 = __expf(mrun0 - mn0), al1 = __expf(mrun1 - mn1);
        mrun0 = mn0; mrun1 = mn1;

        float sum0 = 0.f, sum1 = 0.f;
        #pragma unroll
        for (int f = 0; f < 8; f++) {
            s[f][0] = __expf(s[f][0] - mn0); sum0 += s[f][0];
            s[f][1] = __expf(s[f][1] - mn0); sum0 += s[f][1];
            s[f][2] = __expf(s[f][2] - mn1); sum1 += s[f][2];
            s[f][3] = __expf(s[f][3] - mn1); sum1 += s[f][3];
        }
        sum0 += __shfl_xor_sync(0xffffffffu, sum0, 1);
        sum0 += __shfl_xor_sync(0xffffffffu, sum0, 2);
        sum1 += __shfl_xor_sync(0xffffffffu, sum1, 1);
        sum1 += __shfl_xor_sync(0xffffffffu, sum1, 2);
        l0 = l0 * al0 + sum0;
        l1 = l1 * al1 + sum1;

        #pragma unroll
        for (int nf = 0; nf < 16; ++nf) {
            o[nf][0] *= al0; o[nf][1] *= al0;
            o[nf][2] *= al1; o[nf][3] *= al1;
        }

        // ---- O += P V (1 pass, fp16 P) ----
        #pragma unroll
        for (int j = 0; j < 4; ++j) {
            uint32_t ph[4];
            ph[0] = pack_h2(s[2*j][0],   s[2*j][1]);
            ph[1] = pack_h2(s[2*j][2],   s[2*j][3]);
            ph[2] = pack_h2(s[2*j+1][0], s[2*j+1][1]);
            ph[3] = pack_h2(s[2*j+1][2], s[2*j+1][3]);
            #pragma unroll
            for (int nb = 0; nb < 8; ++nb) {
                uint32_t vb[4];
                LDSM4T(vb, svh + off256(16 * j + vrow, nb * 2 + vcol));
                MMA_PV(o[2*nb],   ph, vb[0], vb[1]);
                MMA_PV(o[2*nb+1], ph, vb[2], vb[3]);
            }
        }

        __syncthreads();
        if (kt + 2 < nt) {
            attn_load_kv(kvs0 + (uint32_t)(kt & 1) * KVSTAGE, tid, b, kvh,
                         (kt + 2) * AKT, kh, vh);
            asm volatile("cp.async.commit_group;" ::: "memory");
        }
    }

    // ---- normalize + write fp16 ctx (hi only) ----
    float inv0 = 1.f / l0, inv1 = 1.f / l1;
    int r0g = q0 + w * 16 + (lane >> 2);
    #pragma unroll
    for (int nf = 0; nf < 16; ++nf) {
        int col = nf * 8 + (lane & 3) * 2;
        size_t base0 = ((size_t)(b * SEQ + r0g) * QH + h) * HD + col;
        size_t base1 = ((size_t)(b * SEQ + r0g + 8) * QH + h) * HD + col;
        *reinterpret_cast<uint32_t*>(&ch[base0]) =
            pack_h2(o[nf][0] * inv0, o[nf][1] * inv0);
        *reinterpret_cast<uint32_t*>(&ch[base1]) =
            pack_h2(o[nf][2] * inv1, o[nf][3] * inv1);
    }
}

// ---------------------------------------------------------------------------
// Launch
// ---------------------------------------------------------------------------
extern "C" void kernel_launch(void* const* d_in, const int* in_sizes, int n_in,
                              void* d_out, int out_size)
{
    const float* x         = (const float*)d_in[0];
    const int*   positions = (const int*)  d_in[1];
    const float* wq        = (const float*)d_in[2];
    const float* wk        = (const float*)d_in[3];
    const float* wv        = (const float*)d_in[4];
    const float* wo        = (const float*)d_in[5];
    float* out = (float*)d_out;

    __half *xh, *xl, *wqh, *wkh, *wvh, *woh, *ch;
    __half *aqh, *aql, *akh, *avh;
    cudaGetSymbolAddress((void**)&xh,  g_xh);  cudaGetSymbolAddress((void**)&xl,  g_xl);
    cudaGetSymbolAddress((void**)&wqh, g_wqh);
    cudaGetSymbolAddress((void**)&wkh, g_wkh);
    cudaGetSymbolAddress((void**)&wvh, g_wvh);
    cudaGetSymbolAddress((void**)&woh, g_woh);
    cudaGetSymbolAddress((void**)&ch,  g_ch);
    cudaGetSymbolAddress((void**)&aqh, g_aqh); cudaGetSymbolAddress((void**)&aql, g_aql);
    cudaGetSymbolAddress((void**)&akh, g_akh);
    cudaGetSymbolAddress((void**)&avh, g_avh);

    cudaFuncSetAttribute(qkv_mma_kernel,
                         cudaFuncAttributeMaxDynamicSharedMemorySize, GEMM_SMEM_LO);
    cudaFuncSetAttribute(out_mma_kernel,
                         cudaFuncAttributeMaxDynamicSharedMemorySize, GEMM_SMEM_1P);
    cudaFuncSetAttribute(attn_mma_kernel,
                         cudaFuncAttributeMaxDynamicSharedMemorySize, (int)ATT_SMEM);

    // One prep launch: x split + all weight converts
    prep_kernel<<<(PREP_TOTAL + 255) / 256, 256>>>(
        (const float4*)x, (uint2*)xh, (uint2*)xl,
        (const float4*)wq, (uint2*)wqh,
        (const float4*)wk, (uint2*)wkh,
        (const float4*)wv, (uint2*)wvh,
        (const float4*)wo, (uint2*)woh);

    // Fused QKV projection (one launch, 24 x 32 CTAs)
    {
        dim3 grid(24, NT / 128);
        qkv_mma_kernel<<<grid, 256, GEMM_SMEM_LO>>>(
            xh, xl, wqh, wkh, wvh, aqh, aql, akh, avh, positions);
    }

    // Attention (QK 2-pass, PV 1-pass) -> ctx fp16
    {
        dim3 grid(SEQ / AQ, QH, BATCH);
        attn_mma_kernel<<<grid, 128, ATT_SMEM>>>(aqh, aql, akh, avh, ch);
    }

    // Output projection (plain fp16 1-pass, fp32 epilogue)
    {
        dim3 grid(DMODEL / 128, NT / 128);
        out_mma_kernel<<<grid, 256, GEMM_SMEM_1P>>>(
            ch, woh, out, NT, DMODEL, DMODEL);
    }
}

// round 15
// speedup vs baseline: 8.4275x; 1.0491x over previous
#include <cuda_runtime.h>
#include <cuda_fp16.h>
#include <math.h>
#include <stdint.h>

// Problem constants
#define BATCH 2
#define SEQ   2048
#define DMODEL 2048
#define QH 16
#define KVH 4
#define HD 128
#define NT (BATCH*SEQ)          // 4096 rows

// ---------------------------------------------------------------------------
// Scratch buffers (device globals: no allocation allowed)
// ---------------------------------------------------------------------------
__device__ __half g_xh[(size_t)NT * DMODEL];
__device__ __half g_xl[(size_t)NT * DMODEL];
__device__ __half g_wqh[(size_t)(QH*HD) * DMODEL];
__device__ __half g_wkh[(size_t)(KVH*HD) * DMODEL];
__device__ __half g_wvh[(size_t)(KVH*HD) * DMODEL];
__device__ __half g_woh[(size_t)DMODEL * (QH*HD)];
__device__ __half g_ch[(size_t)NT * (QH*HD)];

// attention inputs (post-RoPE)
__device__ __half g_aqh[(size_t)NT * QH * HD];
__device__ __half g_aql[(size_t)NT * QH * HD];
__device__ __half g_akh[(size_t)NT * KVH * HD];
__device__ __half g_avh[(size_t)NT * KVH * HD];

// ---------------------------------------------------------------------------
// helpers
// ---------------------------------------------------------------------------
__device__ __forceinline__ void split_pack(float e0, float e1,
                                           uint32_t& hi, uint32_t& lo)
{
    __half h0 = __float2half_rn(e0);
    __half h1 = __float2half_rn(e1);
    hi = ((uint32_t)__half_as_ushort(h1) << 16) | __half_as_ushort(h0);
    __half g0 = __float2half_rn(e0 - __half2float(h0));
    __half g1 = __float2half_rn(e1 - __half2float(h1));
    lo = ((uint32_t)__half_as_ushort(g1) << 16) | __half_as_ushort(g0);
}

__device__ __forceinline__ uint32_t pack_h2(float e0, float e1)
{
    __half h0 = __float2half_rn(e0);
    __half h1 = __float2half_rn(e1);
    return ((uint32_t)__half_as_ushort(h1) << 16) | __half_as_ushort(h0);
}

__device__ __forceinline__ float ex2f(float x)
{
    float y;
    asm("ex2.approx.f32 %0, %1;" : "=f"(y) : "f"(x));
    return y;
}

// One launch: x hi/lo split + all four weight fp16 converts (range dispatch).
#define NX4  ((NT*DMODEL)/4)
#define NQ4  ((QH*HD*DMODEL)/4)
#define NKV4 ((KVH*HD*DMODEL)/4)
#define NO4  ((DMODEL*QH*HD)/4)
#define PREP_TOTAL (NX4 + NQ4 + 2*NKV4 + NO4)

__global__ void prep_kernel(const float4* __restrict__ x,
                            uint2* __restrict__ xh, uint2* __restrict__ xl,
                            const float4* __restrict__ wq, uint2* __restrict__ wqh,
                            const float4* __restrict__ wk, uint2* __restrict__ wkh,
                            const float4* __restrict__ wv, uint2* __restrict__ wvh,
                            const float4* __restrict__ wo, uint2* __restrict__ woh)
{
    int i = blockIdx.x * blockDim.x + threadIdx.x;
    if (i >= PREP_TOTAL) return;
    if (i < NX4) {
        float4 v = x[i];
        uint2 h, l;
        split_pack(v.x, v.y, h.x, l.x);
        split_pack(v.z, v.w, h.y, l.y);
        xh[i] = h;
        xl[i] = l;
        return;
    }
    int j = i - NX4;
    const float4* src;
    uint2* dst;
    if (j < NQ4)                { src = wq; dst = wqh; }
    else if (j < NQ4 + NKV4)    { src = wk; dst = wkh; j -= NQ4; }
    else if (j < NQ4 + 2*NKV4)  { src = wv; dst = wvh; j -= NQ4 + NKV4; }
    else                        { src = wo; dst = woh; j -= NQ4 + 2*NKV4; }
    float4 v = src[j];
    uint2 h;
    h.x = pack_h2(v.x, v.y);
    h.y = pack_h2(v.z, v.w);
    dst[j] = h;
}

#define LDSM4(r, addr) \
    asm volatile("ldmatrix.sync.aligned.m8n8.x4.shared.b16 {%0,%1,%2,%3}, [%4];" \
        : "=r"((r)[0]), "=r"((r)[1]), "=r"((r)[2]), "=r"((r)[3]) : "r"(addr))

#define LDSM4T(r, addr) \
    asm volatile("ldmatrix.sync.aligned.m8n8.x4.trans.shared.b16 {%0,%1,%2,%3}, [%4];" \
        : "=r"((r)[0]), "=r"((r)[1]), "=r"((r)[2]), "=r"((r)[3]) : "r"(addr))

// A from ldmatrix (reorder 0,2,1,3)
#define MMA16816(acc, A, B0, B1) \
    asm volatile("mma.sync.aligned.m16n8k16.row.col.f32.f16.f16.f32 " \
        "{%0,%1,%2,%3}, {%4,%5,%6,%7}, {%8,%9}, {%0,%1,%2,%3};" \
        : "+f"((acc)[0]), "+f"((acc)[1]), "+f"((acc)[2]), "+f"((acc)[3]) \
        : "r"((A)[0]), "r"((A)[2]), "r"((A)[1]), "r"((A)[3]), "r"(B0), "r"(B1))

// A already in mma register order
#define MMA_PV(acc, A, B0, B1) \
    asm volatile("mma.sync.aligned.m16n8k16.row.col.f32.f16.f16.f32 " \
        "{%0,%1,%2,%3}, {%4,%5,%6,%7}, {%8,%9}, {%0,%1,%2,%3};" \
        : "+f"((acc)[0]), "+f"((acc)[1]), "+f"((acc)[2]), "+f"((acc)[3]) \
        : "r"((A)[0]), "r"((A)[1]), "r"((A)[2]), "r"((A)[3]), "r"(B0), "r"(B1))

// ---------------------------------------------------------------------------
// GEMM constants: BK=64, tiles 128 rows x 64 halves (128B rows), 2 stages.
// ---------------------------------------------------------------------------
#define BKK 64
#define TILE_B 16384u
#define NSTAGE 2
#define GEMM_SMEM_LO (NSTAGE*3u*TILE_B)   // 96 KB
#define GEMM_SMEM_1P (NSTAGE*2u*TILE_B)   // 64 KB

// 128-byte row swizzle: row r (0..127), 16B-chunk c (0..7)
__device__ __forceinline__ uint32_t off128(int r, int c) {
    return (uint32_t)(r * 128 + (((c ^ (r & 7)) & 7) << 4));
}

// Issue one 3-tile stage (Ah, Al, B) for the 2-pass GEMM. 1024 chunks/tile.
__device__ __forceinline__ void issue_stage_lo(
    uint32_t sbase, int st, int it, int row0, int col0, int tid, int K,
    const __half* Ah, const __half* Al, const __half* Bh)
{
    int k0 = it * BKK;
    uint32_t dst0 = sbase + (uint32_t)st * (3u * TILE_B);
    #pragma unroll
    for (int u = 0; u < 12; ++u) {
        int idx = tid + u * 256;          // 0..3071
        int t = idx >> 10;
        int win = idx & 1023;
        int r = win >> 3, c = win & 7;
        const __half* src = (t == 0) ? Ah : (t == 1) ? Al : Bh;
        int gr = ((t == 2) ? col0 : row0) + r;
        const __half* gp = src + (size_t)gr * K + k0 + c * 8;
        uint32_t d = dst0 + (uint32_t)t * TILE_B + off128(r, c);
        asm volatile("cp.async.cg.shared.global [%0], [%1], 16;" :: "r"(d), "l"(gp));
    }
    asm volatile("cp.async.commit_group;" ::: "memory");
}

// Issue one 2-tile stage (Ah, B) for the 1-pass GEMM.
__device__ __forceinline__ void issue_stage_1p(
    uint32_t sbase, int st, int it, int row0, int col0, int tid, int K,
    const __half* Ah, const __half* Bh)
{
    int k0 = it * BKK;
    uint32_t dst0 = sbase + (uint32_t)st * (2u * TILE_B);
    #pragma unroll
    for (int u = 0; u < 8; ++u) {
        int idx = tid + u * 256;          // 0..2047
        int t = idx >> 10;
        int win = idx & 1023;
        int r = win >> 3, c = win & 7;
        const __half* src = (t == 0) ? Ah : Bh;
        int gr = ((t == 1) ? col0 : row0) + r;
        const __half* gp = src + (size_t)gr * K + k0 + c * 8;
        uint32_t d = dst0 + (uint32_t)t * TILE_B + off128(r, c);
        asm volatile("cp.async.cg.shared.global [%0], [%1], 16;" :: "r"(d), "l"(gp));
    }
    asm volatile("cp.async.commit_group;" ::: "memory");
}

// ---------------------------------------------------------------------------
// Fused QKV projection. grid.x 0-15 -> Q (rope + hi/lo), 16-19 -> K (rope),
// 20-23 -> V (plain fp16). 2-pass compensated, BK=64, 2 stages.
// ---------------------------------------------------------------------------
__global__ __launch_bounds__(256)
void qkv_mma_kernel(const __half* __restrict__ Ah,
                    const __half* __restrict__ Al,
                    const __half* __restrict__ Wq,
                    const __half* __restrict__ Wk,
                    const __half* __restrict__ Wv,
                    __half* __restrict__ Daqh, __half* __restrict__ Daql,
                    __half* __restrict__ Dakh, __half* __restrict__ Davh,
                    const int* __restrict__ positions)
{
    extern __shared__ char smem[];
    uint32_t sbase = (uint32_t)__cvta_generic_to_shared(smem);

    int tid = threadIdx.x;
    int lane = tid & 31;
    int w = tid >> 5;
    int wm = w & 3;
    int wn = w >> 2;
    int row0 = blockIdx.y * 128;

    int bx = blockIdx.x;
    const __half* Bh;
    __half *Dh, *Dl;
    int col0, Nout;
    bool do_rope;
    if (bx < 16)      { Bh = Wq; col0 = bx * 128;        Nout = QH * HD;  Dh = Daqh; Dl = Daql; do_rope = true; }
    else if (bx < 20) { Bh = Wk; col0 = (bx - 16) * 128; Nout = KVH * HD; Dh = Dakh; Dl = nullptr; do_rope = true; }
    else              { Bh = Wv; col0 = (bx - 20) * 128; Nout = KVH * HD; Dh = Davh; Dl = nullptr; do_rope = false; }

    const int K = DMODEL;
    float acc[2][8][4];
    #pragma unroll
    for (int i = 0; i < 2; i++)
        #pragma unroll
        for (int j = 0; j < 8; j++)
            #pragma unroll
            for (int q = 0; q < 4; q++) acc[i][j][q] = 0.f;

    const int nIter = K / BKK;   // 32

    issue_stage_lo(sbase, 0, 0, row0, col0, tid, K, Ah, Al, Bh);

    int lrow = (lane & 7) + ((lane >> 4) << 3);
    int lsel = (lane >> 3) & 1;

    for (int it = 0; it < nIter; ++it) {
        asm volatile("cp.async.wait_group 0;" ::: "memory");
        __syncthreads();
        if (it + 1 < nIter)
            issue_stage_lo(sbase, (it + 1) & 1, it + 1, row0, col0, tid, K,
                           Ah, Al, Bh);

        uint32_t tb = sbase + (uint32_t)(it & 1) * (3u * TILE_B);
        uint32_t aH = tb;
        uint32_t aL = tb + TILE_B;
        uint32_t bHb = tb + 2 * TILE_B;

        #pragma unroll
        for (int kk = 0; kk < 4; ++kk) {
            int c = 2 * kk + lsel;
            uint32_t ah2[2][4], al2[2][4], b[4][4];

            #pragma unroll
            for (int mf = 0; mf < 2; ++mf) {
                int r = wm * 32 + mf * 16 + lrow;
                LDSM4(al2[mf], aL + off128(r, c));
                LDSM4(ah2[mf], aH + off128(r, c));
            }
            #pragma unroll
            for (int p = 0; p < 4; ++p) {
                int r = wn * 64 + p * 16 + lrow;
                LDSM4(b[p], bHb + off128(r, c));
            }
            #pragma unroll
            for (int mf = 0; mf < 2; ++mf)
                #pragma unroll
                for (int p = 0; p < 4; ++p) {
                    MMA16816(acc[mf][2*p],   al2[mf], b[p][0], b[p][1]);
                    MMA16816(acc[mf][2*p+1], al2[mf], b[p][2], b[p][3]);
                }
            #pragma unroll
            for (int mf = 0; mf < 2; ++mf)
                #pragma unroll
                for (int p = 0; p < 4; ++p) {
                    MMA16816(acc[mf][2*p],   ah2[mf], b[p][0], b[p][1]);
                    MMA16816(acc[mf][2*p+1], ah2[mf], b[p][2], b[p][3]);
                }
        }
    }

    if (!do_rope) {
        #pragma unroll
        for (int mf = 0; mf < 2; ++mf) {
            int rbase = row0 + wm * 32 + mf * 16 + (lane >> 2);
            #pragma unroll
            for (int nf = 0; nf < 8; ++nf) {
                int cc = col0 + wn * 64 + nf * 8 + (lane & 3) * 2;
                *reinterpret_cast<uint32_t*>(&Dh[(size_t)rbase * Nout + cc]) =
                    pack_h2(acc[mf][nf][0], acc[mf][nf][1]);
                *reinterpret_cast<uint32_t*>(&Dh[(size_t)(rbase + 8) * Nout + cc]) =
                    pack_h2(acc[mf][nf][2], acc[mf][nf][3]);
            }
        }
    } else {
        __syncthreads();
        float* S = reinterpret_cast<float*>(smem);
        #pragma unroll
        for (int mf = 0; mf < 2; ++mf) {
            int rl = wm * 32 + mf * 16 + (lane >> 2);
            #pragma unroll
            for (int nf = 0; nf < 8; ++nf) {
                int cl2 = wn * 64 + nf * 8 + (lane & 3) * 2;
                S[rl * 132 + cl2]           = acc[mf][nf][0];
                S[rl * 132 + cl2 + 1]       = acc[mf][nf][1];
                S[(rl + 8) * 132 + cl2]     = acc[mf][nf][2];
                S[(rl + 8) * 132 + cl2 + 1] = acc[mf][nf][3];
            }
        }
        __syncthreads();
        #pragma unroll
        for (int u = 0; u < 32; ++u) {
            int idx = tid + u * 256;          // 0..8191
            int r = idx >> 6, j = idx & 63;
            float x1 = S[r * 132 + j];
            float x2 = S[r * 132 + j + 64];
            float pos = (float)positions[row0 + r];
            float inv = expf(-9.210340371976184f * (float)j * (1.0f / 64.0f));
            float sn, cs;
            sincosf(pos * inv, &sn, &cs);
            float y1 = x1 * cs - x2 * sn;
            float y2 = x1 * sn + x2 * cs;
            size_t base = (size_t)(row0 + r) * Nout + col0 + j;
            __half h1 = __float2half_rn(y1);
            __half h2 = __float2half_rn(y2);
            Dh[base]      = h1;
            Dh[base + 64] = h2;
            if (Dl) {
                Dl[base]      = __float2half_rn(y1 - __half2float(h1));
                Dl[base + 64] = __float2half_rn(y2 - __half2float(h2));
            }
        }
    }
}

// ---------------------------------------------------------------------------
// Output projection: plain 1-pass fp16 GEMM, fp32 store. BK=64, 2 stages.
// ---------------------------------------------------------------------------
__global__ __launch_bounds__(256)
void out_mma_kernel(const __half* __restrict__ Ah,
                    const __half* __restrict__ Bh,
                    float* __restrict__ C, int M, int N, int K)
{
    extern __shared__ char smem[];
    uint32_t sbase = (uint32_t)__cvta_generic_to_shared(smem);

    int tid = threadIdx.x;
    int lane = tid & 31;
    int w = tid >> 5;
    int wm = w & 3;
    int wn = w >> 2;
    int row0 = blockIdx.y * 128;
    int col0 = blockIdx.x * 128;

    float acc[2][8][4];
    #pragma unroll
    for (int i = 0; i < 2; i++)
        #pragma unroll
        for (int j = 0; j < 8; j++)
            #pragma unroll
            for (int q = 0; q < 4; q++) acc[i][j][q] = 0.f;

    const int nIter = K / BKK;

    issue_stage_1p(sbase, 0, 0, row0, col0, tid, K, Ah, Bh);

    int lrow = (lane & 7) + ((lane >> 4) << 3);
    int lsel = (lane >> 3) & 1;

    for (int it = 0; it < nIter; ++it) {
        asm volatile("cp.async.wait_group 0;" ::: "memory");
        __syncthreads();
        if (it + 1 < nIter)
            issue_stage_1p(sbase, (it + 1) & 1, it + 1, row0, col0, tid, K,
                           Ah, Bh);

        uint32_t tb = sbase + (uint32_t)(it & 1) * (2u * TILE_B);
        uint32_t aH = tb;
        uint32_t bHb = tb + TILE_B;

        #pragma unroll
        for (int kk = 0; kk < 4; ++kk) {
            int c = 2 * kk + lsel;
            uint32_t ah2[2][4], b[4][4];

            #pragma unroll
            for (int mf = 0; mf < 2; ++mf) {
                int r = wm * 32 + mf * 16 + lrow;
                LDSM4(ah2[mf], aH + off128(r, c));
            }
            #pragma unroll
            for (int p = 0; p < 4; ++p) {
                int r = wn * 64 + p * 16 + lrow;
                LDSM4(b[p], bHb + off128(r, c));
            }
            #pragma unroll
            for (int mf = 0; mf < 2; ++mf)
                #pragma unroll
                for (int p = 0; p < 4; ++p) {
                    MMA16816(acc[mf][2*p],   ah2[mf], b[p][0], b[p][1]);
                    MMA16816(acc[mf][2*p+1], ah2[mf], b[p][2], b[p][3]);
                }
        }
    }

    #pragma unroll
    for (int mf = 0; mf < 2; ++mf) {
        int rbase = row0 + wm * 32 + mf * 16 + (lane >> 2);
        #pragma unroll
        for (int nf = 0; nf < 8; ++nf) {
            int cc = col0 + wn * 64 + nf * 8 + (lane & 3) * 2;
            float2 v0 = make_float2(acc[mf][nf][0], acc[mf][nf][1]);
            float2 v1 = make_float2(acc[mf][nf][2], acc[mf][nf][3]);
            *reinterpret_cast<float2*>(&C[(size_t)rbase * N + cc]) = v0;
            *reinterpret_cast<float2*>(&C[(size_t)(rbase + 8) * N + cc]) = v1;
        }
    }
}

// ---------------------------------------------------------------------------
// Tensor-core flash attention, fp16 (QK 2-pass, PV 1-pass), double-buffered KV.
// CTA: 64 queries x (head, batch). 4 warps. K tile = 64, 2 stages. 96 KB smem.
// LPT order. Softmax in log2 domain (ex2.approx).
// ---------------------------------------------------------------------------
#define AQ 64
#define AKT 64
#define QTILE 16384u
#define KVTILE 16384u
#define KVSTAGE (2u*KVTILE)
#define ATT_SMEM (2u*QTILE + 2u*KVSTAGE)   // 96 KB

__device__ __forceinline__ uint32_t off256(int r, int c) {
    return (uint32_t)(r * 256 + (((c ^ (r & 7)) & 15) << 4));
}

__device__ __forceinline__ void attn_load_kv(
    uint32_t dst, int tid, int b, int kvh, int k0,
    const __half* kh, const __half* vh)
{
    const __half* srcs[2] = {kh, vh};
    #pragma unroll
    for (int u = 0; u < 16; ++u) {
        int idx = tid + u * 128;          // 0..2047
        int t = idx >> 10, win = idx & 1023;
        int r = win >> 4, c = win & 15;
        const __half* gp = srcs[t] +
            (((size_t)(b * SEQ + k0 + r) * KVH + kvh) * HD + c * 8);
        uint32_t d = dst + (uint32_t)t * KVTILE + off256(r, c);
        asm volatile("cp.async.cg.shared.global [%0], [%1], 16;" :: "r"(d), "l"(gp));
    }
}

__global__ __launch_bounds__(128)
void attn_mma_kernel(const __half* __restrict__ qh, const __half* __restrict__ ql,
                     const __half* __restrict__ kh, const __half* __restrict__ vh,
                     __half* __restrict__ ch)
{
    extern __shared__ char asmem[];
    uint32_t sb = (uint32_t)__cvta_generic_to_shared(asmem);
    uint32_t sqh = sb, sql = sb + QTILE;
    uint32_t kvs0 = sb + 2 * QTILE;

    int qt = gridDim.x - 1 - blockIdx.x;   // LPT
    int h = blockIdx.y, b = blockIdx.z;
    int tid = threadIdx.x, lane = tid & 31, w = tid >> 5;
    int q0 = qt * AQ;
    int kvh = h >> 2;
    // 1/sqrt(128) * log2(e): softmax computed in log2 domain
    const float SC2 = 0.08838834764831845f * 1.4426950408889634f;

    int lrow = (lane & 7) | ((lane >> 4) << 3);
    int lsel = (lane >> 3) & 1;
    int vrow = (lane & 7) | (((lane >> 3) & 1) << 3);
    int vcol = lane >> 4;

    const int nt = qt + 1;

    // group 0: Q (hi+lo) + KV tile 0
    {
        const __half* srcs[2] = {qh, ql};
        uint32_t dsts[2] = {sqh, sql};
        #pragma unroll
        for (int u = 0; u < 16; ++u) {
            int idx = tid + u * 128;
            int t = idx >> 10, win = idx & 1023;
            int r = win >> 4, c = win & 15;
            const __half* gp = srcs[t] +
                (((size_t)(b * SEQ + q0 + r) * QH + h) * HD + c * 8);
            uint32_t d = dsts[t] + off256(r, c);
            asm volatile("cp.async.cg.shared.global [%0], [%1], 16;" :: "r"(d), "l"(gp));
        }
        attn_load_kv(kvs0, tid, b, kvh, 0, kh, vh);
        asm volatile("cp.async.commit_group;" ::: "memory");
    }
    // group 1: KV tile 1 (prefetch; valid memory even when nt == 1)
    {
        int k1 = (1 < nt) ? AKT : 0;
        attn_load_kv(kvs0 + KVSTAGE, tid, b, kvh, k1, kh, vh);
        asm volatile("cp.async.commit_group;" ::: "memory");
    }

    float o[16][4];
    #pragma unroll
    for (int i = 0; i < 16; i++) {
        o[i][0] = 0.f; o[i][1] = 0.f; o[i][2] = 0.f; o[i][3] = 0.f;
    }
    float mrun0 = -1e30f, mrun1 = -1e30f, l0 = 0.f, l1 = 0.f;

    for (int kt = 0; kt < nt; ++kt) {
        int k0 = kt * AKT;
        if (kt + 1 < nt)
            asm volatile("cp.async.wait_group 1;" ::: "memory");
        else
            asm volatile("cp.async.wait_group 0;" ::: "memory");
        __syncthreads();

        uint32_t st = kvs0 + (uint32_t)(kt & 1) * KVSTAGE;
        uint32_t skh = st, svh = st + KVTILE;

        // ---- S = Q K^T (2 compensated passes), 64 keys ----
        float s[8][4];
        #pragma unroll
        for (int f = 0; f < 8; f++) {
            s[f][0] = 0.f; s[f][1] = 0.f; s[f][2] = 0.f; s[f][3] = 0.f;
        }
        #pragma unroll
        for (int kk = 0; kk < 8; ++kk) {
            int c = 2 * kk + lsel;
            uint32_t qa[4], qb[4], kbf[4][4];
            LDSM4(qa, sqh + off256(w * 16 + lrow, c));
            LDSM4(qb, sql + off256(w * 16 + lrow, c));
            #pragma unroll
            for (int p = 0; p < 4; ++p)
                LDSM4(kbf[p], skh + off256(p * 16 + lrow, c));
            #pragma unroll
            for (int p = 0; p < 4; ++p) {
                MMA16816(s[2*p],   qa, kbf[p][0], kbf[p][1]);
                MMA16816(s[2*p+1], qa, kbf[p][2], kbf[p][3]);
                MMA16816(s[2*p],   qb, kbf[p][0], kbf[p][1]);
                MMA16816(s[2*p+1], qb, kbf[p][2], kbf[p][3]);
            }
        }

        // ---- scale to log2 domain, then causal mask (diagonal tile only) ----
        #pragma unroll
        for (int f = 0; f < 8; f++) {
            s[f][0] *= SC2; s[f][1] *= SC2; s[f][2] *= SC2; s[f][3] *= SC2;
        }
        if (k0 + AKT - 1 > q0) {
            #pragma unroll
            for (int f = 0; f < 8; ++f) {
                #pragma unroll
                for (int cc = 0; cc < 4; ++cc) {
                    int col = f * 8 + (lane & 3) * 2 + (cc & 1);
                    int row = w * 16 + (lane >> 2) + ((cc >> 1) << 3);
                    if (k0 + col > q0 + row) s[f][cc] = -1e30f;
                }
            }
        }

        // ---- online softmax (log2 domain, ex2.approx) ----
        float mx0 = -1e30f, mx1 = -1e30f;
        #pragma unroll
        for (int f = 0; f < 8; f++) {
            mx0 = fmaxf(mx0, fmaxf(s[f][0], s[f][1]));
            mx1 = fmaxf(mx1, fmaxf(s[f][2], s[f][3]));
        }
        mx0 = fmaxf(mx0, __shfl_xor_sync(0xffffffffu, mx0, 1));
        mx0 = fmaxf(mx0, __shfl_xor_sync(0xffffffffu, mx0, 2));
        mx1 = fmaxf(mx1, __shfl_xor_sync(0xffffffffu, mx1, 1));
        mx1 = fmaxf(mx1, __shfl_xor_sync(0xffffffffu, mx1, 2));

        float mn0 = fmaxf(mrun0, mx0), mn1 = fmaxf(mrun1, mx1);
        float al0 = ex2f(mrun0 - mn0), al1 = ex2f(mrun1 - mn1);
        mrun0 = mn0; mrun1 = mn1;

        float sum0 = 0.f, sum1 = 0.f;
        #pragma unroll
        for (int f = 0; f < 8; f++) {
            s[f][0] = ex2f(s[f][0] - mn0); sum0 += s[f][0];
            s[f][1] = ex2f(s[f][1] - mn0); sum0 += s[f][1];
            s[f][2] = ex2f(s[f][2] - mn1); sum1 += s[f][2];
            s[f][3] = ex2f(s[f][3] - mn1); sum1 += s[f][3];
        }
        sum0 += __shfl_xor_sync(0xffffffffu, sum0, 1);
        sum0 += __shfl_xor_sync(0xffffffffu, sum0, 2);
        sum1 += __shfl_xor_sync(0xffffffffu, sum1, 1);
        sum1 += __shfl_xor_sync(0xffffffffu, sum1, 2);
        l0 = l0 * al0 + sum0;
        l1 = l1 * al1 + sum1;

        #pragma unroll
        for (int nf = 0; nf < 16; ++nf) {
            o[nf][0] *= al0; o[nf][1] *= al0;
            o[nf][2] *= al1; o[nf][3] *= al1;
        }

        // ---- O += P V (1 pass, fp16 P) ----
        #pragma unroll
        for (int j = 0; j < 4; ++j) {
            uint32_t ph[4];
            ph[0] = pack_h2(s[2*j][0],   s[2*j][1]);
            ph[1] = pack_h2(s[2*j][2],   s[2*j][3]);
            ph[2] = pack_h2(s[2*j+1][0], s[2*j+1][1]);
            ph[3] = pack_h2(s[2*j+1][2], s[2*j+1][3]);
            #pragma unroll
            for (int nb = 0; nb < 8; ++nb) {
                uint32_t vb[4];
                LDSM4T(vb, svh + off256(16 * j + vrow, nb * 2 + vcol));
                MMA_PV(o[2*nb],   ph, vb[0], vb[1]);
                MMA_PV(o[2*nb+1], ph, vb[2], vb[3]);
            }
        }

        __syncthreads();
        if (kt + 2 < nt) {
            attn_load_kv(kvs0 + (uint32_t)(kt & 1) * KVSTAGE, tid, b, kvh,
                         (kt + 2) * AKT, kh, vh);
            asm volatile("cp.async.commit_group;" ::: "memory");
        }
    }

    // ---- normalize + write fp16 ctx (hi only) ----
    float inv0 = 1.f / l0, inv1 = 1.f / l1;
    int r0g = q0 + w * 16 + (lane >> 2);
    #pragma unroll
    for (int nf = 0; nf < 16; ++nf) {
        int col = nf * 8 + (lane & 3) * 2;
        size_t base0 = ((size_t)(b * SEQ + r0g) * QH + h) * HD + col;
        size_t base1 = ((size_t)(b * SEQ + r0g + 8) * QH + h) * HD + col;
        *reinterpret_cast<uint32_t*>(&ch[base0]) =
            pack_h2(o[nf][0] * inv0, o[nf][1] * inv0);
        *reinterpret_cast<uint32_t*>(&ch[base1]) =
            pack_h2(o[nf][2] * inv1, o[nf][3] * inv1);
    }
}

// ---------------------------------------------------------------------------
// Launch
// ---------------------------------------------------------------------------
extern "C" void kernel_launch(void* const* d_in, const int* in_sizes, int n_in,
                              void* d_out, int out_size)
{
    const float* x         = (const float*)d_in[0];
    const int*   positions = (const int*)  d_in[1];
    const float* wq        = (const float*)d_in[2];
    const float* wk        = (const float*)d_in[3];
    const float* wv        = (const float*)d_in[4];
    const float* wo        = (const float*)d_in[5];
    float* out = (float*)d_out;

    __half *xh, *xl, *wqh, *wkh, *wvh, *woh, *ch;
    __half *aqh, *aql, *akh, *avh;
    cudaGetSymbolAddress((void**)&xh,  g_xh);  cudaGetSymbolAddress((void**)&xl,  g_xl);
    cudaGetSymbolAddress((void**)&wqh, g_wqh);
    cudaGetSymbolAddress((void**)&wkh, g_wkh);
    cudaGetSymbolAddress((void**)&wvh, g_wvh);
    cudaGetSymbolAddress((void**)&woh, g_woh);
    cudaGetSymbolAddress((void**)&ch,  g_ch);
    cudaGetSymbolAddress((void**)&aqh, g_aqh); cudaGetSymbolAddress((void**)&aql, g_aql);
    cudaGetSymbolAddress((void**)&akh, g_akh);
    cudaGetSymbolAddress((void**)&avh, g_avh);

    cudaFuncSetAttribute(qkv_mma_kernel,
                         cudaFuncAttributeMaxDynamicSharedMemorySize, GEMM_SMEM_LO);
    cudaFuncSetAttribute(out_mma_kernel,
                         cudaFuncAttributeMaxDynamicSharedMemorySize, GEMM_SMEM_1P);
    cudaFuncSetAttribute(attn_mma_kernel,
                         cudaFuncAttributeMaxDynamicSharedMemorySize, (int)ATT_SMEM);

    // One prep launch: x split + all weight converts
    prep_kernel<<<(PREP_TOTAL + 255) / 256, 256>>>(
        (const float4*)x, (uint2*)xh, (uint2*)xl,
        (const float4*)wq, (uint2*)wqh,
        (const float4*)wk, (uint2*)wkh,
        (const float4*)wv, (uint2*)wvh,
        (const float4*)wo, (uint2*)woh);

    // Fused QKV projection (one launch, 24 x 32 CTAs)
    {
        dim3 grid(24, NT / 128);
        qkv_mma_kernel<<<grid, 256, GEMM_SMEM_LO>>>(
            xh, xl, wqh, wkh, wvh, aqh, aql, akh, avh, positions);
    }

    // Attention (QK 2-pass, PV 1-pass) -> ctx fp16
    {
        dim3 grid(SEQ / AQ, QH, BATCH);
        attn_mma_kernel<<<grid, 128, ATT_SMEM>>>(aqh, aql, akh, avh, ch);
    }

    // Output projection (plain fp16 1-pass, fp32 epilogue)
    {
        dim3 grid(DMODEL / 128, NT / 128);
        out_mma_kernel<<<grid, 256, GEMM_SMEM_1P>>>(
            ch, woh, out, NT, DMODEL, DMODEL);
    }
}

// round 16
// speedup vs baseline: 8.9208x; 1.0585x over previous
#include <cuda_runtime.h>
#include <cuda_fp16.h>
#include <math.h>
#include <stdint.h>

// Problem constants
#define BATCH 2
#define SEQ   2048
#define DMODEL 2048
#define QH 16
#define KVH 4
#define HD 128
#define NT (BATCH*SEQ)          // 4096 rows

// ---------------------------------------------------------------------------
// Scratch buffers (device globals: no allocation allowed)
// ---------------------------------------------------------------------------
__device__ __half g_xh[(size_t)NT * DMODEL];
__device__ __half g_xl[(size_t)NT * DMODEL];
__device__ __half g_wqh[(size_t)(QH*HD) * DMODEL];
__device__ __half g_wkh[(size_t)(KVH*HD) * DMODEL];
__device__ __half g_wvh[(size_t)(KVH*HD) * DMODEL];
__device__ __half g_woh[(size_t)DMODEL * (QH*HD)];
__device__ __half g_ch[(size_t)NT * (QH*HD)];

// attention inputs (post-RoPE)
__device__ __half g_aqh[(size_t)NT * QH * HD];
__device__ __half g_aql[(size_t)NT * QH * HD];
__device__ __half g_akh[(size_t)NT * KVH * HD];
__device__ __half g_avh[(size_t)NT * KVH * HD];

// ---------------------------------------------------------------------------
// helpers
// ---------------------------------------------------------------------------
__device__ __forceinline__ void split_pack(float e0, float e1,
                                           uint32_t& hi, uint32_t& lo)
{
    __half h0 = __float2half_rn(e0);
    __half h1 = __float2half_rn(e1);
    hi = ((uint32_t)__half_as_ushort(h1) << 16) | __half_as_ushort(h0);
    __half g0 = __float2half_rn(e0 - __half2float(h0));
    __half g1 = __float2half_rn(e1 - __half2float(h1));
    lo = ((uint32_t)__half_as_ushort(g1) << 16) | __half_as_ushort(g0);
}

__device__ __forceinline__ uint32_t pack_h2(float e0, float e1)
{
    __half h0 = __float2half_rn(e0);
    __half h1 = __float2half_rn(e1);
    return ((uint32_t)__half_as_ushort(h1) << 16) | __half_as_ushort(h0);
}

__device__ __forceinline__ float ex2f(float x)
{
    float y;
    asm("ex2.approx.f32 %0, %1;" : "=f"(y) : "f"(x));
    return y;
}

// One launch: x hi/lo split + all four weight fp16 converts (range dispatch).
#define NX4  ((NT*DMODEL)/4)
#define NQ4  ((QH*HD*DMODEL)/4)
#define NKV4 ((KVH*HD*DMODEL)/4)
#define NO4  ((DMODEL*QH*HD)/4)
#define PREP_TOTAL (NX4 + NQ4 + 2*NKV4 + NO4)

__global__ void prep_kernel(const float4* __restrict__ x,
                            uint2* __restrict__ xh, uint2* __restrict__ xl,
                            const float4* __restrict__ wq, uint2* __restrict__ wqh,
                            const float4* __restrict__ wk, uint2* __restrict__ wkh,
                            const float4* __restrict__ wv, uint2* __restrict__ wvh,
                            const float4* __restrict__ wo, uint2* __restrict__ woh)
{
    int i = blockIdx.x * blockDim.x + threadIdx.x;
    if (i >= PREP_TOTAL) return;
    if (i < NX4) {
        float4 v = x[i];
        uint2 h, l;
        split_pack(v.x, v.y, h.x, l.x);
        split_pack(v.z, v.w, h.y, l.y);
        xh[i] = h;
        xl[i] = l;
        return;
    }
    int j = i - NX4;
    const float4* src;
    uint2* dst;
    if (j < NQ4)                { src = wq; dst = wqh; }
    else if (j < NQ4 + NKV4)    { src = wk; dst = wkh; j -= NQ4; }
    else if (j < NQ4 + 2*NKV4)  { src = wv; dst = wvh; j -= NQ4 + NKV4; }
    else                        { src = wo; dst = woh; j -= NQ4 + 2*NKV4; }
    float4 v = src[j];
    uint2 h;
    h.x = pack_h2(v.x, v.y);
    h.y = pack_h2(v.z, v.w);
    dst[j] = h;
}

#define LDSM4(r, addr) \
    asm volatile("ldmatrix.sync.aligned.m8n8.x4.shared.b16 {%0,%1,%2,%3}, [%4];" \
        : "=r"((r)[0]), "=r"((r)[1]), "=r"((r)[2]), "=r"((r)[3]) : "r"(addr))

#define LDSM4T(r, addr) \
    asm volatile("ldmatrix.sync.aligned.m8n8.x4.trans.shared.b16 {%0,%1,%2,%3}, [%4];" \
        : "=r"((r)[0]), "=r"((r)[1]), "=r"((r)[2]), "=r"((r)[3]) : "r"(addr))

// A from ldmatrix (reorder 0,2,1,3)
#define MMA16816(acc, A, B0, B1) \
    asm volatile("mma.sync.aligned.m16n8k16.row.col.f32.f16.f16.f32 " \
        "{%0,%1,%2,%3}, {%4,%5,%6,%7}, {%8,%9}, {%0,%1,%2,%3};" \
        : "+f"((acc)[0]), "+f"((acc)[1]), "+f"((acc)[2]), "+f"((acc)[3]) \
        : "r"((A)[0]), "r"((A)[2]), "r"((A)[1]), "r"((A)[3]), "r"(B0), "r"(B1))

// A already in mma register order
#define MMA_PV(acc, A, B0, B1) \
    asm volatile("mma.sync.aligned.m16n8k16.row.col.f32.f16.f16.f32 " \
        "{%0,%1,%2,%3}, {%4,%5,%6,%7}, {%8,%9}, {%0,%1,%2,%3};" \
        : "+f"((acc)[0]), "+f"((acc)[1]), "+f"((acc)[2]), "+f"((acc)[3]) \
        : "r"((A)[0]), "r"((A)[1]), "r"((A)[2]), "r"((A)[3]), "r"(B0), "r"(B1))

// ---------------------------------------------------------------------------
// GEMM constants: BK=64, tiles 128 rows x 64 halves (128B rows), 2 stages.
// ---------------------------------------------------------------------------
#define BKK 64
#define TILE_B 16384u
#define NSTAGE 2
#define GEMM_SMEM_LO (NSTAGE*3u*TILE_B)   // 96 KB
#define GEMM_SMEM_1P (NSTAGE*2u*TILE_B)   // 64 KB

// 128-byte row swizzle: row r (0..127), 16B-chunk c (0..7)
__device__ __forceinline__ uint32_t off128(int r, int c) {
    return (uint32_t)(r * 128 + (((c ^ (r & 7)) & 7) << 4));
}

// chunk-offset within a row given row parity already folded into base:
// base must be aH + r*128; chunk c XORs with (r&7).
__device__ __forceinline__ uint32_t chunk_off(int r, int c) {
    return (uint32_t)(((c ^ (r & 7)) & 7) << 4);
}

// Issue one 3-tile stage (Ah, Al, B) for the 2-pass GEMM. 1024 chunks/tile.
__device__ __forceinline__ void issue_stage_lo(
    uint32_t sbase, int st, int it, int row0, int col0, int tid, int K,
    const __half* Ah, const __half* Al, const __half* Bh)
{
    int k0 = it * BKK;
    uint32_t dst0 = sbase + (uint32_t)st * (3u * TILE_B);
    #pragma unroll
    for (int u = 0; u < 12; ++u) {
        int idx = tid + u * 256;          // 0..3071
        int t = idx >> 10;
        int win = idx & 1023;
        int r = win >> 3, c = win & 7;
        const __half* src = (t == 0) ? Ah : (t == 1) ? Al : Bh;
        int gr = ((t == 2) ? col0 : row0) + r;
        const __half* gp = src + (size_t)gr * K + k0 + c * 8;
        uint32_t d = dst0 + (uint32_t)t * TILE_B + off128(r, c);
        asm volatile("cp.async.cg.shared.global [%0], [%1], 16;" :: "r"(d), "l"(gp));
    }
    asm volatile("cp.async.commit_group;" ::: "memory");
}

// Issue one 2-tile stage (Ah, B) for the 1-pass GEMM.
__device__ __forceinline__ void issue_stage_1p(
    uint32_t sbase, int st, int it, int row0, int col0, int tid, int K,
    const __half* Ah, const __half* Bh)
{
    int k0 = it * BKK;
    uint32_t dst0 = sbase + (uint32_t)st * (2u * TILE_B);
    #pragma unroll
    for (int u = 0; u < 8; ++u) {
        int idx = tid + u * 256;          // 0..2047
        int t = idx >> 10;
        int win = idx & 1023;
        int r = win >> 3, c = win & 7;
        const __half* src = (t == 0) ? Ah : Bh;
        int gr = ((t == 1) ? col0 : row0) + r;
        const __half* gp = src + (size_t)gr * K + k0 + c * 8;
        uint32_t d = dst0 + (uint32_t)t * TILE_B + off128(r, c);
        asm volatile("cp.async.cg.shared.global [%0], [%1], 16;" :: "r"(d), "l"(gp));
    }
    asm volatile("cp.async.commit_group;" ::: "memory");
}

// ---------------------------------------------------------------------------
// Fused QKV projection. grid.x 0-15 -> Q (rope + hi/lo), 16-19 -> K (rope),
// 20-23 -> V (plain fp16). 2-pass compensated, BK=64, 2 stages, 2 CTA/SM cap.
// ---------------------------------------------------------------------------
__global__ __launch_bounds__(256, 2)
void qkv_mma_kernel(const __half* __restrict__ Ah,
                    const __half* __restrict__ Al,
                    const __half* __restrict__ Wq,
                    const __half* __restrict__ Wk,
                    const __half* __restrict__ Wv,
                    __half* __restrict__ Daqh, __half* __restrict__ Daql,
                    __half* __restrict__ Dakh, __half* __restrict__ Davh,
                    const int* __restrict__ positions)
{
    extern __shared__ char smem[];
    uint32_t sbase = (uint32_t)__cvta_generic_to_shared(smem);

    int tid = threadIdx.x;
    int lane = tid & 31;
    int w = tid >> 5;
    int wm = w & 3;
    int wn = w >> 2;
    int row0 = blockIdx.y * 128;

    int bx = blockIdx.x;
    const __half* Bh;
    __half *Dh, *Dl;
    int col0, Nout;
    bool do_rope;
    if (bx < 16)      { Bh = Wq; col0 = bx * 128;        Nout = QH * HD;  Dh = Daqh; Dl = Daql; do_rope = true; }
    else if (bx < 20) { Bh = Wk; col0 = (bx - 16) * 128; Nout = KVH * HD; Dh = Dakh; Dl = nullptr; do_rope = true; }
    else              { Bh = Wv; col0 = (bx - 20) * 128; Nout = KVH * HD; Dh = Davh; Dl = nullptr; do_rope = false; }

    const int K = DMODEL;
    float acc[2][8][4];
    #pragma unroll
    for (int i = 0; i < 2; i++)
        #pragma unroll
        for (int j = 0; j < 8; j++)
            #pragma unroll
            for (int q = 0; q < 4; q++) acc[i][j][q] = 0.f;

    const int nIter = K / BKK;   // 32

    issue_stage_lo(sbase, 0, 0, row0, col0, tid, K, Ah, Al, Bh);

    int lrow = (lane & 7) + ((lane >> 4) << 3);
    int lsel = (lane >> 3) & 1;

    // hoisted per-warp row bases (row * 128 part of off128)
    uint32_t arow0 = (uint32_t)((wm * 32 + lrow) * 128);
    uint32_t arow1 = (uint32_t)((wm * 32 + 16 + lrow) * 128);
    int apar0 = (wm * 32 + lrow) & 7;
    int apar1 = (wm * 32 + 16 + lrow) & 7;
    uint32_t brow[4];
    int bpar[4];
    #pragma unroll
    for (int p = 0; p < 4; ++p) {
        int r = wn * 64 + p * 16 + lrow;
        brow[p] = (uint32_t)(r * 128);
        bpar[p] = r & 7;
    }

    for (int it = 0; it < nIter; ++it) {
        asm volatile("cp.async.wait_group 0;" ::: "memory");
        __syncthreads();
        if (it + 1 < nIter)
            issue_stage_lo(sbase, (it + 1) & 1, it + 1, row0, col0, tid, K,
                           Ah, Al, Bh);

        uint32_t tb = sbase + (uint32_t)(it & 1) * (3u * TILE_B);
        uint32_t aH = tb;
        uint32_t aL = tb + TILE_B;
        uint32_t bHb = tb + 2 * TILE_B;

        #pragma unroll
        for (int kk = 0; kk < 4; ++kk) {
            int c = 2 * kk + lsel;
            uint32_t ah2[2][4], al2[2][4], b[4][4];

            LDSM4(al2[0], aL + arow0 + ((uint32_t)(((c ^ apar0) & 7) << 4)));
            LDSM4(al2[1], aL + arow1 + ((uint32_t)(((c ^ apar1) & 7) << 4)));
            LDSM4(ah2[0], aH + arow0 + ((uint32_t)(((c ^ apar0) & 7) << 4)));
            LDSM4(ah2[1], aH + arow1 + ((uint32_t)(((c ^ apar1) & 7) << 4)));
            #pragma unroll
            for (int p = 0; p < 4; ++p)
                LDSM4(b[p], bHb + brow[p] + ((uint32_t)(((c ^ bpar[p]) & 7) << 4)));
            #pragma unroll
            for (int mf = 0; mf < 2; ++mf)
                #pragma unroll
                for (int p = 0; p < 4; ++p) {
                    MMA16816(acc[mf][2*p],   al2[mf], b[p][0], b[p][1]);
                    MMA16816(acc[mf][2*p+1], al2[mf], b[p][2], b[p][3]);
                }
            #pragma unroll
            for (int mf = 0; mf < 2; ++mf)
                #pragma unroll
                for (int p = 0; p < 4; ++p) {
                    MMA16816(acc[mf][2*p],   ah2[mf], b[p][0], b[p][1]);
                    MMA16816(acc[mf][2*p+1], ah2[mf], b[p][2], b[p][3]);
                }
        }
    }

    if (!do_rope) {
        #pragma unroll
        for (int mf = 0; mf < 2; ++mf) {
            int rbase = row0 + wm * 32 + mf * 16 + (lane >> 2);
            #pragma unroll
            for (int nf = 0; nf < 8; ++nf) {
                int cc = col0 + wn * 64 + nf * 8 + (lane & 3) * 2;
                *reinterpret_cast<uint32_t*>(&Dh[(size_t)rbase * Nout + cc]) =
                    pack_h2(acc[mf][nf][0], acc[mf][nf][1]);
                *reinterpret_cast<uint32_t*>(&Dh[(size_t)(rbase + 8) * Nout + cc]) =
                    pack_h2(acc[mf][nf][2], acc[mf][nf][3]);
            }
        }
    } else {
        __syncthreads();
        float* S = reinterpret_cast<float*>(smem);
        #pragma unroll
        for (int mf = 0; mf < 2; ++mf) {
            int rl = wm * 32 + mf * 16 + (lane >> 2);
            #pragma unroll
            for (int nf = 0; nf < 8; ++nf) {
                int cl2 = wn * 64 + nf * 8 + (lane & 3) * 2;
                S[rl * 132 + cl2]           = acc[mf][nf][0];
                S[rl * 132 + cl2 + 1]       = acc[mf][nf][1];
                S[(rl + 8) * 132 + cl2]     = acc[mf][nf][2];
                S[(rl + 8) * 132 + cl2 + 1] = acc[mf][nf][3];
            }
        }
        __syncthreads();
        #pragma unroll
        for (int u = 0; u < 32; ++u) {
            int idx = tid + u * 256;          // 0..8191
            int r = idx >> 6, j = idx & 63;
            float x1 = S[r * 132 + j];
            float x2 = S[r * 132 + j + 64];
            float pos = (float)positions[row0 + r];
            float inv = expf(-9.210340371976184f * (float)j * (1.0f / 64.0f));
            float sn, cs;
            sincosf(pos * inv, &sn, &cs);
            float y1 = x1 * cs - x2 * sn;
            float y2 = x1 * sn + x2 * cs;
            size_t base = (size_t)(row0 + r) * Nout + col0 + j;
            __half h1 = __float2half_rn(y1);
            __half h2 = __float2half_rn(y2);
            Dh[base]      = h1;
            Dh[base + 64] = h2;
            if (Dl) {
                Dl[base]      = __float2half_rn(y1 - __half2float(h1));
                Dl[base + 64] = __float2half_rn(y2 - __half2float(h2));
            }
        }
    }
}

// ---------------------------------------------------------------------------
// Output projection: plain 1-pass fp16 GEMM, fp32 store. BK=64, 2 stages,
// 2 CTA/SM cap.
// ---------------------------------------------------------------------------
__global__ __launch_bounds__(256, 2)
void out_mma_kernel(const __half* __restrict__ Ah,
                    const __half* __restrict__ Bh,
                    float* __restrict__ C, int M, int N, int K)
{
    extern __shared__ char smem[];
    uint32_t sbase = (uint32_t)__cvta_generic_to_shared(smem);

    int tid = threadIdx.x;
    int lane = tid & 31;
    int w = tid >> 5;
    int wm = w & 3;
    int wn = w >> 2;
    int row0 = blockIdx.y * 128;
    int col0 = blockIdx.x * 128;

    float acc[2][8][4];
    #pragma unroll
    for (int i = 0; i < 2; i++)
        #pragma unroll
        for (int j = 0; j < 8; j++)
            #pragma unroll
            for (int q = 0; q < 4; q++) acc[i][j][q] = 0.f;

    const int nIter = K / BKK;

    issue_stage_1p(sbase, 0, 0, row0, col0, tid, K, Ah, Bh);

    int lrow = (lane & 7) + ((lane >> 4) << 3);
    int lsel = (lane >> 3) & 1;

    uint32_t arow0 = (uint32_t)((wm * 32 + lrow) * 128);
    uint32_t arow1 = (uint32_t)((wm * 32 + 16 + lrow) * 128);
    int apar0 = (wm * 32 + lrow) & 7;
    int apar1 = (wm * 32 + 16 + lrow) & 7;
    uint32_t brow[4];
    int bpar[4];
    #pragma unroll
    for (int p = 0; p < 4; ++p) {
        int r = wn * 64 + p * 16 + lrow;
        brow[p] = (uint32_t)(r * 128);
        bpar[p] = r & 7;
    }

    for (int it = 0; it < nIter; ++it) {
        asm volatile("cp.async.wait_group 0;" ::: "memory");
        __syncthreads();
        if (it + 1 < nIter)
            issue_stage_1p(sbase, (it + 1) & 1, it + 1, row0, col0, tid, K,
                           Ah, Bh);

        uint32_t tb = sbase + (uint32_t)(it & 1) * (2u * TILE_B);
        uint32_t aH = tb;
        uint32_t bHb = tb + TILE_B;

        #pragma unroll
        for (int kk = 0; kk < 4; ++kk) {
            int c = 2 * kk + lsel;
            uint32_t ah2[2][4], b[4][4];

            LDSM4(ah2[0], aH + arow0 + ((uint32_t)(((c ^ apar0) & 7) << 4)));
            LDSM4(ah2[1], aH + arow1 + ((uint32_t)(((c ^ apar1) & 7) << 4)));
            #pragma unroll
            for (int p = 0; p < 4; ++p)
                LDSM4(b[p], bHb + brow[p] + ((uint32_t)(((c ^ bpar[p]) & 7) << 4)));
            #pragma unroll
            for (int mf = 0; mf < 2; ++mf)
                #pragma unroll
                for (int p = 0; p < 4; ++p) {
                    MMA16816(acc[mf][2*p],   ah2[mf], b[p][0], b[p][1]);
                    MMA16816(acc[mf][2*p+1], ah2[mf], b[p][2], b[p][3]);
                }
        }
    }

    #pragma unroll
    for (int mf = 0; mf < 2; ++mf) {
        int rbase = row0 + wm * 32 + mf * 16 + (lane >> 2);
        #pragma unroll
        for (int nf = 0; nf < 8; ++nf) {
            int cc = col0 + wn * 64 + nf * 8 + (lane & 3) * 2;
            float2 v0 = make_float2(acc[mf][nf][0], acc[mf][nf][1]);
            float2 v1 = make_float2(acc[mf][nf][2], acc[mf][nf][3]);
            *reinterpret_cast<float2*>(&C[(size_t)rbase * N + cc]) = v0;
            *reinterpret_cast<float2*>(&C[(size_t)(rbase + 8) * N + cc]) = v1;
        }
    }
}

// ---------------------------------------------------------------------------
// Tensor-core flash attention, fp16 (QK 2-pass, PV 1-pass), double-buffered KV.
// CTA: 64 queries x (head, batch). 4 warps. K tile = 64, 2 stages. 96 KB smem.
// LPT order. Softmax in log2 domain (ex2.approx).
// ---------------------------------------------------------------------------
#define AQ 64
#define AKT 64
#define QTILE 16384u
#define KVTILE 16384u
#define KVSTAGE (2u*KVTILE)
#define ATT_SMEM (2u*QTILE + 2u*KVSTAGE)   // 96 KB

__device__ __forceinline__ uint32_t off256(int r, int c) {
    return (uint32_t)(r * 256 + (((c ^ (r & 7)) & 15) << 4));
}

__device__ __forceinline__ void attn_load_kv(
    uint32_t dst, int tid, int b, int kvh, int k0,
    const __half* kh, const __half* vh)
{
    const __half* srcs[2] = {kh, vh};
    #pragma unroll
    for (int u = 0; u < 16; ++u) {
        int idx = tid + u * 128;          // 0..2047
        int t = idx >> 10, win = idx & 1023;
        int r = win >> 4, c = win & 15;
        const __half* gp = srcs[t] +
            (((size_t)(b * SEQ + k0 + r) * KVH + kvh) * HD + c * 8);
        uint32_t d = dst + (uint32_t)t * KVTILE + off256(r, c);
        asm volatile("cp.async.cg.shared.global [%0], [%1], 16;" :: "r"(d), "l"(gp));
    }
}

__global__ __launch_bounds__(128, 2)
void attn_mma_kernel(const __half* __restrict__ qh, const __half* __restrict__ ql,
                     const __half* __restrict__ kh, const __half* __restrict__ vh,
                     __half* __restrict__ ch)
{
    extern __shared__ char asmem[];
    uint32_t sb = (uint32_t)__cvta_generic_to_shared(asmem);
    uint32_t sqh = sb, sql = sb + QTILE;
    uint32_t kvs0 = sb + 2 * QTILE;

    int qt = gridDim.x - 1 - blockIdx.x;   // LPT
    int h = blockIdx.y, b = blockIdx.z;
    int tid = threadIdx.x, lane = tid & 31, w = tid >> 5;
    int q0 = qt * AQ;
    int kvh = h >> 2;
    const float SC2 = 0.08838834764831845f * 1.4426950408889634f;

    int lrow = (lane & 7) | ((lane >> 4) << 3);
    int lsel = (lane >> 3) & 1;
    int vrow = (lane & 7) | (((lane >> 3) & 1) << 3);
    int vcol = lane >> 4;

    const int nt = qt + 1;

    // group 0: Q (hi+lo) + KV tile 0
    {
        const __half* srcs[2] = {qh, ql};
        uint32_t dsts[2] = {sqh, sql};
        #pragma unroll
        for (int u = 0; u < 16; ++u) {
            int idx = tid + u * 128;
            int t = idx >> 10, win = idx & 1023;
            int r = win >> 4, c = win & 15;
            const __half* gp = srcs[t] +
                (((size_t)(b * SEQ + q0 + r) * QH + h) * HD + c * 8);
            uint32_t d = dsts[t] + off256(r, c);
            asm volatile("cp.async.cg.shared.global [%0], [%1], 16;" :: "r"(d), "l"(gp));
        }
        attn_load_kv(kvs0, tid, b, kvh, 0, kh, vh);
        asm volatile("cp.async.commit_group;" ::: "memory");
    }
    // group 1: KV tile 1 (prefetch; valid memory even when nt == 1)
    {
        int k1 = (1 < nt) ? AKT : 0;
        attn_load_kv(kvs0 + KVSTAGE, tid, b, kvh, k1, kh, vh);
        asm volatile("cp.async.commit_group;" ::: "memory");
    }

    float o[16][4];
    #pragma unroll
    for (int i = 0; i < 16; i++) {
        o[i][0] = 0.f; o[i][1] = 0.f; o[i][2] = 0.f; o[i][3] = 0.f;
    }
    float mrun0 = -1e30f, mrun1 = -1e30f, l0 = 0.f, l1 = 0.f;

    for (int kt = 0; kt < nt; ++kt) {
        int k0 = kt * AKT;
        if (kt + 1 < nt)
            asm volatile("cp.async.wait_group 1;" ::: "memory");
        else
            asm volatile("cp.async.wait_group 0;" ::: "memory");
        __syncthreads();

        uint32_t st = kvs0 + (uint32_t)(kt & 1) * KVSTAGE;
        uint32_t skh = st, svh = st + KVTILE;

        // ---- S = Q K^T (2 compensated passes), 64 keys ----
        float s[8][4];
        #pragma unroll
        for (int f = 0; f < 8; f++) {
            s[f][0] = 0.f; s[f][1] = 0.f; s[f][2] = 0.f; s[f][3] = 0.f;
        }
        #pragma unroll
        for (int kk = 0; kk < 8; ++kk) {
            int c = 2 * kk + lsel;
            uint32_t qa[4], qb[4], kbf[4][4];
            LDSM4(qa, sqh + off256(w * 16 + lrow, c));
            LDSM4(qb, sql + off256(w * 16 + lrow, c));
            #pragma unroll
            for (int p = 0; p < 4; ++p)
                LDSM4(kbf[p], skh + off256(p * 16 + lrow, c));
            #pragma unroll
            for (int p = 0; p < 4; ++p) {
                MMA16816(s[2*p],   qa, kbf[p][0], kbf[p][1]);
                MMA16816(s[2*p+1], qa, kbf[p][2], kbf[p][3]);
                MMA16816(s[2*p],   qb, kbf[p][0], kbf[p][1]);
                MMA16816(s[2*p+1], qb, kbf[p][2], kbf[p][3]);
            }
        }

        // ---- scale to log2 domain, then causal mask (diagonal tile only) ----
        #pragma unroll
        for (int f = 0; f < 8; f++) {
            s[f][0] *= SC2; s[f][1] *= SC2; s[f][2] *= SC2; s[f][3] *= SC2;
        }
        if (k0 + AKT - 1 > q0) {
            #pragma unroll
            for (int f = 0; f < 8; ++f) {
                #pragma unroll
                for (int cc = 0; cc < 4; ++cc) {
                    int col = f * 8 + (lane & 3) * 2 + (cc & 1);
                    int row = w * 16 + (lane >> 2) + ((cc >> 1) << 3);
                    if (k0 + col > q0 + row) s[f][cc] = -1e30f;
                }
            }
        }

        // ---- online softmax (log2 domain, ex2.approx) ----
        float mx0 = -1e30f, mx1 = -1e30f;
        #pragma unroll
        for (int f = 0; f < 8; f++) {
            mx0 = fmaxf(mx0, fmaxf(s[f][0], s[f][1]));
            mx1 = fmaxf(mx1, fmaxf(s[f][2], s[f][3]));
        }
        mx0 = fmaxf(mx0, __shfl_xor_sync(0xffffffffu, mx0, 1));
        mx0 = fmaxf(mx0, __shfl_xor_sync(0xffffffffu, mx0, 2));
        mx1 = fmaxf(mx1, __shfl_xor_sync(0xffffffffu, mx1, 1));
        mx1 = fmaxf(mx1, __shfl_xor_sync(0xffffffffu, mx1, 2));

        float mn0 = fmaxf(mrun0, mx0), mn1 = fmaxf(mrun1, mx1);
        float al0 = ex2f(mrun0 - mn0), al1 = ex2f(mrun1 - mn1);
        mrun0 = mn0; mrun1 = mn1;

        float sum0 = 0.f, sum1 = 0.f;
        #pragma unroll
        for (int f = 0; f < 8; f++) {
            s[f][0] = ex2f(s[f][0] - mn0); sum0 += s[f][0];
            s[f][1] = ex2f(s[f][1] - mn0); sum0 += s[f][1];
            s[f][2] = ex2f(s[f][2] - mn1); sum1 += s[f][2];
            s[f][3] = ex2f(s[f][3] - mn1); sum1 += s[f][3];
        }
        sum0 += __shfl_xor_sync(0xffffffffu, sum0, 1);
        sum0 += __shfl_xor_sync(0xffffffffu, sum0, 2);
        sum1 += __shfl_xor_sync(0xffffffffu, sum1, 1);
        sum1 += __shfl_xor_sync(0xffffffffu, sum1, 2);
        l0 = l0 * al0 + sum0;
        l1 = l1 * al1 + sum1;

        #pragma unroll
        for (int nf = 0; nf < 16; ++nf) {
            o[nf][0] *= al0; o[nf][1] *= al0;
            o[nf][2] *= al1; o[nf][3] *= al1;
        }

        // ---- O += P V (1 pass, fp16 P) ----
        #pragma unroll
        for (int j = 0; j < 4; ++j) {
            uint32_t ph[4];
            ph[0] = pack_h2(s[2*j][0],   s[2*j][1]);
            ph[1] = pack_h2(s[2*j][2],   s[2*j][3]);
            ph[2] = pack_h2(s[2*j+1][0], s[2*j+1][1]);
            ph[3] = pack_h2(s[2*j+1][2], s[2*j+1][3]);
            #pragma unroll
            for (int nb = 0; nb < 8; ++nb) {
                uint32_t vb[4];
                LDSM4T(vb, svh + off256(16 * j + vrow, nb * 2 + vcol));
                MMA_PV(o[2*nb],   ph, vb[0], vb[1]);
                MMA_PV(o[2*nb+1], ph, vb[2], vb[3]);
            }
        }

        __syncthreads();
        if (kt + 2 < nt) {
            attn_load_kv(kvs0 + (uint32_t)(kt & 1) * KVSTAGE, tid, b, kvh,
                         (kt + 2) * AKT, kh, vh);
            asm volatile("cp.async.commit_group;" ::: "memory");
        }
    }

    // ---- normalize + write fp16 ctx (hi only) ----
    float inv0 = 1.f / l0, inv1 = 1.f / l1;
    int r0g = q0 + w * 16 + (lane >> 2);
    #pragma unroll
    for (int nf = 0; nf < 16; ++nf) {
        int col = nf * 8 + (lane & 3) * 2;
        size_t base0 = ((size_t)(b * SEQ + r0g) * QH + h) * HD + col;
        size_t base1 = ((size_t)(b * SEQ + r0g + 8) * QH + h) * HD + col;
        *reinterpret_cast<uint32_t*>(&ch[base0]) =
            pack_h2(o[nf][0] * inv0, o[nf][1] * inv0);
        *reinterpret_cast<uint32_t*>(&ch[base1]) =
            pack_h2(o[nf][2] * inv1, o[nf][3] * inv1);
    }
}

// ---------------------------------------------------------------------------
// Launch
// ---------------------------------------------------------------------------
extern "C" void kernel_launch(void* const* d_in, const int* in_sizes, int n_in,
                              void* d_out, int out_size)
{
    const float* x         = (const float*)d_in[0];
    const int*   positions = (const int*)  d_in[1];
    const float* wq        = (const float*)d_in[2];
    const float* wk        = (const float*)d_in[3];
    const float* wv        = (const float*)d_in[4];
    const float* wo        = (const float*)d_in[5];
    float* out = (float*)d_out;

    __half *xh, *xl, *wqh, *wkh, *wvh, *woh, *ch;
    __half *aqh, *aql, *akh, *avh;
    cudaGetSymbolAddress((void**)&xh,  g_xh);  cudaGetSymbolAddress((void**)&xl,  g_xl);
    cudaGetSymbolAddress((void**)&wqh, g_wqh);
    cudaGetSymbolAddress((void**)&wkh, g_wkh);
    cudaGetSymbolAddress((void**)&wvh, g_wvh);
    cudaGetSymbolAddress((void**)&woh, g_woh);
    cudaGetSymbolAddress((void**)&ch,  g_ch);
    cudaGetSymbolAddress((void**)&aqh, g_aqh); cudaGetSymbolAddress((void**)&aql, g_aql);
    cudaGetSymbolAddress((void**)&akh, g_akh);
    cudaGetSymbolAddress((void**)&avh, g_avh);

    cudaFuncSetAttribute(qkv_mma_kernel,
                         cudaFuncAttributeMaxDynamicSharedMemorySize, GEMM_SMEM_LO);
    cudaFuncSetAttribute(out_mma_kernel,
                         cudaFuncAttributeMaxDynamicSharedMemorySize, GEMM_SMEM_1P);
    cudaFuncSetAttribute(attn_mma_kernel,
                         cudaFuncAttributeMaxDynamicSharedMemorySize, (int)ATT_SMEM);

    // One prep launch: x split + all weight converts
    prep_kernel<<<(PREP_TOTAL + 255) / 256, 256>>>(
        (const float4*)x, (uint2*)xh, (uint2*)xl,
        (const float4*)wq, (uint2*)wqh,
        (const float4*)wk, (uint2*)wkh,
        (const float4*)wv, (uint2*)wvh,
        (const float4*)wo, (uint2*)woh);

    // Fused QKV projection (one launch, 24 x 32 CTAs)
    {
        dim3 grid(24, NT / 128);
        qkv_mma_kernel<<<grid, 256, GEMM_SMEM_LO>>>(
            xh, xl, wqh, wkh, wvh, aqh, aql, akh, avh, positions);
    }

    // Attention (QK 2-pass, PV 1-pass) -> ctx fp16
    {
        dim3 grid(SEQ / AQ, QH, BATCH);
        attn_mma_kernel<<<grid, 128, ATT_SMEM>>>(aqh, aql, akh, avh, ch);
    }

    // Output projection (plain fp16 1-pass, fp32 epilogue)
    {
        dim3 grid(DMODEL / 128, NT / 128);
        out_mma_kernel<<<grid, 256, GEMM_SMEM_1P>>>(
            ch, woh, out, NT, DMODEL, DMODEL);
    }
}